// round 12
// baseline (speedup 1.0000x reference)
#include <cuda_runtime.h>
#include <cuda_bf16.h>
#include <math.h>
#include <stdint.h>

// ---------------- problem constants ----------------
#define N_TX   100000
#define N_ADDR 200000
#define NE     400000
#define F_TX   165
#define F_ADDR 64
#define HDIM   64
#define HD     256
#define LN_EPS 1e-5f
#define NEG_SLOPE 0.2f

// ---------------- scratch (device globals; no cudaMalloc allowed) ----------------
__device__ float g_htx64[(size_t)N_TX * HDIM];
__device__ float g_haddr64[(size_t)N_ADDR * HDIM];
__device__ float g_hs_at[(size_t)N_ADDR * HD];
__device__ float g_hs_ta[(size_t)N_TX * HD];
__device__ float g_pool_tx[(size_t)N_TX * HD];
__device__ float g_htx[(size_t)N_TX * HD];
__device__ float g_haddr[(size_t)N_ADDR * HD];
__device__ float4 g_als_at[N_ADDR];
__device__ float4 g_ald_at[N_TX];
__device__ float4 g_als_ta[N_TX];
__device__ float4 g_ald_ta[N_ADDR];
__device__ float4 g_al_at[NE];
__device__ float4 g_al_ta[NE];
__device__ int g_cnt_tx[N_TX];
__device__ int g_cnt_addr[N_ADDR];
__device__ int g_rp_at[N_TX + 1];
__device__ int g_rp_ta[N_ADDR + 1];
__device__ int g_cur_tx[N_TX];
__device__ int g_cur_addr[N_ADDR];
__device__ int g_src_at[NE];
__device__ int g_dst_at[NE];
__device__ int g_src_ta[NE];
__device__ int g_dst_ta[NE];
__device__ int g_bsum_tx[256];
__device__ int g_bsum_addr[256];
__device__ float g_ws_at[HD * 4];
__device__ float g_wd_at[HD * 4];
__device__ float g_ws_ta[HD * 4];
__device__ float g_wd_ta[HD * 4];
__device__ float g_ws_ta1[HD * 4];
__device__ float g_wd_ta1[HD * 4];
// weight images: [N][K_pad] bf16, N*K_pad <= 256*256 = 65536
__device__ __nv_bfloat16 g_w_hi[256 * 256];
__device__ __nv_bfloat16 g_w_lo[256 * 256];

// ---------------- weight split: W[K,N] fp32 -> Wt[n][K_pad] bf16 hi/lo ----------------
__global__ void hg_cvt_w(const float* __restrict__ W, __nv_bfloat16* __restrict__ hi,
                         __nv_bfloat16* __restrict__ lo, int N, int K, int K_pad) {
    int idx = blockIdx.x * blockDim.x + threadIdx.x;
    if (idx >= N * K_pad) return;
    int n = idx / K_pad, k = idx - n * K_pad;
    float v = (k < K) ? W[(long)k * N + n] : 0.f;
    __nv_bfloat16 h = __float2bfloat16(v);
    __nv_bfloat16 l = __float2bfloat16(v - __bfloat162float(h));
    hi[idx] = h;
    lo[idx] = l;
}

// ---------------- tensor-core GEMM via family-compatible mma.sync (bf16x3 split) -----
// C[M,N] = A[M,K] @ W[K,N] (+bias), fp32 in/out, fp32 accumulate.
// block 128x128, 256 threads = 8 warps (4 m x 2 n), warp tile 32x64,
// mma.sync.m16n8k16: per warp 2 mt x 8 nt tiles. K chunked by 32 in smem.

#define HG_MMA(c, a, b0v, b1v) \
    asm volatile( \
        "mma.sync.aligned.m16n8k16.row.col.f32.bf16.bf16.f32 " \
        "{%0,%1,%2,%3}, {%4,%5,%6,%7}, {%8,%9}, {%0,%1,%2,%3};" \
        : "+f"((c)[0]), "+f"((c)[1]), "+f"((c)[2]), "+f"((c)[3]) \
        : "r"((a)[0]), "r"((a)[1]), "r"((a)[2]), "r"((a)[3]), "r"(b0v), "r"(b1v))

#define SMP 36  // padded k-stride (72B rows: 8B-aligned, bank-rotating)

__global__ __launch_bounds__(256)
void hg_mgemm(const float* __restrict__ A, const __nv_bfloat16* __restrict__ wh,
              const __nv_bfloat16* __restrict__ wl, const float* __restrict__ bias,
              float* __restrict__ C, int M, int N, int K, int K_pad) {
    __shared__ __nv_bfloat16 Ah[128][SMP], Al[128][SMP];
    __shared__ __nv_bfloat16 Bh[128][SMP], Bl[128][SMP];
    int tid = threadIdx.x, lane = tid & 31, wid = tid >> 5;
    int wm = wid & 3, wn = wid >> 2;
    int g = lane >> 2, tg = lane & 3;
    int row0 = blockIdx.y * 128, col0 = blockIdx.x * 128;
    bool k4ok = ((K & 3) == 0);

    float acc[2][8][4];
    #pragma unroll
    for (int mt = 0; mt < 2; mt++)
        #pragma unroll
        for (int nt = 0; nt < 8; nt++)
            #pragma unroll
            for (int i = 0; i < 4; i++) acc[mt][nt][i] = 0.f;

    int nch = K_pad >> 5;
    for (int c = 0; c < nch; c++) {
        __syncthreads();
        // ---- load + split A chunk: 128 rows x 32 k ----
        #pragma unroll
        for (int j = 0; j < 4; j++) {
            int idx = tid + j * 256;
            int row = idx >> 3, k4 = (idx & 7) * 4;
            int gr = row0 + row, gk = c * 32 + k4;
            float v[4];
            if (gr < M && k4ok && gk + 3 < K) {
                float4 t = *(const float4*)(A + (long)gr * K + gk);
                v[0] = t.x; v[1] = t.y; v[2] = t.z; v[3] = t.w;
            } else {
                #pragma unroll
                for (int i = 0; i < 4; i++)
                    v[i] = (gr < M && gk + i < K) ? A[(long)gr * K + gk + i] : 0.f;
            }
            unsigned short hb[4], lb[4];
            #pragma unroll
            for (int i = 0; i < 4; i++) {
                __nv_bfloat16 h = __float2bfloat16(v[i]);
                __nv_bfloat16 l = __float2bfloat16(v[i] - __bfloat162float(h));
                hb[i] = __bfloat16_as_ushort(h);
                lb[i] = __bfloat16_as_ushort(l);
            }
            *(uint2*)&Ah[row][k4] =
                make_uint2((uint32_t)hb[0] | ((uint32_t)hb[1] << 16),
                           (uint32_t)hb[2] | ((uint32_t)hb[3] << 16));
            *(uint2*)&Al[row][k4] =
                make_uint2((uint32_t)lb[0] | ((uint32_t)lb[1] << 16),
                           (uint32_t)lb[2] | ((uint32_t)lb[3] << 16));
        }
        // ---- load pre-split B chunk: 128 n-rows x 32 k ----
        #pragma unroll
        for (int j = 0; j < 4; j++) {
            int idx = tid + j * 256;
            int row = idx >> 3, k4 = (idx & 7) * 4;
            int gn = col0 + row;
            uint2 vh = make_uint2(0u, 0u), vl = make_uint2(0u, 0u);
            if (gn < N) {
                long p = (long)gn * K_pad + c * 32 + k4;
                vh = *(const uint2*)(wh + p);
                vl = *(const uint2*)(wl + p);
            }
            *(uint2*)&Bh[row][k4] = vh;
            *(uint2*)&Bl[row][k4] = vl;
        }
        __syncthreads();

        // ---- compute: 2 k16 steps ----
        #pragma unroll
        for (int ks = 0; ks < 32; ks += 16) {
            uint32_t afh[2][4], afl[2][4];
            int kk = ks + tg * 2;
            #pragma unroll
            for (int mt = 0; mt < 2; mt++) {
                int r0 = wm * 32 + mt * 16 + g, r1 = r0 + 8;
                afh[mt][0] = *(uint32_t*)&Ah[r0][kk];
                afh[mt][1] = *(uint32_t*)&Ah[r1][kk];
                afh[mt][2] = *(uint32_t*)&Ah[r0][kk + 8];
                afh[mt][3] = *(uint32_t*)&Ah[r1][kk + 8];
                afl[mt][0] = *(uint32_t*)&Al[r0][kk];
                afl[mt][1] = *(uint32_t*)&Al[r1][kk];
                afl[mt][2] = *(uint32_t*)&Al[r0][kk + 8];
                afl[mt][3] = *(uint32_t*)&Al[r1][kk + 8];
            }
            #pragma unroll
            for (int nt = 0; nt < 8; nt++) {
                int nr = wn * 64 + nt * 8 + g;
                uint32_t bh0 = *(uint32_t*)&Bh[nr][kk];
                uint32_t bh1 = *(uint32_t*)&Bh[nr][kk + 8];
                uint32_t bl0 = *(uint32_t*)&Bl[nr][kk];
                uint32_t bl1 = *(uint32_t*)&Bl[nr][kk + 8];
                #pragma unroll
                for (int mt = 0; mt < 2; mt++) {
                    HG_MMA(acc[mt][nt], afh[mt], bh0, bh1);
                    HG_MMA(acc[mt][nt], afh[mt], bl0, bl1);
                    HG_MMA(acc[mt][nt], afl[mt], bh0, bh1);
                }
            }
        }
    }

    // ---- epilogue ----
    #pragma unroll
    for (int nt = 0; nt < 8; nt++) {
        int col = col0 + wn * 64 + nt * 8 + tg * 2;
        if (col >= N) continue;
        float bv0 = bias ? bias[col] : 0.f;
        float bv1 = bias ? bias[col + 1] : 0.f;
        #pragma unroll
        for (int mt = 0; mt < 2; mt++) {
            int r = row0 + wm * 32 + mt * 16 + g;
            if (r < M) {
                float2 v = make_float2(acc[mt][nt][0] + bv0, acc[mt][nt][1] + bv1);
                *(float2*)(C + (long)r * N + col) = v;
            }
            if (r + 8 < M) {
                float2 v = make_float2(acc[mt][nt][2] + bv0, acc[mt][nt][3] + bv1);
                *(float2*)(C + (long)(r + 8) * N + col) = v;
            }
        }
    }
}

// ---------------- CSR build ----------------
__global__ void hg_zero2(int* a, int na, int* b, int nb) {
    int i = blockIdx.x * blockDim.x + threadIdx.x;
    if (i < na) a[i] = 0;
    if (i < nb) b[i] = 0;
}

__global__ void hg_count(const int* __restrict__ dst_at, int* cnt_at,
                         const int* __restrict__ dst_ta, int* cnt_ta) {
    int i = blockIdx.x * blockDim.x + threadIdx.x;
    if (i < NE) {
        atomicAdd(&cnt_at[dst_at[i]], 1);
        atomicAdd(&cnt_ta[dst_ta[i]], 1);
    }
}

__device__ __forceinline__ int hg_warp_incl_scan(int v, int lane) {
    #pragma unroll
    for (int o = 1; o < 32; o <<= 1) {
        int t = __shfl_up_sync(0xffffffffu, v, o);
        if (lane >= o) v += t;
    }
    return v;
}

__global__ void hg_scan1(const int* __restrict__ cnt, int* __restrict__ rp,
                         int* __restrict__ bsum, int n) {
    __shared__ int ws[32];
    int lane = threadIdx.x & 31, wid = threadIdx.x >> 5;
    int i = blockIdx.x * 1024 + threadIdx.x;
    int v = (i < n) ? cnt[i] : 0;
    int s = hg_warp_incl_scan(v, lane);
    if (lane == 31) ws[wid] = s;
    __syncthreads();
    if (wid == 0) {
        int w = ws[lane];
        w = hg_warp_incl_scan(w, lane);
        ws[lane] = w;
    }
    __syncthreads();
    s += (wid ? ws[wid - 1] : 0);
    if (i < n) rp[i + 1] = s;
    if (bsum && threadIdx.x == 1023) bsum[blockIdx.x] = s;
}

__global__ void hg_scan3(int* __restrict__ rp, const int* __restrict__ bsum, int n) {
    int i = blockIdx.x * blockDim.x + threadIdx.x;
    if (i == 0) rp[0] = 0;
    if (i < n) {
        int b = i >> 10;
        if (b > 0) rp[i + 1] += bsum[b - 1];
    }
}

__global__ void hg_fill(const int* __restrict__ s_at, const int* __restrict__ d_at,
                        int* cur_at, int* src_at, int* dst_at,
                        const int* __restrict__ s_ta, const int* __restrict__ d_ta,
                        int* cur_ta, int* src_ta, int* dst_ta) {
    int i = blockIdx.x * blockDim.x + threadIdx.x;
    if (i < NE) {
        int d0 = d_at[i];
        int p = atomicAdd(&cur_at[d0], 1);
        src_at[p] = s_at[i];
        dst_at[p] = d0;
        int d1 = d_ta[i];
        int q = atomicAdd(&cur_ta[d1], 1);
        src_ta[q] = s_ta[i];
        dst_ta[q] = d1;
    }
}

// ---------------- folded attention weights ----------------
__global__ void hg_att_w(const float* __restrict__ W, const float* __restrict__ a,
                         float* __restrict__ Wv) {
    int k = blockIdx.x;
    int head = threadIdx.x >> 5, lane = threadIdx.x & 31;
    const float* wr = W + (long)k * HD + head * 64;
    const float* ar = a + head * 64;
    float s = wr[lane] * ar[lane] + wr[lane + 32] * ar[lane + 32];
    #pragma unroll
    for (int o = 16; o > 0; o >>= 1) s += __shfl_xor_sync(0xffffffffu, s, o);
    if (lane == 0) Wv[k * 4 + head] = s;
}

// ---------------- fused node coefficients (layer-0, from h64) ----------------
__global__ void hg_coef2(const float* __restrict__ x,
                         const float* __restrict__ Wv1, const float* __restrict__ Wv2,
                         float4* __restrict__ out1, float4* __restrict__ out2,
                         int n, int K) {
    int warp = (blockIdx.x * blockDim.x + threadIdx.x) >> 5;
    int lane = threadIdx.x & 31;
    if (warp >= n) return;
    const float* xp = x + (long)warp * K;
    const float4* wv1 = (const float4*)Wv1;
    const float4* wv2 = (const float4*)Wv2;
    float s0 = 0.f, s1 = 0.f, s2 = 0.f, s3 = 0.f;
    float t0 = 0.f, t1 = 0.f, t2 = 0.f, t3 = 0.f;
    for (int k = lane; k < K; k += 32) {
        float xv = xp[k];
        float4 w1 = wv1[k];
        float4 w2 = wv2[k];
        s0 += xv * w1.x; s1 += xv * w1.y; s2 += xv * w1.z; s3 += xv * w1.w;
        t0 += xv * w2.x; t1 += xv * w2.y; t2 += xv * w2.z; t3 += xv * w2.w;
    }
    #pragma unroll
    for (int o = 16; o > 0; o >>= 1) {
        s0 += __shfl_xor_sync(0xffffffffu, s0, o);
        s1 += __shfl_xor_sync(0xffffffffu, s1, o);
        s2 += __shfl_xor_sync(0xffffffffu, s2, o);
        s3 += __shfl_xor_sync(0xffffffffu, s3, o);
        t0 += __shfl_xor_sync(0xffffffffu, t0, o);
        t1 += __shfl_xor_sync(0xffffffffu, t1, o);
        t2 += __shfl_xor_sync(0xffffffffu, t2, o);
        t3 += __shfl_xor_sync(0xffffffffu, t3, o);
    }
    if (lane == 0) {
        out1[warp] = make_float4(s0, s1, s2, s3);
        out2[warp] = make_float4(t0, t1, t2, t3);
    }
}

// ---------------- per-edge logits in CSR order ----------------
__device__ __forceinline__ float hg_leaky(float v) { return v >= 0.f ? v : NEG_SLOPE * v; }

__global__ void hg_edge_al(const int* __restrict__ src, const int* __restrict__ dst,
                           const float4* __restrict__ als, const float4* __restrict__ ald,
                           float4* __restrict__ al) {
    int i = blockIdx.x * blockDim.x + threadIdx.x;
    if (i >= NE) return;
    float4 s = als[src[i]];
    float4 d = ald[dst[i]];
    float4 r;
    r.x = hg_leaky(s.x + d.x);
    r.y = hg_leaky(s.y + d.y);
    r.z = hg_leaky(s.z + d.z);
    r.w = hg_leaky(s.w + d.w);
    al[i] = r;
}

// ---------------- FUSED: segment softmax agg + bias + LN + residual + ELU + next coef ----------------
__global__ void hg_gat_agg_ln(const float* __restrict__ hs, const int* __restrict__ srcs,
                              const float4* __restrict__ al, const int* __restrict__ rp,
                              const float* __restrict__ bias, const float* __restrict__ gam,
                              const float* __restrict__ bet, float* __restrict__ h,
                              int residual, const float4* __restrict__ wvn,
                              float4* __restrict__ coef, int ndst) {
    int warp = (blockIdx.x * blockDim.x + threadIdx.x) >> 5;
    int lane = threadIdx.x & 31;
    if (warp >= ndst) return;
    int beg = rp[warp], end = rp[warp + 1];
    int c0 = lane * 8;
    int hl = lane >> 3;

    float acc[8] = {0.f, 0.f, 0.f, 0.f, 0.f, 0.f, 0.f, 0.f};
    if (beg < end) {
        float m0 = -3.4e38f, m1 = -3.4e38f, m2 = -3.4e38f, m3 = -3.4e38f;
        for (int t = beg; t < end; t++) {
            float4 a = al[t];
            m0 = fmaxf(m0, a.x); m1 = fmaxf(m1, a.y);
            m2 = fmaxf(m2, a.z); m3 = fmaxf(m3, a.w);
        }
        float d0 = 0.f, d1 = 0.f, d2 = 0.f, d3 = 0.f;
        for (int t = beg; t < end; t++) {
            float4 a = al[t];
            d0 += __expf(a.x - m0); d1 += __expf(a.y - m1);
            d2 += __expf(a.z - m2); d3 += __expf(a.w - m3);
        }
        float mh = (hl & 2) ? ((hl & 1) ? m3 : m2) : ((hl & 1) ? m1 : m0);
        float dh = (hl & 2) ? ((hl & 1) ? d3 : d2) : ((hl & 1) ? d1 : d0);
        float inv = 1.f / dh;
        for (int t = beg; t < end; t++) {
            int sidx = srcs[t];
            float4 a = al[t];
            float av = (hl & 2) ? ((hl & 1) ? a.w : a.z) : ((hl & 1) ? a.y : a.x);
            float alpha = __expf(av - mh) * inv;
            const float4* hp = (const float4*)(hs + (long)sidx * HD + c0);
            float4 v0 = hp[0], v1 = hp[1];
            acc[0] += alpha * v0.x; acc[1] += alpha * v0.y;
            acc[2] += alpha * v0.z; acc[3] += alpha * v0.w;
            acc[4] += alpha * v1.x; acc[5] += alpha * v1.y;
            acc[6] += alpha * v1.z; acc[7] += alpha * v1.w;
        }
    }

    const float4* bp = (const float4*)(bias + c0);
    float4 b0 = bp[0], b1 = bp[1];
    float v[8] = {acc[0] + b0.x, acc[1] + b0.y, acc[2] + b0.z, acc[3] + b0.w,
                  acc[4] + b1.x, acc[5] + b1.y, acc[6] + b1.z, acc[7] + b1.w};
    float sum = 0.f, sq = 0.f;
    #pragma unroll
    for (int j = 0; j < 8; j++) { sum += v[j]; sq += v[j] * v[j]; }
    #pragma unroll
    for (int o = 16; o > 0; o >>= 1) {
        sum += __shfl_xor_sync(0xffffffffu, sum, o);
        sq  += __shfl_xor_sync(0xffffffffu, sq, o);
    }
    float mu = sum * (1.f / HD);
    float var = sq * (1.f / HD) - mu * mu;
    float rstd = rsqrtf(var + LN_EPS);

    const float4* gp = (const float4*)(gam + c0);
    const float4* ep = (const float4*)(bet + c0);
    float4 g0 = gp[0], g1 = gp[1];
    float4 e0 = ep[0], e1 = ep[1];
    float gm[8] = {g0.x, g0.y, g0.z, g0.w, g1.x, g1.y, g1.z, g1.w};
    float bt[8] = {e0.x, e0.y, e0.z, e0.w, e1.x, e1.y, e1.z, e1.w};
    float* hp = h + (long)warp * HD + c0;
    float r[8] = {0.f, 0.f, 0.f, 0.f, 0.f, 0.f, 0.f, 0.f};
    if (residual) {
        float4 r0 = ((const float4*)hp)[0], r1 = ((const float4*)hp)[1];
        r[0] = r0.x; r[1] = r0.y; r[2] = r0.z; r[3] = r0.w;
        r[4] = r1.x; r[5] = r1.y; r[6] = r1.z; r[7] = r1.w;
    }
    float y[8];
    #pragma unroll
    for (int j = 0; j < 8; j++) {
        float t = (v[j] - mu) * rstd * gm[j] + bt[j] + r[j];
        y[j] = t > 0.f ? t : expm1f(t);
    }
    *(float4*)hp = make_float4(y[0], y[1], y[2], y[3]);
    *(float4*)(hp + 4) = make_float4(y[4], y[5], y[6], y[7]);

    if (wvn) {
        float p0 = 0.f, p1 = 0.f, p2 = 0.f, p3 = 0.f;
        #pragma unroll
        for (int j = 0; j < 8; j++) {
            float4 w = wvn[c0 + j];
            p0 += y[j] * w.x; p1 += y[j] * w.y; p2 += y[j] * w.z; p3 += y[j] * w.w;
        }
        #pragma unroll
        for (int o = 16; o > 0; o >>= 1) {
            p0 += __shfl_xor_sync(0xffffffffu, p0, o);
            p1 += __shfl_xor_sync(0xffffffffu, p1, o);
            p2 += __shfl_xor_sync(0xffffffffu, p2, o);
            p3 += __shfl_xor_sync(0xffffffffu, p3, o);
        }
        if (lane == 0) coef[warp] = make_float4(p0, p1, p2, p3);
    }
}

// ---------------- mean pooling addr -> tx (warp per tx node) ----------------
__global__ void hg_pool_mean(const float* __restrict__ haddr, const int* __restrict__ srcs,
                             const int* __restrict__ rp, float* __restrict__ out, int ndst) {
    int warp = (blockIdx.x * blockDim.x + threadIdx.x) >> 5;
    int lane = threadIdx.x & 31;
    if (warp >= ndst) return;
    int beg = rp[warp], end = rp[warp + 1];
    int c0 = lane * 8;
    float acc[8] = {0.f, 0.f, 0.f, 0.f, 0.f, 0.f, 0.f, 0.f};
    for (int t = beg; t < end; t++) {
        int s = srcs[t];
        const float4* hp = (const float4*)(haddr + (long)s * HD + c0);
        float4 v0 = hp[0], v1 = hp[1];
        acc[0] += v0.x; acc[1] += v0.y; acc[2] += v0.z; acc[3] += v0.w;
        acc[4] += v1.x; acc[5] += v1.y; acc[6] += v1.z; acc[7] += v1.w;
    }
    int deg = end - beg;
    float inv = 1.f / (float)(deg > 0 ? deg : 1);
    float* op = out + (long)warp * HD + c0;
    *(float4*)op = make_float4(acc[0] * inv, acc[1] * inv, acc[2] * inv, acc[3] * inv);
    *(float4*)(op + 4) = make_float4(acc[4] * inv, acc[5] * inv, acc[6] * inv, acc[7] * inv);
}

// ---------------- host launcher ----------------
#define SYMADDR(p, s) do { void* _t = nullptr; cudaGetSymbolAddress(&_t, s); p = (decltype(p))_t; } while (0)

static __nv_bfloat16* hp_wh = nullptr;
static __nv_bfloat16* hp_wl = nullptr;

static inline void launch_mgemm(const float* A, const float* W, const float* bias,
                                float* C, int M, int N, int K) {
    int K_pad = ((K + 31) / 32) * 32;
    hg_cvt_w<<<(N * K_pad + 255) / 256, 256>>>(W, hp_wh, hp_wl, N, K, K_pad);
    dim3 grid((N + 127) / 128, (M + 127) / 128);
    hg_mgemm<<<grid, 256>>>(A, hp_wh, hp_wl, bias, C, M, N, K, K_pad);
}

extern "C" void kernel_launch(void* const* d_in, const int* in_sizes, int n_in,
                              void* d_out, int out_size) {
    const float* x_tx      = (const float*)d_in[0];
    const float* x_addr    = (const float*)d_in[1];
    const int*   addr_idx_at = (const int*)d_in[2];
    const int*   tx_idx_at   = (const int*)d_in[3];
    const int*   tx_idx_ta   = (const int*)d_in[4];
    const int*   addr_idx_ta = (const int*)d_in[5];
    const float* w_in_tx   = (const float*)d_in[6];
    const float* b_in_tx   = (const float*)d_in[7];
    const float* w_in_addr = (const float*)d_in[8];
    const float* b_in_addr = (const float*)d_in[9];
    const float* w_at0 = (const float*)d_in[10];
    const float* as_at0 = (const float*)d_in[11];
    const float* ad_at0 = (const float*)d_in[12];
    const float* b_at0 = (const float*)d_in[13];
    const float* w_ta0 = (const float*)d_in[14];
    const float* as_ta0 = (const float*)d_in[15];
    const float* ad_ta0 = (const float*)d_in[16];
    const float* b_ta0 = (const float*)d_in[17];
    // layer-1 at-relation weights are dead (h_tx after layer 1 unused by output)
    const float* w_ta1 = (const float*)d_in[22];
    const float* as_ta1 = (const float*)d_in[23];
    const float* ad_ta1 = (const float*)d_in[24];
    const float* b_ta1 = (const float*)d_in[25];
    const float* ln_g_tx = (const float*)d_in[26];
    const float* ln_b_tx = (const float*)d_in[27];
    const float* ln_g_addr = (const float*)d_in[28];
    const float* ln_b_addr = (const float*)d_in[29];
    const float* w_out = (const float*)d_in[30];
    const float* b_out = (const float*)d_in[31];
    float* out = (float*)d_out;

    float *p_htx64, *p_haddr64, *p_hs_at, *p_hs_ta, *p_pool_tx, *p_htx, *p_haddr;
    float4 *p_als_at, *p_ald_at, *p_als_ta, *p_ald_ta, *p_al_at, *p_al_ta;
    int *p_cnt_tx, *p_cnt_addr, *p_rp_at, *p_rp_ta, *p_cur_tx, *p_cur_addr;
    int *p_src_at, *p_dst_at, *p_src_ta, *p_dst_ta, *p_bsum_tx, *p_bsum_addr;
    float *p_ws_at, *p_wd_at, *p_ws_ta, *p_wd_ta, *p_ws_ta1, *p_wd_ta1;
    SYMADDR(p_htx64, g_htx64);     SYMADDR(p_haddr64, g_haddr64);
    SYMADDR(p_hs_at, g_hs_at);     SYMADDR(p_hs_ta, g_hs_ta);
    SYMADDR(p_pool_tx, g_pool_tx);
    SYMADDR(p_htx, g_htx);         SYMADDR(p_haddr, g_haddr);
    SYMADDR(p_als_at, g_als_at);   SYMADDR(p_ald_at, g_ald_at);
    SYMADDR(p_als_ta, g_als_ta);   SYMADDR(p_ald_ta, g_ald_ta);
    SYMADDR(p_al_at, g_al_at);     SYMADDR(p_al_ta, g_al_ta);
    SYMADDR(p_cnt_tx, g_cnt_tx);   SYMADDR(p_cnt_addr, g_cnt_addr);
    SYMADDR(p_rp_at, g_rp_at);     SYMADDR(p_rp_ta, g_rp_ta);
    SYMADDR(p_cur_tx, g_cur_tx);   SYMADDR(p_cur_addr, g_cur_addr);
    SYMADDR(p_src_at, g_src_at);   SYMADDR(p_dst_at, g_dst_at);
    SYMADDR(p_src_ta, g_src_ta);   SYMADDR(p_dst_ta, g_dst_ta);
    SYMADDR(p_bsum_tx, g_bsum_tx); SYMADDR(p_bsum_addr, g_bsum_addr);
    SYMADDR(p_ws_at, g_ws_at);     SYMADDR(p_wd_at, g_wd_at);
    SYMADDR(p_ws_ta, g_ws_ta);     SYMADDR(p_wd_ta, g_wd_ta);
    SYMADDR(p_ws_ta1, g_ws_ta1);   SYMADDR(p_wd_ta1, g_wd_ta1);
    SYMADDR(hp_wh, g_w_hi);        SYMADDR(hp_wl, g_w_lo);

    const int TB = 256;
    const int nb_tx = (N_TX + 1023) / 1024;
    const int nb_addr = (N_ADDR + 1023) / 1024;
    int cblk_tx = (N_TX * 32 + TB - 1) / TB;
    int cblk_addr = (N_ADDR * 32 + TB - 1) / TB;
    int eblk = (NE + TB - 1) / TB;

    // ---- CSR build ----
    hg_zero2<<<(N_ADDR + TB - 1) / TB, TB>>>(p_cnt_tx, N_TX, p_cnt_addr, N_ADDR);
    hg_count<<<(NE + TB - 1) / TB, TB>>>(tx_idx_at, p_cnt_tx, addr_idx_ta, p_cnt_addr);
    hg_scan1<<<nb_tx, 1024>>>(p_cnt_tx, p_rp_at, p_bsum_tx, N_TX);
    hg_scan1<<<nb_addr, 1024>>>(p_cnt_addr, p_rp_ta, p_bsum_addr, N_ADDR);
    hg_scan1<<<1, 1024>>>(p_bsum_tx, p_bsum_tx - 1, nullptr, nb_tx);
    hg_scan1<<<1, 1024>>>(p_bsum_addr, p_bsum_addr - 1, nullptr, nb_addr);
    hg_scan3<<<(N_TX + TB - 1) / TB, TB>>>(p_rp_at, p_bsum_tx, N_TX);
    hg_scan3<<<(N_ADDR + TB - 1) / TB, TB>>>(p_rp_ta, p_bsum_addr, N_ADDR);
    cudaMemcpyAsync(p_cur_tx, p_rp_at, N_TX * sizeof(int), cudaMemcpyDeviceToDevice);
    cudaMemcpyAsync(p_cur_addr, p_rp_ta, N_ADDR * sizeof(int), cudaMemcpyDeviceToDevice);
    hg_fill<<<(NE + TB - 1) / TB, TB>>>(addr_idx_at, tx_idx_at, p_cur_tx, p_src_at, p_dst_at,
                                        tx_idx_ta, addr_idx_ta, p_cur_addr, p_src_ta, p_dst_ta);

    // ---- input projections ----
    launch_mgemm(x_tx, w_in_tx, b_in_tx, p_htx64, N_TX, HDIM, F_TX);
    launch_mgemm(x_addr, w_in_addr, b_in_addr, p_haddr64, N_ADDR, HDIM, F_ADDR);

    // ---- fold attention weight vectors ----
    hg_att_w<<<HDIM, 128>>>(w_at0, as_at0, p_ws_at);
    hg_att_w<<<HDIM, 128>>>(w_at0, ad_at0, p_wd_at);
    hg_att_w<<<HDIM, 128>>>(w_ta0, as_ta0, p_ws_ta);
    hg_att_w<<<HDIM, 128>>>(w_ta0, ad_ta0, p_wd_ta);
    hg_att_w<<<HD, 128>>>(w_ta1, as_ta1, p_ws_ta1);
    hg_att_w<<<HD, 128>>>(w_ta1, ad_ta1, p_wd_ta1);

    // ---- layer 0 ----
    launch_mgemm(p_haddr64, w_at0, nullptr, p_hs_at, N_ADDR, HD, HDIM);
    launch_mgemm(p_htx64,   w_ta0, nullptr, p_hs_ta, N_TX,   HD, HDIM);

    hg_coef2<<<cblk_addr, TB>>>(p_haddr64, p_ws_at, p_wd_ta, p_als_at, p_ald_ta,
                                N_ADDR, HDIM);
    hg_coef2<<<cblk_tx,   TB>>>(p_htx64,   p_wd_at, p_ws_ta, p_ald_at, p_als_ta,
                                N_TX, HDIM);

    hg_edge_al<<<eblk, TB>>>(p_src_at, p_dst_at, p_als_at, p_ald_at, p_al_at);
    hg_edge_al<<<eblk, TB>>>(p_src_ta, p_dst_ta, p_als_ta, p_ald_ta, p_al_ta);

    hg_gat_agg_ln<<<cblk_tx, TB>>>(p_hs_at, p_src_at, p_al_at, p_rp_at,
                                   b_at0, ln_g_tx, ln_b_tx, p_htx, 0,
                                   (const float4*)p_ws_ta1, p_als_ta, N_TX);
    hg_gat_agg_ln<<<cblk_addr, TB>>>(p_hs_ta, p_src_ta, p_al_ta, p_rp_ta,
                                     b_ta0, ln_g_addr, ln_b_addr, p_haddr, 0,
                                     (const float4*)p_wd_ta1, p_ald_ta, N_ADDR);

    // ---- layer 1 (ta relation only; tx branch is dead) ----
    launch_mgemm(p_htx, w_ta1, nullptr, p_hs_ta, N_TX, HD, HD);

    hg_edge_al<<<eblk, TB>>>(p_src_ta, p_dst_ta, p_als_ta, p_ald_ta, p_al_ta);

    hg_gat_agg_ln<<<cblk_addr, TB>>>(p_hs_ta, p_src_ta, p_al_ta, p_rp_ta,
                                     b_ta1, ln_g_addr, ln_b_addr, p_haddr, 1,
                                     nullptr, nullptr, N_ADDR);

    // ---- scatter-mean pooling addr -> tx over 'at' edges ----
    hg_pool_mean<<<cblk_tx, TB>>>(p_haddr, p_src_at, p_rp_at, p_pool_tx, N_TX);

    // ---- output projection ----
    launch_mgemm(p_pool_tx, w_out, b_out, out, N_TX, HD, HD);
}

// round 13
// speedup vs baseline: 1.3134x; 1.3134x over previous
#include <cuda_runtime.h>
#include <math.h>
#include <stdint.h>

// ---------------- problem constants ----------------
#define N_TX   100000
#define N_ADDR 200000
#define NE     400000
#define F_TX   165
#define F_ADDR 64
#define HDIM   64
#define HD     256
#define LN_EPS 1e-5f
#define NEG_SLOPE 0.2f

// ---------------- scratch (device globals; no cudaMalloc allowed) ----------------
__device__ float g_htx64[(size_t)N_TX * HDIM];
__device__ float g_haddr64[(size_t)N_ADDR * HDIM];
__device__ float g_buf_addr[(size_t)N_ADDR * HD];  // aggx_addr (L0)
__device__ float g_buf_tx[(size_t)N_TX * HD];      // aggx_tx (L0), then hs_ta (L1)
__device__ float g_pool_tx[(size_t)N_TX * HD];
__device__ float g_htx[(size_t)N_TX * HD];
__device__ float g_haddr[(size_t)N_ADDR * HD];
__device__ float4 g_als_at[N_ADDR];
__device__ float4 g_ald_at[N_TX];
__device__ float4 g_als_ta[N_TX];
__device__ float4 g_ald_ta[N_ADDR];
__device__ float4 g_al_at[NE];
__device__ float4 g_al_ta[NE];
__device__ int g_cnt_tx[N_TX];
__device__ int g_cnt_addr[N_ADDR];
__device__ int g_rp_at[N_TX + 1];
__device__ int g_rp_ta[N_ADDR + 1];
__device__ int g_cur_tx[N_TX];
__device__ int g_cur_addr[N_ADDR];
__device__ int g_src_at[NE];
__device__ int g_dst_at[NE];
__device__ int g_src_ta[NE];
__device__ int g_dst_ta[NE];
__device__ int g_bsum_tx[256];
__device__ int g_bsum_addr[256];
__device__ float g_ws_at[HD * 4];
__device__ float g_wd_at[HD * 4];
__device__ float g_ws_ta[HD * 4];
__device__ float g_wd_ta[HD * 4];
__device__ float g_ws_ta1[HD * 4];
__device__ float g_wd_ta1[HD * 4];

// ---------------- packed f32x2 helpers (sm_103a FFMA2 pipe) ----------------
__device__ __forceinline__ unsigned long long hg_pack2(float x, float y) {
    unsigned long long r;
    asm("mov.b64 %0, {%1, %2};" : "=l"(r) : "f"(x), "f"(y));
    return r;
}
__device__ __forceinline__ void hg_unpack2(unsigned long long v, float& x, float& y) {
    asm("mov.b64 {%0, %1}, %2;" : "=f"(x), "=f"(y) : "l"(v));
}
__device__ __forceinline__ void hg_ffma2(unsigned long long& d,
                                         unsigned long long a, unsigned long long b) {
    asm("fma.rn.f32x2 %0, %1, %2, %0;" : "+l"(d) : "l"(a), "l"(b));
}

// ---------------- SGEMM: C[M,N] = A[M,K] @ B[K,N] (+bias), FFMA2 inner loop ----------
#define BM 128
#define BN 128
#define BK 16
#define TM 8
#define TN 8

__global__ __launch_bounds__(256)
void hg_sgemm(const float* __restrict__ A, const float* __restrict__ B,
              const float* __restrict__ bias, float* __restrict__ C,
              int M, int N, int K) {
    __shared__ float As[2][BK][BM];
    __shared__ float Bs[2][BK][BN];
    int tid = threadIdx.x;
    int row0 = blockIdx.y * BM, col0 = blockIdx.x * BN;
    int tx = tid & 15, ty = tid >> 4;
    int arow = tid >> 1, acol = (tid & 1) * 8;
    int brow = tid >> 4, bcol = (tid & 15) * 8;
    bool k4 = ((K & 3) == 0);
    int nk = (K + BK - 1) / BK;

    float ra[8];
    float4 rb0, rb1;

    unsigned long long acc2[TM][TN / 2];
    #pragma unroll
    for (int i = 0; i < TM; i++)
        #pragma unroll
        for (int j = 0; j < TN / 2; j++) acc2[i][j] = 0ull;

    auto loadA = [&](int k0) {
        int gr = row0 + arow;
        if (k4) {
            #pragma unroll
            for (int i = 0; i < 8; i += 4) {
                int gk = k0 + acol + i;
                float4 v = make_float4(0.f, 0.f, 0.f, 0.f);
                if (gr < M && gk < K) v = *(const float4*)(A + (long)gr * K + gk);
                ra[i] = v.x; ra[i + 1] = v.y; ra[i + 2] = v.z; ra[i + 3] = v.w;
            }
        } else {
            #pragma unroll
            for (int i = 0; i < 8; i++) {
                int gk = k0 + acol + i;
                ra[i] = (gr < M && gk < K) ? A[(long)gr * K + gk] : 0.f;
            }
        }
    };
    auto loadB = [&](int k0) {
        int gk = k0 + brow, gn = col0 + bcol;
        rb0 = make_float4(0.f, 0.f, 0.f, 0.f);
        rb1 = rb0;
        if (gk < K && gn < N) {
            rb0 = *(const float4*)(B + (long)gk * N + gn);
            rb1 = *(const float4*)(B + (long)gk * N + gn + 4);
        }
    };
    auto storeA = [&](int s) {
        #pragma unroll
        for (int i = 0; i < 8; i++) As[s][acol + i][arow] = ra[i];
    };
    auto storeB = [&](int s) {
        *(float4*)&Bs[s][brow][bcol] = rb0;
        *(float4*)&Bs[s][brow][bcol + 4] = rb1;
    };

    loadA(0); loadB(0);
    storeA(0); storeB(0);
    __syncthreads();

    int s = 0;
    for (int t = 0; t < nk; t++) {
        if (t + 1 < nk) { loadA((t + 1) * BK); loadB((t + 1) * BK); }
        #pragma unroll
        for (int k = 0; k < BK; k++) {
            float4 a0 = *(float4*)&As[s][k][ty * TM];
            float4 a1 = *(float4*)&As[s][k][ty * TM + 4];
            float4 b0 = *(float4*)&Bs[s][k][tx * TN];
            float4 b1 = *(float4*)&Bs[s][k][tx * TN + 4];
            unsigned long long b2[4];
            b2[0] = hg_pack2(b0.x, b0.y);
            b2[1] = hg_pack2(b0.z, b0.w);
            b2[2] = hg_pack2(b1.x, b1.y);
            b2[3] = hg_pack2(b1.z, b1.w);
            float af[8] = {a0.x, a0.y, a0.z, a0.w, a1.x, a1.y, a1.z, a1.w};
            #pragma unroll
            for (int i = 0; i < TM; i++) {
                unsigned long long a2 = hg_pack2(af[i], af[i]);
                #pragma unroll
                for (int j = 0; j < TN / 2; j++) hg_ffma2(acc2[i][j], a2, b2[j]);
            }
        }
        if (t + 1 < nk) {
            storeA(s ^ 1); storeB(s ^ 1);
            __syncthreads();
            s ^= 1;
        }
    }

    int gc = col0 + tx * TN;
    if (gc >= N) return;
    float bsv[8];
    #pragma unroll
    for (int j = 0; j < 8; j++) bsv[j] = bias ? bias[gc + j] : 0.f;
    #pragma unroll
    for (int i = 0; i < TM; i++) {
        int gr = row0 + ty * TM + i;
        if (gr >= M) continue;
        float acc[8];
        #pragma unroll
        for (int j = 0; j < 4; j++) hg_unpack2(acc2[i][j], acc[2 * j], acc[2 * j + 1]);
        float* cp = C + (long)gr * N + gc;
        *(float4*)cp = make_float4(acc[0] + bsv[0], acc[1] + bsv[1],
                                   acc[2] + bsv[2], acc[3] + bsv[3]);
        *(float4*)(cp + 4) = make_float4(acc[4] + bsv[4], acc[5] + bsv[5],
                                         acc[6] + bsv[6], acc[7] + bsv[7]);
    }
}

// ---------------- block-diagonal GEMM (K=64 per head) + bias + LN + ELU + coef -------
// A: [M, 256] head-blocked aggregate (col = h*64 + k). W: [64, 256].
// C[r][n] = sum_k A[r][head(n)*64+k] * W[k][n]. Block: 64 rows x 256 cols, 256 thr.
#define GL_BK 16

__global__ __launch_bounds__(256)
void hg_gemm_ln(const float* __restrict__ A, const float* __restrict__ W,
                const float* __restrict__ bias, const float* __restrict__ gam,
                const float* __restrict__ bet, float* __restrict__ h,
                const float4* __restrict__ wvn, float4* __restrict__ coef, int M) {
    __shared__ float As[GL_BK][4][68];   // [k][head][row], padded to kill head conflicts
    __shared__ float Bs[GL_BK][256];
    int tid = threadIdx.x, tx = tid & 31, ty = tid >> 5;
    int row0 = blockIdx.x * 64;
    int arow = tid & 63, apart = tid >> 6;
    int head = tx >> 3;

    unsigned long long acc2[8][4];
    #pragma unroll
    for (int i = 0; i < 8; i++)
        #pragma unroll
        for (int j = 0; j < 4; j++) acc2[i][j] = 0ull;

    for (int k0 = 0; k0 < 64; k0 += GL_BK) {
        __syncthreads();
        // A tile: thread loads 16 k's of one (row, head-part)
        {
            int gr = row0 + arow;
            float4 t0 = make_float4(0.f, 0.f, 0.f, 0.f), t1 = t0, t2 = t0, t3 = t0;
            if (gr < M) {
                const float4* ap = (const float4*)(A + (long)gr * HD + apart * 64 + k0);
                t0 = ap[0]; t1 = ap[1]; t2 = ap[2]; t3 = ap[3];
            }
            float vv[16] = {t0.x, t0.y, t0.z, t0.w, t1.x, t1.y, t1.z, t1.w,
                            t2.x, t2.y, t2.z, t2.w, t3.x, t3.y, t3.z, t3.w};
            #pragma unroll
            for (int k = 0; k < GL_BK; k++) As[k][apart][arow] = vv[k];
        }
        // B tile: thread loads 4 float4s of one W row (strided cols, 2-way stores)
        {
            int kk = tid >> 4, c = (tid & 15) * 4;
            const float* wp = W + (long)(k0 + kk) * HD;
            #pragma unroll
            for (int q = 0; q < 4; q++)
                *(float4*)&Bs[kk][c + q * 64] = *(const float4*)(wp + c + q * 64);
        }
        __syncthreads();

        #pragma unroll
        for (int k = 0; k < GL_BK; k++) {
            float4 a0 = *(float4*)&As[k][head][ty * 8];
            float4 a1 = *(float4*)&As[k][head][ty * 8 + 4];
            float4 b0 = *(float4*)&Bs[k][tx * 8];
            float4 b1 = *(float4*)&Bs[k][tx * 8 + 4];
            unsigned long long b2[4];
            b2[0] = hg_pack2(b0.x, b0.y);
            b2[1] = hg_pack2(b0.z, b0.w);
            b2[2] = hg_pack2(b1.x, b1.y);
            b2[3] = hg_pack2(b1.z, b1.w);
            float af[8] = {a0.x, a0.y, a0.z, a0.w, a1.x, a1.y, a1.z, a1.w};
            #pragma unroll
            for (int i = 0; i < 8; i++) {
                unsigned long long a2 = hg_pack2(af[i], af[i]);
                #pragma unroll
                for (int j = 0; j < 4; j++) hg_ffma2(acc2[i][j], a2, b2[j]);
            }
        }
    }

    // epilogue: bias + LN + ELU + next-layer coef; warp ty holds rows ty*8..+7 fully
    int cbase = tx * 8;
    float bsv[8], gmv[8], btv[8];
    {
        float4 t0 = *(const float4*)(bias + cbase), t1 = *(const float4*)(bias + cbase + 4);
        bsv[0]=t0.x; bsv[1]=t0.y; bsv[2]=t0.z; bsv[3]=t0.w;
        bsv[4]=t1.x; bsv[5]=t1.y; bsv[6]=t1.z; bsv[7]=t1.w;
        t0 = *(const float4*)(gam + cbase); t1 = *(const float4*)(gam + cbase + 4);
        gmv[0]=t0.x; gmv[1]=t0.y; gmv[2]=t0.z; gmv[3]=t0.w;
        gmv[4]=t1.x; gmv[5]=t1.y; gmv[6]=t1.z; gmv[7]=t1.w;
        t0 = *(const float4*)(bet + cbase); t1 = *(const float4*)(bet + cbase + 4);
        btv[0]=t0.x; btv[1]=t0.y; btv[2]=t0.z; btv[3]=t0.w;
        btv[4]=t1.x; btv[5]=t1.y; btv[6]=t1.z; btv[7]=t1.w;
    }
    float4 wv4[8];
    if (wvn) {
        #pragma unroll
        for (int j = 0; j < 8; j++) wv4[j] = wvn[cbase + j];
    }

    #pragma unroll
    for (int i = 0; i < 8; i++) {
        int r = row0 + ty * 8 + i;
        float v[8];
        #pragma unroll
        for (int j = 0; j < 4; j++) hg_unpack2(acc2[i][j], v[2 * j], v[2 * j + 1]);
        #pragma unroll
        for (int j = 0; j < 8; j++) v[j] += bsv[j];
        float sum = 0.f, sq = 0.f;
        #pragma unroll
        for (int j = 0; j < 8; j++) { sum += v[j]; sq += v[j] * v[j]; }
        #pragma unroll
        for (int o = 16; o > 0; o >>= 1) {
            sum += __shfl_xor_sync(0xffffffffu, sum, o);
            sq  += __shfl_xor_sync(0xffffffffu, sq, o);
        }
        float mu = sum * (1.f / HD);
        float var = sq * (1.f / HD) - mu * mu;
        float rstd = rsqrtf(var + LN_EPS);
        float y[8];
        #pragma unroll
        for (int j = 0; j < 8; j++) {
            float t = (v[j] - mu) * rstd * gmv[j] + btv[j];
            y[j] = t > 0.f ? t : expm1f(t);
        }
        if (r < M) {
            float* hp = h + (long)r * HD + cbase;
            *(float4*)hp = make_float4(y[0], y[1], y[2], y[3]);
            *(float4*)(hp + 4) = make_float4(y[4], y[5], y[6], y[7]);
        }
        if (wvn) {
            float p0 = 0.f, p1 = 0.f, p2 = 0.f, p3 = 0.f;
            #pragma unroll
            for (int j = 0; j < 8; j++) {
                p0 += y[j] * wv4[j].x; p1 += y[j] * wv4[j].y;
                p2 += y[j] * wv4[j].z; p3 += y[j] * wv4[j].w;
            }
            #pragma unroll
            for (int o = 16; o > 0; o >>= 1) {
                p0 += __shfl_xor_sync(0xffffffffu, p0, o);
                p1 += __shfl_xor_sync(0xffffffffu, p1, o);
                p2 += __shfl_xor_sync(0xffffffffu, p2, o);
                p3 += __shfl_xor_sync(0xffffffffu, p3, o);
            }
            if (tx == 0 && r < M) coef[r] = make_float4(p0, p1, p2, p3);
        }
    }
}

// ---------------- CSR build ----------------
__global__ void hg_zero2(int* a, int na, int* b, int nb) {
    int i = blockIdx.x * blockDim.x + threadIdx.x;
    if (i < na) a[i] = 0;
    if (i < nb) b[i] = 0;
}

__global__ void hg_count(const int* __restrict__ dst_at, int* cnt_at,
                         const int* __restrict__ dst_ta, int* cnt_ta) {
    int i = blockIdx.x * blockDim.x + threadIdx.x;
    if (i < NE) {
        atomicAdd(&cnt_at[dst_at[i]], 1);
        atomicAdd(&cnt_ta[dst_ta[i]], 1);
    }
}

__device__ __forceinline__ int hg_warp_incl_scan(int v, int lane) {
    #pragma unroll
    for (int o = 1; o < 32; o <<= 1) {
        int t = __shfl_up_sync(0xffffffffu, v, o);
        if (lane >= o) v += t;
    }
    return v;
}

__global__ void hg_scan1(const int* __restrict__ cnt, int* __restrict__ rp,
                         int* __restrict__ bsum, int n) {
    __shared__ int ws[32];
    int lane = threadIdx.x & 31, wid = threadIdx.x >> 5;
    int i = blockIdx.x * 1024 + threadIdx.x;
    int v = (i < n) ? cnt[i] : 0;
    int s = hg_warp_incl_scan(v, lane);
    if (lane == 31) ws[wid] = s;
    __syncthreads();
    if (wid == 0) {
        int w = ws[lane];
        w = hg_warp_incl_scan(w, lane);
        ws[lane] = w;
    }
    __syncthreads();
    s += (wid ? ws[wid - 1] : 0);
    if (i < n) rp[i + 1] = s;
    if (bsum && threadIdx.x == 1023) bsum[blockIdx.x] = s;
}

__global__ void hg_scan3(int* __restrict__ rp, const int* __restrict__ bsum, int n) {
    int i = blockIdx.x * blockDim.x + threadIdx.x;
    if (i == 0) rp[0] = 0;
    if (i < n) {
        int b = i >> 10;
        if (b > 0) rp[i + 1] += bsum[b - 1];
    }
}

__global__ void hg_fill(const int* __restrict__ s_at, const int* __restrict__ d_at,
                        int* cur_at, int* src_at, int* dst_at,
                        const int* __restrict__ s_ta, const int* __restrict__ d_ta,
                        int* cur_ta, int* src_ta, int* dst_ta) {
    int i = blockIdx.x * blockDim.x + threadIdx.x;
    if (i < NE) {
        int d0 = d_at[i];
        int p = atomicAdd(&cur_at[d0], 1);
        src_at[p] = s_at[i];
        dst_at[p] = d0;
        int d1 = d_ta[i];
        int q = atomicAdd(&cur_ta[d1], 1);
        src_ta[q] = s_ta[i];
        dst_ta[q] = d1;
    }
}

// ---------------- folded attention weights ----------------
__global__ void hg_att_w(const float* __restrict__ W, const float* __restrict__ a,
                         float* __restrict__ Wv) {
    int k = blockIdx.x;
    int head = threadIdx.x >> 5, lane = threadIdx.x & 31;
    const float* wr = W + (long)k * HD + head * 64;
    const float* ar = a + head * 64;
    float s = wr[lane] * ar[lane] + wr[lane + 32] * ar[lane + 32];
    #pragma unroll
    for (int o = 16; o > 0; o >>= 1) s += __shfl_xor_sync(0xffffffffu, s, o);
    if (lane == 0) Wv[k * 4 + head] = s;
}

// ---------------- fused node coefficients (layer-0, from h64) ----------------
__global__ void hg_coef2(const float* __restrict__ x,
                         const float* __restrict__ Wv1, const float* __restrict__ Wv2,
                         float4* __restrict__ out1, float4* __restrict__ out2,
                         int n, int K) {
    int warp = (blockIdx.x * blockDim.x + threadIdx.x) >> 5;
    int lane = threadIdx.x & 31;
    if (warp >= n) return;
    const float* xp = x + (long)warp * K;
    const float4* wv1 = (const float4*)Wv1;
    const float4* wv2 = (const float4*)Wv2;
    float s0 = 0.f, s1 = 0.f, s2 = 0.f, s3 = 0.f;
    float t0 = 0.f, t1 = 0.f, t2 = 0.f, t3 = 0.f;
    for (int k = lane; k < K; k += 32) {
        float xv = xp[k];
        float4 w1 = wv1[k];
        float4 w2 = wv2[k];
        s0 += xv * w1.x; s1 += xv * w1.y; s2 += xv * w1.z; s3 += xv * w1.w;
        t0 += xv * w2.x; t1 += xv * w2.y; t2 += xv * w2.z; t3 += xv * w2.w;
    }
    #pragma unroll
    for (int o = 16; o > 0; o >>= 1) {
        s0 += __shfl_xor_sync(0xffffffffu, s0, o);
        s1 += __shfl_xor_sync(0xffffffffu, s1, o);
        s2 += __shfl_xor_sync(0xffffffffu, s2, o);
        s3 += __shfl_xor_sync(0xffffffffu, s3, o);
        t0 += __shfl_xor_sync(0xffffffffu, t0, o);
        t1 += __shfl_xor_sync(0xffffffffu, t1, o);
        t2 += __shfl_xor_sync(0xffffffffu, t2, o);
        t3 += __shfl_xor_sync(0xffffffffu, t3, o);
    }
    if (lane == 0) {
        out1[warp] = make_float4(s0, s1, s2, s3);
        out2[warp] = make_float4(t0, t1, t2, t3);
    }
}

// ---------------- per-edge logits in CSR order ----------------
__device__ __forceinline__ float hg_leaky(float v) { return v >= 0.f ? v : NEG_SLOPE * v; }

__global__ void hg_edge_al(const int* __restrict__ src, const int* __restrict__ dst,
                           const float4* __restrict__ als, const float4* __restrict__ ald,
                           float4* __restrict__ al) {
    int i = blockIdx.x * blockDim.x + threadIdx.x;
    if (i >= NE) return;
    float4 s = als[src[i]];
    float4 d = ald[dst[i]];
    float4 r;
    r.x = hg_leaky(s.x + d.x);
    r.y = hg_leaky(s.y + d.y);
    r.z = hg_leaky(s.z + d.z);
    r.w = hg_leaky(s.w + d.w);
    al[i] = r;
}

// ---------------- layer-0: softmax-weighted aggregation of 64-dim x into head blocks --
// aggx[dst][h*64+c] = sum_e alpha[e,h] * x[src_e][c]. warp per dst node.
__global__ void hg_agg64(const float* __restrict__ x, const int* __restrict__ srcs,
                         const float4* __restrict__ al, const int* __restrict__ rp,
                         float* __restrict__ aggx, int ndst) {
    int warp = (blockIdx.x * blockDim.x + threadIdx.x) >> 5;
    int lane = threadIdx.x & 31;
    if (warp >= ndst) return;
    int beg = rp[warp], end = rp[warp + 1];
    int c0 = lane * 8;
    int hl = lane >> 3;
    int xo = c0 & 63;

    float acc[8] = {0.f, 0.f, 0.f, 0.f, 0.f, 0.f, 0.f, 0.f};
    if (beg < end) {
        float m0 = -3.4e38f, m1 = -3.4e38f, m2 = -3.4e38f, m3 = -3.4e38f;
        for (int t = beg; t < end; t++) {
            float4 a = al[t];
            m0 = fmaxf(m0, a.x); m1 = fmaxf(m1, a.y);
            m2 = fmaxf(m2, a.z); m3 = fmaxf(m3, a.w);
        }
        float d0 = 0.f, d1 = 0.f, d2 = 0.f, d3 = 0.f;
        for (int t = beg; t < end; t++) {
            float4 a = al[t];
            d0 += __expf(a.x - m0); d1 += __expf(a.y - m1);
            d2 += __expf(a.z - m2); d3 += __expf(a.w - m3);
        }
        float mh = (hl & 2) ? ((hl & 1) ? m3 : m2) : ((hl & 1) ? m1 : m0);
        float dh = (hl & 2) ? ((hl & 1) ? d3 : d2) : ((hl & 1) ? d1 : d0);
        float inv = 1.f / dh;
        for (int t = beg; t < end; t++) {
            int sidx = srcs[t];
            float4 a = al[t];
            float av = (hl & 2) ? ((hl & 1) ? a.w : a.z) : ((hl & 1) ? a.y : a.x);
            float alpha = __expf(av - mh) * inv;
            const float4* hp = (const float4*)(x + (long)sidx * HDIM + xo);
            float4 v0 = hp[0], v1 = hp[1];
            acc[0] += alpha * v0.x; acc[1] += alpha * v0.y;
            acc[2] += alpha * v0.z; acc[3] += alpha * v0.w;
            acc[4] += alpha * v1.x; acc[5] += alpha * v1.y;
            acc[6] += alpha * v1.z; acc[7] += alpha * v1.w;
        }
    }
    float* op = aggx + (long)warp * HD + c0;
    *(float4*)op = make_float4(acc[0], acc[1], acc[2], acc[3]);
    *(float4*)(op + 4) = make_float4(acc[4], acc[5], acc[6], acc[7]);
}

// ---------------- layer-1 FUSED agg + bias + LN + residual + ELU (256-dim sources) ---
__global__ void hg_gat_agg_ln(const float* __restrict__ hs, const int* __restrict__ srcs,
                              const float4* __restrict__ al, const int* __restrict__ rp,
                              const float* __restrict__ bias, const float* __restrict__ gam,
                              const float* __restrict__ bet, float* __restrict__ h,
                              int residual, int ndst) {
    int warp = (blockIdx.x * blockDim.x + threadIdx.x) >> 5;
    int lane = threadIdx.x & 31;
    if (warp >= ndst) return;
    int beg = rp[warp], end = rp[warp + 1];
    int c0 = lane * 8;
    int hl = lane >> 3;

    float acc[8] = {0.f, 0.f, 0.f, 0.f, 0.f, 0.f, 0.f, 0.f};
    if (beg < end) {
        float m0 = -3.4e38f, m1 = -3.4e38f, m2 = -3.4e38f, m3 = -3.4e38f;
        for (int t = beg; t < end; t++) {
            float4 a = al[t];
            m0 = fmaxf(m0, a.x); m1 = fmaxf(m1, a.y);
            m2 = fmaxf(m2, a.z); m3 = fmaxf(m3, a.w);
        }
        float d0 = 0.f, d1 = 0.f, d2 = 0.f, d3 = 0.f;
        for (int t = beg; t < end; t++) {
            float4 a = al[t];
            d0 += __expf(a.x - m0); d1 += __expf(a.y - m1);
            d2 += __expf(a.z - m2); d3 += __expf(a.w - m3);
        }
        float mh = (hl & 2) ? ((hl & 1) ? m3 : m2) : ((hl & 1) ? m1 : m0);
        float dh = (hl & 2) ? ((hl & 1) ? d3 : d2) : ((hl & 1) ? d1 : d0);
        float inv = 1.f / dh;
        for (int t = beg; t < end; t++) {
            int sidx = srcs[t];
            float4 a = al[t];
            float av = (hl & 2) ? ((hl & 1) ? a.w : a.z) : ((hl & 1) ? a.y : a.x);
            float alpha = __expf(av - mh) * inv;
            const float4* hp = (const float4*)(hs + (long)sidx * HD + c0);
            float4 v0 = hp[0], v1 = hp[1];
            acc[0] += alpha * v0.x; acc[1] += alpha * v0.y;
            acc[2] += alpha * v0.z; acc[3] += alpha * v0.w;
            acc[4] += alpha * v1.x; acc[5] += alpha * v1.y;
            acc[6] += alpha * v1.z; acc[7] += alpha * v1.w;
        }
    }

    const float4* bp = (const float4*)(bias + c0);
    float4 b0 = bp[0], b1 = bp[1];
    float v[8] = {acc[0] + b0.x, acc[1] + b0.y, acc[2] + b0.z, acc[3] + b0.w,
                  acc[4] + b1.x, acc[5] + b1.y, acc[6] + b1.z, acc[7] + b1.w};
    float sum = 0.f, sq = 0.f;
    #pragma unroll
    for (int j = 0; j < 8; j++) { sum += v[j]; sq += v[j] * v[j]; }
    #pragma unroll
    for (int o = 16; o > 0; o >>= 1) {
        sum += __shfl_xor_sync(0xffffffffu, sum, o);
        sq  += __shfl_xor_sync(0xffffffffu, sq, o);
    }
    float mu = sum * (1.f / HD);
    float var = sq * (1.f / HD) - mu * mu;
    float rstd = rsqrtf(var + LN_EPS);

    const float4* gp = (const float4*)(gam + c0);
    const float4* ep = (const float4*)(bet + c0);
    float4 g0 = gp[0], g1 = gp[1];
    float4 e0 = ep[0], e1 = ep[1];
    float gm[8] = {g0.x, g0.y, g0.z, g0.w, g1.x, g1.y, g1.z, g1.w};
    float bt[8] = {e0.x, e0.y, e0.z, e0.w, e1.x, e1.y, e1.z, e1.w};
    float* hp = h + (long)warp * HD + c0;
    float r[8] = {0.f, 0.f, 0.f, 0.f, 0.f, 0.f, 0.f, 0.f};
    if (residual) {
        float4 r0 = ((const float4*)hp)[0], r1 = ((const float4*)hp)[1];
        r[0] = r0.x; r[1] = r0.y; r[2] = r0.z; r[3] = r0.w;
        r[4] = r1.x; r[5] = r1.y; r[6] = r1.z; r[7] = r1.w;
    }
    float y[8];
    #pragma unroll
    for (int j = 0; j < 8; j++) {
        float t = (v[j] - mu) * rstd * gm[j] + bt[j] + r[j];
        y[j] = t > 0.f ? t : expm1f(t);
    }
    *(float4*)hp = make_float4(y[0], y[1], y[2], y[3]);
    *(float4*)(hp + 4) = make_float4(y[4], y[5], y[6], y[7]);
}

// ---------------- mean pooling addr -> tx (warp per tx node) ----------------
__global__ void hg_pool_mean(const float* __restrict__ haddr, const int* __restrict__ srcs,
                             const int* __restrict__ rp, float* __restrict__ out, int ndst) {
    int warp = (blockIdx.x * blockDim.x + threadIdx.x) >> 5;
    int lane = threadIdx.x & 31;
    if (warp >= ndst) return;
    int beg = rp[warp], end = rp[warp + 1];
    int c0 = lane * 8;
    float acc[8] = {0.f, 0.f, 0.f, 0.f, 0.f, 0.f, 0.f, 0.f};
    for (int t = beg; t < end; t++) {
        int s = srcs[t];
        const float4* hp = (const float4*)(haddr + (long)s * HD + c0);
        float4 v0 = hp[0], v1 = hp[1];
        acc[0] += v0.x; acc[1] += v0.y; acc[2] += v0.z; acc[3] += v0.w;
        acc[4] += v1.x; acc[5] += v1.y; acc[6] += v1.z; acc[7] += v1.w;
    }
    int deg = end - beg;
    float inv = 1.f / (float)(deg > 0 ? deg : 1);
    float* op = out + (long)warp * HD + c0;
    *(float4*)op = make_float4(acc[0] * inv, acc[1] * inv, acc[2] * inv, acc[3] * inv);
    *(float4*)(op + 4) = make_float4(acc[4] * inv, acc[5] * inv, acc[6] * inv, acc[7] * inv);
}

// ---------------- host launcher ----------------
#define SYMADDR(p, s) do { void* _t = nullptr; cudaGetSymbolAddress(&_t, s); p = (decltype(p))_t; } while (0)

static inline void launch_gemm(const float* A, const float* B, const float* bias,
                               float* C, int M, int N, int K) {
    dim3 grid((N + BN - 1) / BN, (M + BM - 1) / BM);
    hg_sgemm<<<grid, 256>>>(A, B, bias, C, M, N, K);
}

extern "C" void kernel_launch(void* const* d_in, const int* in_sizes, int n_in,
                              void* d_out, int out_size) {
    const float* x_tx      = (const float*)d_in[0];
    const float* x_addr    = (const float*)d_in[1];
    const int*   addr_idx_at = (const int*)d_in[2];
    const int*   tx_idx_at   = (const int*)d_in[3];
    const int*   tx_idx_ta   = (const int*)d_in[4];
    const int*   addr_idx_ta = (const int*)d_in[5];
    const float* w_in_tx   = (const float*)d_in[6];
    const float* b_in_tx   = (const float*)d_in[7];
    const float* w_in_addr = (const float*)d_in[8];
    const float* b_in_addr = (const float*)d_in[9];
    const float* w_at0 = (const float*)d_in[10];
    const float* as_at0 = (const float*)d_in[11];
    const float* ad_at0 = (const float*)d_in[12];
    const float* b_at0 = (const float*)d_in[13];
    const float* w_ta0 = (const float*)d_in[14];
    const float* as_ta0 = (const float*)d_in[15];
    const float* ad_ta0 = (const float*)d_in[16];
    const float* b_ta0 = (const float*)d_in[17];
    // layer-1 at-relation weights are dead (h_tx after layer 1 unused by output)
    const float* w_ta1 = (const float*)d_in[22];
    const float* as_ta1 = (const float*)d_in[23];
    const float* ad_ta1 = (const float*)d_in[24];
    const float* b_ta1 = (const float*)d_in[25];
    const float* ln_g_tx = (const float*)d_in[26];
    const float* ln_b_tx = (const float*)d_in[27];
    const float* ln_g_addr = (const float*)d_in[28];
    const float* ln_b_addr = (const float*)d_in[29];
    const float* w_out = (const float*)d_in[30];
    const float* b_out = (const float*)d_in[31];
    float* out = (float*)d_out;

    float *p_htx64, *p_haddr64, *p_buf_addr, *p_buf_tx, *p_pool_tx, *p_htx, *p_haddr;
    float4 *p_als_at, *p_ald_at, *p_als_ta, *p_ald_ta, *p_al_at, *p_al_ta;
    int *p_cnt_tx, *p_cnt_addr, *p_rp_at, *p_rp_ta, *p_cur_tx, *p_cur_addr;
    int *p_src_at, *p_dst_at, *p_src_ta, *p_dst_ta, *p_bsum_tx, *p_bsum_addr;
    float *p_ws_at, *p_wd_at, *p_ws_ta, *p_wd_ta, *p_ws_ta1, *p_wd_ta1;
    SYMADDR(p_htx64, g_htx64);     SYMADDR(p_haddr64, g_haddr64);
    SYMADDR(p_buf_addr, g_buf_addr); SYMADDR(p_buf_tx, g_buf_tx);
    SYMADDR(p_pool_tx, g_pool_tx);
    SYMADDR(p_htx, g_htx);         SYMADDR(p_haddr, g_haddr);
    SYMADDR(p_als_at, g_als_at);   SYMADDR(p_ald_at, g_ald_at);
    SYMADDR(p_als_ta, g_als_ta);   SYMADDR(p_ald_ta, g_ald_ta);
    SYMADDR(p_al_at, g_al_at);     SYMADDR(p_al_ta, g_al_ta);
    SYMADDR(p_cnt_tx, g_cnt_tx);   SYMADDR(p_cnt_addr, g_cnt_addr);
    SYMADDR(p_rp_at, g_rp_at);     SYMADDR(p_rp_ta, g_rp_ta);
    SYMADDR(p_cur_tx, g_cur_tx);   SYMADDR(p_cur_addr, g_cur_addr);
    SYMADDR(p_src_at, g_src_at);   SYMADDR(p_dst_at, g_dst_at);
    SYMADDR(p_src_ta, g_src_ta);   SYMADDR(p_dst_ta, g_dst_ta);
    SYMADDR(p_bsum_tx, g_bsum_tx); SYMADDR(p_bsum_addr, g_bsum_addr);
    SYMADDR(p_ws_at, g_ws_at);     SYMADDR(p_wd_at, g_wd_at);
    SYMADDR(p_ws_ta, g_ws_ta);     SYMADDR(p_wd_ta, g_wd_ta);
    SYMADDR(p_ws_ta1, g_ws_ta1);   SYMADDR(p_wd_ta1, g_wd_ta1);

    const int TB = 256;
    const int nb_tx = (N_TX + 1023) / 1024;
    const int nb_addr = (N_ADDR + 1023) / 1024;
    int cblk_tx = (N_TX * 32 + TB - 1) / TB;
    int cblk_addr = (N_ADDR * 32 + TB - 1) / TB;
    int eblk = (NE + TB - 1) / TB;

    // ---- CSR build ----
    hg_zero2<<<(N_ADDR + TB - 1) / TB, TB>>>(p_cnt_tx, N_TX, p_cnt_addr, N_ADDR);
    hg_count<<<(NE + TB - 1) / TB, TB>>>(tx_idx_at, p_cnt_tx, addr_idx_ta, p_cnt_addr);
    hg_scan1<<<nb_tx, 1024>>>(p_cnt_tx, p_rp_at, p_bsum_tx, N_TX);
    hg_scan1<<<nb_addr, 1024>>>(p_cnt_addr, p_rp_ta, p_bsum_addr, N_ADDR);
    hg_scan1<<<1, 1024>>>(p_bsum_tx, p_bsum_tx - 1, nullptr, nb_tx);
    hg_scan1<<<1, 1024>>>(p_bsum_addr, p_bsum_addr - 1, nullptr, nb_addr);
    hg_scan3<<<(N_TX + TB - 1) / TB, TB>>>(p_rp_at, p_bsum_tx, N_TX);
    hg_scan3<<<(N_ADDR + TB - 1) / TB, TB>>>(p_rp_ta, p_bsum_addr, N_ADDR);
    cudaMemcpyAsync(p_cur_tx, p_rp_at, N_TX * sizeof(int), cudaMemcpyDeviceToDevice);
    cudaMemcpyAsync(p_cur_addr, p_rp_ta, N_ADDR * sizeof(int), cudaMemcpyDeviceToDevice);
    hg_fill<<<(NE + TB - 1) / TB, TB>>>(addr_idx_at, tx_idx_at, p_cur_tx, p_src_at, p_dst_at,
                                        tx_idx_ta, addr_idx_ta, p_cur_addr, p_src_ta, p_dst_ta);

    // ---- input projections ----
    launch_gemm(x_tx, w_in_tx, b_in_tx, p_htx64, N_TX, HDIM, F_TX);
    launch_gemm(x_addr, w_in_addr, b_in_addr, p_haddr64, N_ADDR, HDIM, F_ADDR);

    // ---- fold attention weight vectors ----
    hg_att_w<<<HDIM, 128>>>(w_at0, as_at0, p_ws_at);
    hg_att_w<<<HDIM, 128>>>(w_at0, ad_at0, p_wd_at);
    hg_att_w<<<HDIM, 128>>>(w_ta0, as_ta0, p_ws_ta);
    hg_att_w<<<HDIM, 128>>>(w_ta0, ad_ta0, p_wd_ta);
    hg_att_w<<<HD, 128>>>(w_ta1, as_ta1, p_ws_ta1);
    hg_att_w<<<HD, 128>>>(w_ta1, ad_ta1, p_wd_ta1);

    // ---- layer 0: coefficients from h64, logits, aggregate-then-project ----
    hg_coef2<<<cblk_addr, TB>>>(p_haddr64, p_ws_at, p_wd_ta, p_als_at, p_ald_ta,
                                N_ADDR, HDIM);
    hg_coef2<<<cblk_tx,   TB>>>(p_htx64,   p_wd_at, p_ws_ta, p_ald_at, p_als_ta,
                                N_TX, HDIM);

    hg_edge_al<<<eblk, TB>>>(p_src_at, p_dst_at, p_als_at, p_ald_at, p_al_at);
    hg_edge_al<<<eblk, TB>>>(p_src_ta, p_dst_ta, p_als_ta, p_ald_ta, p_al_ta);

    // aggregate 64-dim sources into head-blocked aggx
    hg_agg64<<<cblk_tx,   TB>>>(p_haddr64, p_src_at, p_al_at, p_rp_at, p_buf_tx, N_TX);
    hg_agg64<<<cblk_addr, TB>>>(p_htx64,   p_src_ta, p_al_ta, p_rp_ta, p_buf_addr, N_ADDR);

    // block-diagonal GEMM + bias + LN + ELU + next-layer coef
    hg_gemm_ln<<<(N_TX + 63) / 64, 256>>>(p_buf_tx, w_at0, b_at0, ln_g_tx, ln_b_tx,
                                          p_htx, (const float4*)p_ws_ta1, p_als_ta, N_TX);
    hg_gemm_ln<<<(N_ADDR + 63) / 64, 256>>>(p_buf_addr, w_ta0, b_ta0, ln_g_addr, ln_b_addr,
                                            p_haddr, (const float4*)p_wd_ta1, p_ald_ta,
                                            N_ADDR);

    // ---- layer 1 (ta relation only; tx branch is dead): project-then-aggregate ----
    launch_gemm(p_htx, w_ta1, nullptr, p_buf_tx, N_TX, HD, HD);

    hg_edge_al<<<eblk, TB>>>(p_src_ta, p_dst_ta, p_als_ta, p_ald_ta, p_al_ta);

    hg_gat_agg_ln<<<cblk_addr, TB>>>(p_buf_tx, p_src_ta, p_al_ta, p_rp_ta,
                                     b_ta1, ln_g_addr, ln_b_addr, p_haddr, 1, N_ADDR);

    // ---- scatter-mean pooling addr -> tx over 'at' edges ----
    hg_pool_mean<<<cblk_tx, TB>>>(p_haddr, p_src_at, p_rp_at, p_pool_tx, N_TX);

    // ---- output projection ----
    launch_gemm(p_pool_tx, w_out, b_out, out, N_TX, HD, HD);
}

// round 14
// speedup vs baseline: 1.3397x; 1.0200x over previous
#include <cuda_runtime.h>
#include <math.h>
#include <stdint.h>

// ---------------- problem constants ----------------
#define N_TX   100000
#define N_ADDR 200000
#define NE     400000
#define F_TX   165
#define F_ADDR 64
#define HDIM   64
#define HD     256
#define LN_EPS 1e-5f
#define NEG_SLOPE 0.2f

// ---------------- scratch (device globals; no cudaMalloc allowed) ----------------
__device__ float g_htx64[(size_t)N_TX * HDIM];
__device__ float g_haddr64[(size_t)N_ADDR * HDIM];
__device__ float g_buf_addr[(size_t)N_ADDR * HD];  // aggx_addr (L0)
__device__ float g_buf_tx[(size_t)N_TX * HD];      // aggx_tx (L0), then hs_ta (L1)
__device__ float g_pool_tx[(size_t)N_TX * HD];
__device__ float g_htx[(size_t)N_TX * HD];
__device__ float g_haddr[(size_t)N_ADDR * HD];
__device__ float4 g_als_at[N_ADDR];
__device__ float4 g_ald_at[N_TX];
__device__ float4 g_als_ta[N_TX];
__device__ float4 g_ald_ta[N_ADDR];
__device__ float4 g_al_at[NE];
__device__ float4 g_al_ta[NE];
__device__ int g_cnt_tx[N_TX];
__device__ int g_cnt_addr[N_ADDR];
__device__ int g_rp_at[N_TX + 1];
__device__ int g_rp_ta[N_ADDR + 1];
__device__ int g_cur_tx[N_TX];
__device__ int g_cur_addr[N_ADDR];
__device__ int g_src_at[NE];
__device__ int g_dst_at[NE];
__device__ int g_src_ta[NE];
__device__ int g_dst_ta[NE];
__device__ int g_bsum_tx[256];
__device__ int g_bsum_addr[256];
__device__ float g_ws_at[HD * 4];
__device__ float g_wd_at[HD * 4];
__device__ float g_ws_ta[HD * 4];
__device__ float g_wd_ta[HD * 4];
__device__ float g_ws_ta1[HD * 4];
__device__ float g_wd_ta1[HD * 4];

// ---------------- packed f32x2 helpers (sm_103a FFMA2 pipe) ----------------
__device__ __forceinline__ unsigned long long hg_pack2(float x, float y) {
    unsigned long long r;
    asm("mov.b64 %0, {%1, %2};" : "=l"(r) : "f"(x), "f"(y));
    return r;
}
__device__ __forceinline__ void hg_unpack2(unsigned long long v, float& x, float& y) {
    asm("mov.b64 {%0, %1}, %2;" : "=f"(x), "=f"(y) : "l"(v));
}
__device__ __forceinline__ void hg_ffma2(unsigned long long& d,
                                         unsigned long long a, unsigned long long b) {
    asm("fma.rn.f32x2 %0, %1, %2, %0;" : "+l"(d) : "l"(a), "l"(b));
}

// ---------------- SGEMM: C[M,N] = A[M,K] @ B[K,N] (+bias), FFMA2 inner loop ----------
#define BM 128
#define BN 128
#define BK 16
#define TM 8
#define TN 8

__global__ __launch_bounds__(256)
void hg_sgemm(const float* __restrict__ A, const float* __restrict__ B,
              const float* __restrict__ bias, float* __restrict__ C,
              int M, int N, int K) {
    __shared__ float As[2][BK][BM];
    __shared__ float Bs[2][BK][BN];
    int tid = threadIdx.x;
    int row0 = blockIdx.y * BM, col0 = blockIdx.x * BN;
    int tx = tid & 15, ty = tid >> 4;
    int arow = tid >> 1, acol = (tid & 1) * 8;
    int brow = tid >> 4, bcol = (tid & 15) * 8;
    bool k4 = ((K & 3) == 0);
    int nk = (K + BK - 1) / BK;

    float ra[8];
    float4 rb0, rb1;

    unsigned long long acc2[TM][TN / 2];
    #pragma unroll
    for (int i = 0; i < TM; i++)
        #pragma unroll
        for (int j = 0; j < TN / 2; j++) acc2[i][j] = 0ull;

    auto loadA = [&](int k0) {
        int gr = row0 + arow;
        if (k4) {
            #pragma unroll
            for (int i = 0; i < 8; i += 4) {
                int gk = k0 + acol + i;
                float4 v = make_float4(0.f, 0.f, 0.f, 0.f);
                if (gr < M && gk < K) v = *(const float4*)(A + (long)gr * K + gk);
                ra[i] = v.x; ra[i + 1] = v.y; ra[i + 2] = v.z; ra[i + 3] = v.w;
            }
        } else {
            #pragma unroll
            for (int i = 0; i < 8; i++) {
                int gk = k0 + acol + i;
                ra[i] = (gr < M && gk < K) ? A[(long)gr * K + gk] : 0.f;
            }
        }
    };
    auto loadB = [&](int k0) {
        int gk = k0 + brow, gn = col0 + bcol;
        rb0 = make_float4(0.f, 0.f, 0.f, 0.f);
        rb1 = rb0;
        if (gk < K && gn < N) {
            rb0 = *(const float4*)(B + (long)gk * N + gn);
            rb1 = *(const float4*)(B + (long)gk * N + gn + 4);
        }
    };
    auto storeA = [&](int s) {
        #pragma unroll
        for (int i = 0; i < 8; i++) As[s][acol + i][arow] = ra[i];
    };
    auto storeB = [&](int s) {
        *(float4*)&Bs[s][brow][bcol] = rb0;
        *(float4*)&Bs[s][brow][bcol + 4] = rb1;
    };

    loadA(0); loadB(0);
    storeA(0); storeB(0);
    __syncthreads();

    int s = 0;
    for (int t = 0; t < nk; t++) {
        if (t + 1 < nk) { loadA((t + 1) * BK); loadB((t + 1) * BK); }
        #pragma unroll
        for (int k = 0; k < BK; k++) {
            float4 a0 = *(float4*)&As[s][k][ty * TM];
            float4 a1 = *(float4*)&As[s][k][ty * TM + 4];
            // direct f32x2-pair loads of B (no pack MOVs)
            ulonglong2 bb0 = *(ulonglong2*)&Bs[s][k][tx * TN];
            ulonglong2 bb1 = *(ulonglong2*)&Bs[s][k][tx * TN + 4];
            unsigned long long b2[4] = {bb0.x, bb0.y, bb1.x, bb1.y};
            float af[8] = {a0.x, a0.y, a0.z, a0.w, a1.x, a1.y, a1.z, a1.w};
            #pragma unroll
            for (int i = 0; i < TM; i++) {
                unsigned long long a2 = hg_pack2(af[i], af[i]);
                #pragma unroll
                for (int j = 0; j < TN / 2; j++) hg_ffma2(acc2[i][j], a2, b2[j]);
            }
        }
        if (t + 1 < nk) {
            storeA(s ^ 1); storeB(s ^ 1);
            __syncthreads();
            s ^= 1;
        }
    }

    int gc = col0 + tx * TN;
    if (gc >= N) return;
    float bsv[8];
    #pragma unroll
    for (int j = 0; j < 8; j++) bsv[j] = bias ? bias[gc + j] : 0.f;
    #pragma unroll
    for (int i = 0; i < TM; i++) {
        int gr = row0 + ty * TM + i;
        if (gr >= M) continue;
        float acc[8];
        #pragma unroll
        for (int j = 0; j < 4; j++) hg_unpack2(acc2[i][j], acc[2 * j], acc[2 * j + 1]);
        float* cp = C + (long)gr * N + gc;
        *(float4*)cp = make_float4(acc[0] + bsv[0], acc[1] + bsv[1],
                                   acc[2] + bsv[2], acc[3] + bsv[3]);
        *(float4*)(cp + 4) = make_float4(acc[4] + bsv[4], acc[5] + bsv[5],
                                         acc[6] + bsv[6], acc[7] + bsv[7]);
    }
}

// ---------------- block-diagonal GEMM (K=64 per head) + bias + LN + ELU + coef -------
#define GL_BK 16

__global__ __launch_bounds__(256)
void hg_gemm_ln(const float* __restrict__ A, const float* __restrict__ W,
                const float* __restrict__ bias, const float* __restrict__ gam,
                const float* __restrict__ bet, float* __restrict__ h,
                const float4* __restrict__ wvn, float4* __restrict__ coef, int M) {
    __shared__ float As[GL_BK][4][68];
    __shared__ float Bs[GL_BK][256];
    int tid = threadIdx.x, tx = tid & 31, ty = tid >> 5;
    int row0 = blockIdx.x * 64;
    int arow = tid & 63, apart = tid >> 6;
    int head = tx >> 3;

    unsigned long long acc2[8][4];
    #pragma unroll
    for (int i = 0; i < 8; i++)
        #pragma unroll
        for (int j = 0; j < 4; j++) acc2[i][j] = 0ull;

    for (int k0 = 0; k0 < 64; k0 += GL_BK) {
        __syncthreads();
        {
            int gr = row0 + arow;
            float4 t0 = make_float4(0.f, 0.f, 0.f, 0.f), t1 = t0, t2 = t0, t3 = t0;
            if (gr < M) {
                const float4* ap = (const float4*)(A + (long)gr * HD + apart * 64 + k0);
                t0 = ap[0]; t1 = ap[1]; t2 = ap[2]; t3 = ap[3];
            }
            float vv[16] = {t0.x, t0.y, t0.z, t0.w, t1.x, t1.y, t1.z, t1.w,
                            t2.x, t2.y, t2.z, t2.w, t3.x, t3.y, t3.z, t3.w};
            #pragma unroll
            for (int k = 0; k < GL_BK; k++) As[k][apart][arow] = vv[k];
        }
        {
            int kk = tid >> 4, c = (tid & 15) * 4;
            const float* wp = W + (long)(k0 + kk) * HD;
            #pragma unroll
            for (int q = 0; q < 4; q++)
                *(float4*)&Bs[kk][c + q * 64] = *(const float4*)(wp + c + q * 64);
        }
        __syncthreads();

        #pragma unroll
        for (int k = 0; k < GL_BK; k++) {
            float4 a0 = *(float4*)&As[k][head][ty * 8];
            float4 a1 = *(float4*)&As[k][head][ty * 8 + 4];
            ulonglong2 bb0 = *(ulonglong2*)&Bs[k][tx * 8];
            ulonglong2 bb1 = *(ulonglong2*)&Bs[k][tx * 8 + 4];
            unsigned long long b2[4] = {bb0.x, bb0.y, bb1.x, bb1.y};
            float af[8] = {a0.x, a0.y, a0.z, a0.w, a1.x, a1.y, a1.z, a1.w};
            #pragma unroll
            for (int i = 0; i < 8; i++) {
                unsigned long long a2 = hg_pack2(af[i], af[i]);
                #pragma unroll
                for (int j = 0; j < 4; j++) hg_ffma2(acc2[i][j], a2, b2[j]);
            }
        }
    }

    int cbase = tx * 8;
    float bsv[8], gmv[8], btv[8];
    {
        float4 t0 = *(const float4*)(bias + cbase), t1 = *(const float4*)(bias + cbase + 4);
        bsv[0]=t0.x; bsv[1]=t0.y; bsv[2]=t0.z; bsv[3]=t0.w;
        bsv[4]=t1.x; bsv[5]=t1.y; bsv[6]=t1.z; bsv[7]=t1.w;
        t0 = *(const float4*)(gam + cbase); t1 = *(const float4*)(gam + cbase + 4);
        gmv[0]=t0.x; gmv[1]=t0.y; gmv[2]=t0.z; gmv[3]=t0.w;
        gmv[4]=t1.x; gmv[5]=t1.y; gmv[6]=t1.z; gmv[7]=t1.w;
        t0 = *(const float4*)(bet + cbase); t1 = *(const float4*)(bet + cbase + 4);
        btv[0]=t0.x; btv[1]=t0.y; btv[2]=t0.z; btv[3]=t0.w;
        btv[4]=t1.x; btv[5]=t1.y; btv[6]=t1.z; btv[7]=t1.w;
    }
    float4 wv4[8];
    if (wvn) {
        #pragma unroll
        for (int j = 0; j < 8; j++) wv4[j] = wvn[cbase + j];
    }

    #pragma unroll
    for (int i = 0; i < 8; i++) {
        int r = row0 + ty * 8 + i;
        float v[8];
        #pragma unroll
        for (int j = 0; j < 4; j++) hg_unpack2(acc2[i][j], v[2 * j], v[2 * j + 1]);
        #pragma unroll
        for (int j = 0; j < 8; j++) v[j] += bsv[j];
        float sum = 0.f, sq = 0.f;
        #pragma unroll
        for (int j = 0; j < 8; j++) { sum += v[j]; sq += v[j] * v[j]; }
        #pragma unroll
        for (int o = 16; o > 0; o >>= 1) {
            sum += __shfl_xor_sync(0xffffffffu, sum, o);
            sq  += __shfl_xor_sync(0xffffffffu, sq, o);
        }
        float mu = sum * (1.f / HD);
        float var = sq * (1.f / HD) - mu * mu;
        float rstd = rsqrtf(var + LN_EPS);
        float y[8];
        #pragma unroll
        for (int j = 0; j < 8; j++) {
            float t = (v[j] - mu) * rstd * gmv[j] + btv[j];
            y[j] = t > 0.f ? t : expm1f(t);
        }
        if (r < M) {
            float* hp = h + (long)r * HD + cbase;
            *(float4*)hp = make_float4(y[0], y[1], y[2], y[3]);
            *(float4*)(hp + 4) = make_float4(y[4], y[5], y[6], y[7]);
        }
        if (wvn) {
            float p0 = 0.f, p1 = 0.f, p2 = 0.f, p3 = 0.f;
            #pragma unroll
            for (int j = 0; j < 8; j++) {
                p0 += y[j] * wv4[j].x; p1 += y[j] * wv4[j].y;
                p2 += y[j] * wv4[j].z; p3 += y[j] * wv4[j].w;
            }
            #pragma unroll
            for (int o = 16; o > 0; o >>= 1) {
                p0 += __shfl_xor_sync(0xffffffffu, p0, o);
                p1 += __shfl_xor_sync(0xffffffffu, p1, o);
                p2 += __shfl_xor_sync(0xffffffffu, p2, o);
                p3 += __shfl_xor_sync(0xffffffffu, p3, o);
            }
            if (tx == 0 && r < M) coef[r] = make_float4(p0, p1, p2, p3);
        }
    }
}

// ---------------- CSR build ----------------
__global__ void hg_zero2(int* a, int na, int* b, int nb) {
    int i = blockIdx.x * blockDim.x + threadIdx.x;
    if (i < na) a[i] = 0;
    if (i < nb) b[i] = 0;
}

__global__ void hg_count(const int* __restrict__ dst_at, int* cnt_at,
                         const int* __restrict__ dst_ta, int* cnt_ta) {
    int i = blockIdx.x * blockDim.x + threadIdx.x;
    if (i < NE) {
        atomicAdd(&cnt_at[dst_at[i]], 1);
        atomicAdd(&cnt_ta[dst_ta[i]], 1);
    }
}

__device__ __forceinline__ int hg_warp_incl_scan(int v, int lane) {
    #pragma unroll
    for (int o = 1; o < 32; o <<= 1) {
        int t = __shfl_up_sync(0xffffffffu, v, o);
        if (lane >= o) v += t;
    }
    return v;
}

__global__ void hg_scan1(const int* __restrict__ cnt, int* __restrict__ rp,
                         int* __restrict__ bsum, int n) {
    __shared__ int ws[32];
    int lane = threadIdx.x & 31, wid = threadIdx.x >> 5;
    int i = blockIdx.x * 1024 + threadIdx.x;
    int v = (i < n) ? cnt[i] : 0;
    int s = hg_warp_incl_scan(v, lane);
    if (lane == 31) ws[wid] = s;
    __syncthreads();
    if (wid == 0) {
        int w = ws[lane];
        w = hg_warp_incl_scan(w, lane);
        ws[lane] = w;
    }
    __syncthreads();
    s += (wid ? ws[wid - 1] : 0);
    if (i < n) rp[i + 1] = s;
    if (bsum && threadIdx.x == 1023) bsum[blockIdx.x] = s;
}

__global__ void hg_scan3(int* __restrict__ rp, const int* __restrict__ bsum, int n) {
    int i = blockIdx.x * blockDim.x + threadIdx.x;
    if (i == 0) rp[0] = 0;
    if (i < n) {
        int b = i >> 10;
        if (b > 0) rp[i + 1] += bsum[b - 1];
    }
}

__global__ void hg_fill(const int* __restrict__ s_at, const int* __restrict__ d_at,
                        int* cur_at, int* src_at, int* dst_at,
                        const int* __restrict__ s_ta, const int* __restrict__ d_ta,
                        int* cur_ta, int* src_ta, int* dst_ta) {
    int i = blockIdx.x * blockDim.x + threadIdx.x;
    if (i < NE) {
        int d0 = d_at[i];
        int p = atomicAdd(&cur_at[d0], 1);
        src_at[p] = s_at[i];
        dst_at[p] = d0;
        int d1 = d_ta[i];
        int q = atomicAdd(&cur_ta[d1], 1);
        src_ta[q] = s_ta[i];
        dst_ta[q] = d1;
    }
}

// ---------------- folded attention weights, all 6 in one launch ----------------
struct AttW6 {
    const float* W[6];
    const float* a[6];
    float* o[6];
    int K[6];
};

__global__ void hg_att_w6(AttW6 p) {
    int j = blockIdx.y;
    int k = blockIdx.x;
    if (k >= p.K[j]) return;
    int head = threadIdx.x >> 5, lane = threadIdx.x & 31;
    const float* wr = p.W[j] + (long)k * HD + head * 64;
    const float* ar = p.a[j] + head * 64;
    float s = wr[lane] * ar[lane] + wr[lane + 32] * ar[lane + 32];
    #pragma unroll
    for (int o = 16; o > 0; o >>= 1) s += __shfl_xor_sync(0xffffffffu, s, o);
    if (lane == 0) p.o[j][k * 4 + head] = s;
}

// ---------------- fused node coefficients (layer-0, from h64) ----------------
__global__ void hg_coef2(const float* __restrict__ x,
                         const float* __restrict__ Wv1, const float* __restrict__ Wv2,
                         float4* __restrict__ out1, float4* __restrict__ out2,
                         int n, int K) {
    int warp = (blockIdx.x * blockDim.x + threadIdx.x) >> 5;
    int lane = threadIdx.x & 31;
    if (warp >= n) return;
    const float* xp = x + (long)warp * K;
    const float4* wv1 = (const float4*)Wv1;
    const float4* wv2 = (const float4*)Wv2;
    float s0 = 0.f, s1 = 0.f, s2 = 0.f, s3 = 0.f;
    float t0 = 0.f, t1 = 0.f, t2 = 0.f, t3 = 0.f;
    for (int k = lane; k < K; k += 32) {
        float xv = xp[k];
        float4 w1 = wv1[k];
        float4 w2 = wv2[k];
        s0 += xv * w1.x; s1 += xv * w1.y; s2 += xv * w1.z; s3 += xv * w1.w;
        t0 += xv * w2.x; t1 += xv * w2.y; t2 += xv * w2.z; t3 += xv * w2.w;
    }
    #pragma unroll
    for (int o = 16; o > 0; o >>= 1) {
        s0 += __shfl_xor_sync(0xffffffffu, s0, o);
        s1 += __shfl_xor_sync(0xffffffffu, s1, o);
        s2 += __shfl_xor_sync(0xffffffffu, s2, o);
        s3 += __shfl_xor_sync(0xffffffffu, s3, o);
        t0 += __shfl_xor_sync(0xffffffffu, t0, o);
        t1 += __shfl_xor_sync(0xffffffffu, t1, o);
        t2 += __shfl_xor_sync(0xffffffffu, t2, o);
        t3 += __shfl_xor_sync(0xffffffffu, t3, o);
    }
    if (lane == 0) {
        out1[warp] = make_float4(s0, s1, s2, s3);
        out2[warp] = make_float4(t0, t1, t2, t3);
    }
}

// ---------------- per-edge logits in CSR order ----------------
__device__ __forceinline__ float hg_leaky(float v) { return v >= 0.f ? v : NEG_SLOPE * v; }

__global__ void hg_edge_al(const int* __restrict__ src, const int* __restrict__ dst,
                           const float4* __restrict__ als, const float4* __restrict__ ald,
                           float4* __restrict__ al) {
    int i = blockIdx.x * blockDim.x + threadIdx.x;
    if (i >= NE) return;
    float4 s = als[src[i]];
    float4 d = ald[dst[i]];
    float4 r;
    r.x = hg_leaky(s.x + d.x);
    r.y = hg_leaky(s.y + d.y);
    r.z = hg_leaky(s.z + d.z);
    r.w = hg_leaky(s.w + d.w);
    al[i] = r;
}

// both layer-0 relations in one launch
__global__ void hg_edge_al2(const int* __restrict__ src0, const int* __restrict__ dst0,
                            const float4* __restrict__ als0, const float4* __restrict__ ald0,
                            float4* __restrict__ al0,
                            const int* __restrict__ src1, const int* __restrict__ dst1,
                            const float4* __restrict__ als1, const float4* __restrict__ ald1,
                            float4* __restrict__ al1) {
    int i = blockIdx.x * blockDim.x + threadIdx.x;
    if (i < NE) {
        float4 s = als0[src0[i]];
        float4 d = ald0[dst0[i]];
        al0[i] = make_float4(hg_leaky(s.x + d.x), hg_leaky(s.y + d.y),
                             hg_leaky(s.z + d.z), hg_leaky(s.w + d.w));
    } else if (i < 2 * NE) {
        int j = i - NE;
        float4 s = als1[src1[j]];
        float4 d = ald1[dst1[j]];
        al1[j] = make_float4(hg_leaky(s.x + d.x), hg_leaky(s.y + d.y),
                             hg_leaky(s.z + d.z), hg_leaky(s.w + d.w));
    }
}

// ---------------- layer-0: 2-pass softmax agg of 64-dim x into head blocks ------------
__global__ void hg_agg64(const float* __restrict__ x, const int* __restrict__ srcs,
                         const float4* __restrict__ al, const int* __restrict__ rp,
                         float* __restrict__ aggx, int ndst) {
    int warp = (blockIdx.x * blockDim.x + threadIdx.x) >> 5;
    int lane = threadIdx.x & 31;
    if (warp >= ndst) return;
    int beg = rp[warp], end = rp[warp + 1];
    int c0 = lane * 8;
    int hl = lane >> 3;
    int xo = c0 & 63;

    float acc[8] = {0.f, 0.f, 0.f, 0.f, 0.f, 0.f, 0.f, 0.f};
    if (beg < end) {
        float m0 = -3.4e38f, m1 = -3.4e38f, m2 = -3.4e38f, m3 = -3.4e38f;
        for (int t = beg; t < end; t++) {
            float4 a = al[t];
            m0 = fmaxf(m0, a.x); m1 = fmaxf(m1, a.y);
            m2 = fmaxf(m2, a.z); m3 = fmaxf(m3, a.w);
        }
        float mh = (hl & 2) ? ((hl & 1) ? m3 : m2) : ((hl & 1) ? m1 : m0);
        float den = 0.f;
        for (int t = beg; t < end; t++) {
            int sidx = srcs[t];
            float4 a = al[t];
            float av = (hl & 2) ? ((hl & 1) ? a.w : a.z) : ((hl & 1) ? a.y : a.x);
            float e = __expf(av - mh);
            den += e;
            const float4* hp = (const float4*)(x + (long)sidx * HDIM + xo);
            float4 v0 = hp[0], v1 = hp[1];
            acc[0] += e * v0.x; acc[1] += e * v0.y;
            acc[2] += e * v0.z; acc[3] += e * v0.w;
            acc[4] += e * v1.x; acc[5] += e * v1.y;
            acc[6] += e * v1.z; acc[7] += e * v1.w;
        }
        float inv = 1.f / den;
        #pragma unroll
        for (int j = 0; j < 8; j++) acc[j] *= inv;
    }
    float* op = aggx + (long)warp * HD + c0;
    *(float4*)op = make_float4(acc[0], acc[1], acc[2], acc[3]);
    *(float4*)(op + 4) = make_float4(acc[4], acc[5], acc[6], acc[7]);
}

// ---------------- layer-1 FUSED 2-pass agg + bias + LN + residual + ELU --------------
__global__ void hg_gat_agg_ln(const float* __restrict__ hs, const int* __restrict__ srcs,
                              const float4* __restrict__ al, const int* __restrict__ rp,
                              const float* __restrict__ bias, const float* __restrict__ gam,
                              const float* __restrict__ bet, float* __restrict__ h,
                              int residual, int ndst) {
    int warp = (blockIdx.x * blockDim.x + threadIdx.x) >> 5;
    int lane = threadIdx.x & 31;
    if (warp >= ndst) return;
    int beg = rp[warp], end = rp[warp + 1];
    int c0 = lane * 8;
    int hl = lane >> 3;

    float acc[8] = {0.f, 0.f, 0.f, 0.f, 0.f, 0.f, 0.f, 0.f};
    if (beg < end) {
        float m0 = -3.4e38f, m1 = -3.4e38f, m2 = -3.4e38f, m3 = -3.4e38f;
        for (int t = beg; t < end; t++) {
            float4 a = al[t];
            m0 = fmaxf(m0, a.x); m1 = fmaxf(m1, a.y);
            m2 = fmaxf(m2, a.z); m3 = fmaxf(m3, a.w);
        }
        float mh = (hl & 2) ? ((hl & 1) ? m3 : m2) : ((hl & 1) ? m1 : m0);
        float den = 0.f;
        for (int t = beg; t < end; t++) {
            int sidx = srcs[t];
            float4 a = al[t];
            float av = (hl & 2) ? ((hl & 1) ? a.w : a.z) : ((hl & 1) ? a.y : a.x);
            float e = __expf(av - mh);
            den += e;
            const float4* hp = (const float4*)(hs + (long)sidx * HD + c0);
            float4 v0 = hp[0], v1 = hp[1];
            acc[0] += e * v0.x; acc[1] += e * v0.y;
            acc[2] += e * v0.z; acc[3] += e * v0.w;
            acc[4] += e * v1.x; acc[5] += e * v1.y;
            acc[6] += e * v1.z; acc[7] += e * v1.w;
        }
        float inv = 1.f / den;
        #pragma unroll
        for (int j = 0; j < 8; j++) acc[j] *= inv;
    }

    const float4* bp = (const float4*)(bias + c0);
    float4 b0 = bp[0], b1 = bp[1];
    float v[8] = {acc[0] + b0.x, acc[1] + b0.y, acc[2] + b0.z, acc[3] + b0.w,
                  acc[4] + b1.x, acc[5] + b1.y, acc[6] + b1.z, acc[7] + b1.w};
    float sum = 0.f, sq = 0.f;
    #pragma unroll
    for (int j = 0; j < 8; j++) { sum += v[j]; sq += v[j] * v[j]; }
    #pragma unroll
    for (int o = 16; o > 0; o >>= 1) {
        sum += __shfl_xor_sync(0xffffffffu, sum, o);
        sq  += __shfl_xor_sync(0xffffffffu, sq, o);
    }
    float mu = sum * (1.f / HD);
    float var = sq * (1.f / HD) - mu * mu;
    float rstd = rsqrtf(var + LN_EPS);

    const float4* gp = (const float4*)(gam + c0);
    const float4* ep = (const float4*)(bet + c0);
    float4 g0 = gp[0], g1 = gp[1];
    float4 e0 = ep[0], e1 = ep[1];
    float gm[8] = {g0.x, g0.y, g0.z, g0.w, g1.x, g1.y, g1.z, g1.w};
    float bt[8] = {e0.x, e0.y, e0.z, e0.w, e1.x, e1.y, e1.z, e1.w};
    float* hp = h + (long)warp * HD + c0;
    float r[8] = {0.f, 0.f, 0.f, 0.f, 0.f, 0.f, 0.f, 0.f};
    if (residual) {
        float4 r0 = ((const float4*)hp)[0], r1 = ((const float4*)hp)[1];
        r[0] = r0.x; r[1] = r0.y; r[2] = r0.z; r[3] = r0.w;
        r[4] = r1.x; r[5] = r1.y; r[6] = r1.z; r[7] = r1.w;
    }
    float y[8];
    #pragma unroll
    for (int j = 0; j < 8; j++) {
        float t = (v[j] - mu) * rstd * gm[j] + bt[j] + r[j];
        y[j] = t > 0.f ? t : expm1f(t);
    }
    *(float4*)hp = make_float4(y[0], y[1], y[2], y[3]);
    *(float4*)(hp + 4) = make_float4(y[4], y[5], y[6], y[7]);
}

// ---------------- mean pooling addr -> tx (warp per tx node) ----------------
__global__ void hg_pool_mean(const float* __restrict__ haddr, const int* __restrict__ srcs,
                             const int* __restrict__ rp, float* __restrict__ out, int ndst) {
    int warp = (blockIdx.x * blockDim.x + threadIdx.x) >> 5;
    int lane = threadIdx.x & 31;
    if (warp >= ndst) return;
    int beg = rp[warp], end = rp[warp + 1];
    int c0 = lane * 8;
    float acc[8] = {0.f, 0.f, 0.f, 0.f, 0.f, 0.f, 0.f, 0.f};
    for (int t = beg; t < end; t++) {
        int s = srcs[t];
        const float4* hp = (const float4*)(haddr + (long)s * HD + c0);
        float4 v0 = hp[0], v1 = hp[1];
        acc[0] += v0.x; acc[1] += v0.y; acc[2] += v0.z; acc[3] += v0.w;
        acc[4] += v1.x; acc[5] += v1.y; acc[6] += v1.z; acc[7] += v1.w;
    }
    int deg = end - beg;
    float inv = 1.f / (float)(deg > 0 ? deg : 1);
    float* op = out + (long)warp * HD + c0;
    *(float4*)op = make_float4(acc[0] * inv, acc[1] * inv, acc[2] * inv, acc[3] * inv);
    *(float4*)(op + 4) = make_float4(acc[4] * inv, acc[5] * inv, acc[6] * inv, acc[7] * inv);
}

// ---------------- host launcher ----------------
#define SYMADDR(p, s) do { void* _t = nullptr; cudaGetSymbolAddress(&_t, s); p = (decltype(p))_t; } while (0)

static inline void launch_gemm(const float* A, const float* B, const float* bias,
                               float* C, int M, int N, int K) {
    dim3 grid((N + BN - 1) / BN, (M + BM - 1) / BM);
    hg_sgemm<<<grid, 256>>>(A, B, bias, C, M, N, K);
}

extern "C" void kernel_launch(void* const* d_in, const int* in_sizes, int n_in,
                              void* d_out, int out_size) {
    const float* x_tx      = (const float*)d_in[0];
    const float* x_addr    = (const float*)d_in[1];
    const int*   addr_idx_at = (const int*)d_in[2];
    const int*   tx_idx_at   = (const int*)d_in[3];
    const int*   tx_idx_ta   = (const int*)d_in[4];
    const int*   addr_idx_ta = (const int*)d_in[5];
    const float* w_in_tx   = (const float*)d_in[6];
    const float* b_in_tx   = (const float*)d_in[7];
    const float* w_in_addr = (const float*)d_in[8];
    const float* b_in_addr = (const float*)d_in[9];
    const float* w_at0 = (const float*)d_in[10];
    const float* as_at0 = (const float*)d_in[11];
    const float* ad_at0 = (const float*)d_in[12];
    const float* b_at0 = (const float*)d_in[13];
    const float* w_ta0 = (const float*)d_in[14];
    const float* as_ta0 = (const float*)d_in[15];
    const float* ad_ta0 = (const float*)d_in[16];
    const float* b_ta0 = (const float*)d_in[17];
    // layer-1 at-relation weights are dead (h_tx after layer 1 unused by output)
    const float* w_ta1 = (const float*)d_in[22];
    const float* as_ta1 = (const float*)d_in[23];
    const float* ad_ta1 = (const float*)d_in[24];
    const float* b_ta1 = (const float*)d_in[25];
    const float* ln_g_tx = (const float*)d_in[26];
    const float* ln_b_tx = (const float*)d_in[27];
    const float* ln_g_addr = (const float*)d_in[28];
    const float* ln_b_addr = (const float*)d_in[29];
    const float* w_out = (const float*)d_in[30];
    const float* b_out = (const float*)d_in[31];
    float* out = (float*)d_out;

    float *p_htx64, *p_haddr64, *p_buf_addr, *p_buf_tx, *p_pool_tx, *p_htx, *p_haddr;
    float4 *p_als_at, *p_ald_at, *p_als_ta, *p_ald_ta, *p_al_at, *p_al_ta;
    int *p_cnt_tx, *p_cnt_addr, *p_rp_at, *p_rp_ta, *p_cur_tx, *p_cur_addr;
    int *p_src_at, *p_dst_at, *p_src_ta, *p_dst_ta, *p_bsum_tx, *p_bsum_addr;
    float *p_ws_at, *p_wd_at, *p_ws_ta, *p_wd_ta, *p_ws_ta1, *p_wd_ta1;
    SYMADDR(p_htx64, g_htx64);     SYMADDR(p_haddr64, g_haddr64);
    SYMADDR(p_buf_addr, g_buf_addr); SYMADDR(p_buf_tx, g_buf_tx);
    SYMADDR(p_pool_tx, g_pool_tx);
    SYMADDR(p_htx, g_htx);         SYMADDR(p_haddr, g_haddr);
    SYMADDR(p_als_at, g_als_at);   SYMADDR(p_ald_at, g_ald_at);
    SYMADDR(p_als_ta, g_als_ta);   SYMADDR(p_ald_ta, g_ald_ta);
    SYMADDR(p_al_at, g_al_at);     SYMADDR(p_al_ta, g_al_ta);
    SYMADDR(p_cnt_tx, g_cnt_tx);   SYMADDR(p_cnt_addr, g_cnt_addr);
    SYMADDR(p_rp_at, g_rp_at);     SYMADDR(p_rp_ta, g_rp_ta);
    SYMADDR(p_cur_tx, g_cur_tx);   SYMADDR(p_cur_addr, g_cur_addr);
    SYMADDR(p_src_at, g_src_at);   SYMADDR(p_dst_at, g_dst_at);
    SYMADDR(p_src_ta, g_src_ta);   SYMADDR(p_dst_ta, g_dst_ta);
    SYMADDR(p_bsum_tx, g_bsum_tx); SYMADDR(p_bsum_addr, g_bsum_addr);
    SYMADDR(p_ws_at, g_ws_at);     SYMADDR(p_wd_at, g_wd_at);
    SYMADDR(p_ws_ta, g_ws_ta);     SYMADDR(p_wd_ta, g_wd_ta);
    SYMADDR(p_ws_ta1, g_ws_ta1);   SYMADDR(p_wd_ta1, g_wd_ta1);

    const int TB = 256;
    const int nb_tx = (N_TX + 1023) / 1024;
    const int nb_addr = (N_ADDR + 1023) / 1024;
    int cblk_tx = (N_TX * 32 + TB - 1) / TB;
    int cblk_addr = (N_ADDR * 32 + TB - 1) / TB;
    int eblk = (NE + TB - 1) / TB;

    // ---- CSR build ----
    hg_zero2<<<(N_ADDR + TB - 1) / TB, TB>>>(p_cnt_tx, N_TX, p_cnt_addr, N_ADDR);
    hg_count<<<(NE + TB - 1) / TB, TB>>>(tx_idx_at, p_cnt_tx, addr_idx_ta, p_cnt_addr);
    hg_scan1<<<nb_tx, 1024>>>(p_cnt_tx, p_rp_at, p_bsum_tx, N_TX);
    hg_scan1<<<nb_addr, 1024>>>(p_cnt_addr, p_rp_ta, p_bsum_addr, N_ADDR);
    hg_scan1<<<1, 1024>>>(p_bsum_tx, p_bsum_tx - 1, nullptr, nb_tx);
    hg_scan1<<<1, 1024>>>(p_bsum_addr, p_bsum_addr - 1, nullptr, nb_addr);
    hg_scan3<<<(N_TX + TB - 1) / TB, TB>>>(p_rp_at, p_bsum_tx, N_TX);
    hg_scan3<<<(N_ADDR + TB - 1) / TB, TB>>>(p_rp_ta, p_bsum_addr, N_ADDR);
    cudaMemcpyAsync(p_cur_tx, p_rp_at, N_TX * sizeof(int), cudaMemcpyDeviceToDevice);
    cudaMemcpyAsync(p_cur_addr, p_rp_ta, N_ADDR * sizeof(int), cudaMemcpyDeviceToDevice);
    hg_fill<<<(NE + TB - 1) / TB, TB>>>(addr_idx_at, tx_idx_at, p_cur_tx, p_src_at, p_dst_at,
                                        tx_idx_ta, addr_idx_ta, p_cur_addr, p_src_ta, p_dst_ta);

    // ---- input projections ----
    launch_gemm(x_tx, w_in_tx, b_in_tx, p_htx64, N_TX, HDIM, F_TX);
    launch_gemm(x_addr, w_in_addr, b_in_addr, p_haddr64, N_ADDR, HDIM, F_ADDR);

    // ---- fold all 6 attention weight vectors in one launch ----
    {
        AttW6 p;
        p.W[0] = w_at0; p.a[0] = as_at0; p.o[0] = p_ws_at;  p.K[0] = HDIM;
        p.W[1] = w_at0; p.a[1] = ad_at0; p.o[1] = p_wd_at;  p.K[1] = HDIM;
        p.W[2] = w_ta0; p.a[2] = as_ta0; p.o[2] = p_ws_ta;  p.K[2] = HDIM;
        p.W[3] = w_ta0; p.a[3] = ad_ta0; p.o[3] = p_wd_ta;  p.K[3] = HDIM;
        p.W[4] = w_ta1; p.a[4] = as_ta1; p.o[4] = p_ws_ta1; p.K[4] = HD;
        p.W[5] = w_ta1; p.a[5] = ad_ta1; p.o[5] = p_wd_ta1; p.K[5] = HD;
        hg_att_w6<<<dim3(HD, 6), 128>>>(p);
    }

    // ---- layer 0: coefficients from h64, logits, aggregate-then-project ----
    hg_coef2<<<cblk_addr, TB>>>(p_haddr64, p_ws_at, p_wd_ta, p_als_at, p_ald_ta,
                                N_ADDR, HDIM);
    hg_coef2<<<cblk_tx,   TB>>>(p_htx64,   p_wd_at, p_ws_ta, p_ald_at, p_als_ta,
                                N_TX, HDIM);

    hg_edge_al2<<<2 * eblk, TB>>>(p_src_at, p_dst_at, p_als_at, p_ald_at, p_al_at,
                                  p_src_ta, p_dst_ta, p_als_ta, p_ald_ta, p_al_ta);

    // aggregate 64-dim sources into head-blocked aggx (2-pass softmax)
    hg_agg64<<<cblk_tx,   TB>>>(p_haddr64, p_src_at, p_al_at, p_rp_at, p_buf_tx, N_TX);
    hg_agg64<<<cblk_addr, TB>>>(p_htx64,   p_src_ta, p_al_ta, p_rp_ta, p_buf_addr, N_ADDR);

    // block-diagonal GEMM + bias + LN + ELU + next-layer coef
    hg_gemm_ln<<<(N_TX + 63) / 64, 256>>>(p_buf_tx, w_at0, b_at0, ln_g_tx, ln_b_tx,
                                          p_htx, (const float4*)p_ws_ta1, p_als_ta, N_TX);
    hg_gemm_ln<<<(N_ADDR + 63) / 64, 256>>>(p_buf_addr, w_ta0, b_ta0, ln_g_addr, ln_b_addr,
                                            p_haddr, (const float4*)p_wd_ta1, p_ald_ta,
                                            N_ADDR);

    // ---- layer 1 (ta relation only; tx branch is dead): project-then-aggregate ----
    launch_gemm(p_htx, w_ta1, nullptr, p_buf_tx, N_TX, HD, HD);

    hg_edge_al<<<eblk, TB>>>(p_src_ta, p_dst_ta, p_als_ta, p_ald_ta, p_al_ta);

    hg_gat_agg_ln<<<cblk_addr, TB>>>(p_buf_tx, p_src_ta, p_al_ta, p_rp_ta,
                                     b_ta1, ln_g_addr, ln_b_addr, p_haddr, 1, N_ADDR);

    // ---- scatter-mean pooling addr -> tx over 'at' edges ----
    hg_pool_mean<<<cblk_tx, TB>>>(p_haddr, p_src_at, p_rp_at, p_pool_tx, N_TX);

    // ---- output projection ----
    launch_gemm(p_pool_tx, w_out, b_out, out, N_TX, HD, HD);
}

// round 15
// speedup vs baseline: 1.3841x; 1.0332x over previous
#include <cuda_runtime.h>
#include <math.h>
#include <stdint.h>

// ---------------- problem constants ----------------
#define N_TX   100000
#define N_ADDR 200000
#define NE     400000
#define F_TX   165
#define F_ADDR 64
#define HDIM   64
#define HD     256
#define LN_EPS 1e-5f
#define NEG_SLOPE 0.2f

// ---------------- scratch (device globals; no cudaMalloc allowed) ----------------
__device__ float g_htx64[(size_t)N_TX * HDIM];
__device__ float g_haddr64[(size_t)N_ADDR * HDIM];
__device__ float g_buf_addr[(size_t)N_ADDR * HD];  // aggx_addr (L0)
__device__ float g_buf_tx[(size_t)N_TX * HD];      // aggx_tx (L0), then hs_ta (L1)
__device__ float g_pool_tx[(size_t)N_TX * HD];
__device__ float g_htx[(size_t)N_TX * HD];
__device__ float g_haddr[(size_t)N_ADDR * HD];
__device__ float4 g_als_at[N_ADDR];
__device__ float4 g_ald_at[N_TX];
__device__ float4 g_als_ta[N_TX];
__device__ float4 g_ald_ta[N_ADDR];
__device__ float4 g_al_at[NE];
__device__ float4 g_al_ta[NE];
__device__ int g_cnt_tx[N_TX];
__device__ int g_cnt_addr[N_ADDR];
__device__ int g_rp_at[N_TX + 1];
__device__ int g_rp_ta[N_ADDR + 1];
__device__ int g_cur_tx[N_TX];
__device__ int g_cur_addr[N_ADDR];
__device__ int g_src_at[NE];
__device__ int g_dst_at[NE];
__device__ int g_src_ta[NE];
__device__ int g_dst_ta[NE];
__device__ int g_bsum_tx[256];
__device__ int g_bsum_addr[256];
__device__ float g_ws_at[HD * 4];
__device__ float g_wd_at[HD * 4];
__device__ float g_ws_ta[HD * 4];
__device__ float g_wd_ta[HD * 4];
__device__ float g_ws_ta1[HD * 4];
__device__ float g_wd_ta1[HD * 4];

// ---------------- packed f32x2 helpers (sm_103a FFMA2 pipe) ----------------
__device__ __forceinline__ unsigned long long hg_pack2(float x, float y) {
    unsigned long long r;
    asm("mov.b64 %0, {%1, %2};" : "=l"(r) : "f"(x), "f"(y));
    return r;
}
__device__ __forceinline__ void hg_unpack2(unsigned long long v, float& x, float& y) {
    asm("mov.b64 {%0, %1}, %2;" : "=f"(x), "=f"(y) : "l"(v));
}
__device__ __forceinline__ void hg_ffma2(unsigned long long& d,
                                         unsigned long long a, unsigned long long b) {
    asm("fma.rn.f32x2 %0, %1, %2, %0;" : "+l"(d) : "l"(a), "l"(b));
}

// ---------------- SGEMM (N>=128 path): C[M,N] = A[M,K] @ B[K,N] (+bias) --------------
#define BM 128
#define BN 128
#define BK 16
#define TM 8
#define TN 8

__global__ __launch_bounds__(256)
void hg_sgemm(const float* __restrict__ A, const float* __restrict__ B,
              const float* __restrict__ bias, float* __restrict__ C,
              int M, int N, int K) {
    __shared__ float As[2][BK][BM];
    __shared__ float Bs[2][BK][BN];
    int tid = threadIdx.x;
    int row0 = blockIdx.y * BM, col0 = blockIdx.x * BN;
    int tx = tid & 15, ty = tid >> 4;
    int arow = tid >> 1, acol = (tid & 1) * 8;
    int brow = tid >> 4, bcol = (tid & 15) * 8;
    bool k4 = ((K & 3) == 0);
    int nk = (K + BK - 1) / BK;

    float ra[8];
    float4 rb0, rb1;

    unsigned long long acc2[TM][TN / 2];
    #pragma unroll
    for (int i = 0; i < TM; i++)
        #pragma unroll
        for (int j = 0; j < TN / 2; j++) acc2[i][j] = 0ull;

    auto loadA = [&](int k0) {
        int gr = row0 + arow;
        if (k4) {
            #pragma unroll
            for (int i = 0; i < 8; i += 4) {
                int gk = k0 + acol + i;
                float4 v = make_float4(0.f, 0.f, 0.f, 0.f);
                if (gr < M && gk < K) v = *(const float4*)(A + (long)gr * K + gk);
                ra[i] = v.x; ra[i + 1] = v.y; ra[i + 2] = v.z; ra[i + 3] = v.w;
            }
        } else {
            #pragma unroll
            for (int i = 0; i < 8; i++) {
                int gk = k0 + acol + i;
                ra[i] = (gr < M && gk < K) ? A[(long)gr * K + gk] : 0.f;
            }
        }
    };
    auto loadB = [&](int k0) {
        int gk = k0 + brow, gn = col0 + bcol;
        rb0 = make_float4(0.f, 0.f, 0.f, 0.f);
        rb1 = rb0;
        if (gk < K && gn < N) {
            rb0 = *(const float4*)(B + (long)gk * N + gn);
            rb1 = *(const float4*)(B + (long)gk * N + gn + 4);
        }
    };
    auto storeA = [&](int s) {
        #pragma unroll
        for (int i = 0; i < 8; i++) As[s][acol + i][arow] = ra[i];
    };
    auto storeB = [&](int s) {
        *(float4*)&Bs[s][brow][bcol] = rb0;
        *(float4*)&Bs[s][brow][bcol + 4] = rb1;
    };

    loadA(0); loadB(0);
    storeA(0); storeB(0);
    __syncthreads();

    int s = 0;
    for (int t = 0; t < nk; t++) {
        if (t + 1 < nk) { loadA((t + 1) * BK); loadB((t + 1) * BK); }
        #pragma unroll
        for (int k = 0; k < BK; k++) {
            float4 a0 = *(float4*)&As[s][k][ty * TM];
            float4 a1 = *(float4*)&As[s][k][ty * TM + 4];
            ulonglong2 bb0 = *(ulonglong2*)&Bs[s][k][tx * TN];
            ulonglong2 bb1 = *(ulonglong2*)&Bs[s][k][tx * TN + 4];
            unsigned long long b2[4] = {bb0.x, bb0.y, bb1.x, bb1.y};
            float af[8] = {a0.x, a0.y, a0.z, a0.w, a1.x, a1.y, a1.z, a1.w};
            #pragma unroll
            for (int i = 0; i < TM; i++) {
                unsigned long long a2 = hg_pack2(af[i], af[i]);
                #pragma unroll
                for (int j = 0; j < TN / 2; j++) hg_ffma2(acc2[i][j], a2, b2[j]);
            }
        }
        if (t + 1 < nk) {
            storeA(s ^ 1); storeB(s ^ 1);
            __syncthreads();
            s ^= 1;
        }
    }

    int gc = col0 + tx * TN;
    if (gc >= N) return;
    float bsv[8];
    #pragma unroll
    for (int j = 0; j < 8; j++) bsv[j] = bias ? bias[gc + j] : 0.f;
    #pragma unroll
    for (int i = 0; i < TM; i++) {
        int gr = row0 + ty * TM + i;
        if (gr >= M) continue;
        float acc[8];
        #pragma unroll
        for (int j = 0; j < 4; j++) hg_unpack2(acc2[i][j], acc[2 * j], acc[2 * j + 1]);
        float* cp = C + (long)gr * N + gc;
        *(float4*)cp = make_float4(acc[0] + bsv[0], acc[1] + bsv[1],
                                   acc[2] + bsv[2], acc[3] + bsv[3]);
        *(float4*)(cp + 4) = make_float4(acc[4] + bsv[4], acc[5] + bsv[5],
                                         acc[6] + bsv[6], acc[7] + bsv[7]);
    }
}

// ---------------- SGEMM N=64 path: 128x64 tile, 128 threads (input projections) ------
__global__ __launch_bounds__(128)
void hg_sgemm_n64(const float* __restrict__ A, const float* __restrict__ B,
                  const float* __restrict__ bias, float* __restrict__ C,
                  int M, int K) {
    const int N = 64;
    __shared__ float As[2][BK][BM];
    __shared__ float Bs[2][BK][64];
    int tid = threadIdx.x;
    int row0 = blockIdx.x * BM;
    int tx = tid & 7, ty = tid >> 3;       // 16 x 8 thread grid, 8x8 per thread
    int arow = tid;                         // each thread: one row, 16 k's
    int brow = tid >> 3, bcol = (tid & 7) * 8;
    bool k4 = ((K & 3) == 0);
    int nk = (K + BK - 1) / BK;

    float ra[16];
    float4 rb0, rb1;

    unsigned long long acc2[TM][4];
    #pragma unroll
    for (int i = 0; i < TM; i++)
        #pragma unroll
        for (int j = 0; j < 4; j++) acc2[i][j] = 0ull;

    auto loadA = [&](int k0) {
        int gr = row0 + arow;
        if (k4) {
            #pragma unroll
            for (int i = 0; i < 16; i += 4) {
                int gk = k0 + i;
                float4 v = make_float4(0.f, 0.f, 0.f, 0.f);
                if (gr < M && gk + 3 < K) v = *(const float4*)(A + (long)gr * K + gk);
                else {
                    #pragma unroll
                    for (int q = 0; q < 4; q++)
                        ((float*)&v)[q] = (gr < M && gk + q < K) ? A[(long)gr * K + gk + q] : 0.f;
                }
                ra[i] = v.x; ra[i + 1] = v.y; ra[i + 2] = v.z; ra[i + 3] = v.w;
            }
        } else {
            #pragma unroll
            for (int i = 0; i < 16; i++) {
                int gk = k0 + i;
                ra[i] = (gr < M && gk < K) ? A[(long)gr * K + gk] : 0.f;
            }
        }
    };
    auto loadB = [&](int k0) {
        int gk = k0 + brow;
        rb0 = make_float4(0.f, 0.f, 0.f, 0.f);
        rb1 = rb0;
        if (gk < K) {
            rb0 = *(const float4*)(B + (long)gk * N + bcol);
            rb1 = *(const float4*)(B + (long)gk * N + bcol + 4);
        }
    };
    auto storeA = [&](int s) {
        #pragma unroll
        for (int i = 0; i < 16; i++) As[s][i][arow] = ra[i];
    };
    auto storeB = [&](int s) {
        *(float4*)&Bs[s][brow][bcol] = rb0;
        *(float4*)&Bs[s][brow][bcol + 4] = rb1;
    };

    loadA(0); loadB(0);
    storeA(0); storeB(0);
    __syncthreads();

    int s = 0;
    for (int t = 0; t < nk; t++) {
        if (t + 1 < nk) { loadA((t + 1) * BK); loadB((t + 1) * BK); }
        #pragma unroll
        for (int k = 0; k < BK; k++) {
            float4 a0 = *(float4*)&As[s][k][ty * TM];
            float4 a1 = *(float4*)&As[s][k][ty * TM + 4];
            ulonglong2 bb0 = *(ulonglong2*)&Bs[s][k][tx * 8];
            ulonglong2 bb1 = *(ulonglong2*)&Bs[s][k][tx * 8 + 4];
            unsigned long long b2[4] = {bb0.x, bb0.y, bb1.x, bb1.y};
            float af[8] = {a0.x, a0.y, a0.z, a0.w, a1.x, a1.y, a1.z, a1.w};
            #pragma unroll
            for (int i = 0; i < TM; i++) {
                unsigned long long a2 = hg_pack2(af[i], af[i]);
                #pragma unroll
                for (int j = 0; j < 4; j++) hg_ffma2(acc2[i][j], a2, b2[j]);
            }
        }
        if (t + 1 < nk) {
            storeA(s ^ 1); storeB(s ^ 1);
            __syncthreads();
            s ^= 1;
        }
    }

    int gc = tx * 8;
    float bsv[8];
    #pragma unroll
    for (int j = 0; j < 8; j++) bsv[j] = bias ? bias[gc + j] : 0.f;
    #pragma unroll
    for (int i = 0; i < TM; i++) {
        int gr = row0 + ty * TM + i;
        if (gr >= M) continue;
        float acc[8];
        #pragma unroll
        for (int j = 0; j < 4; j++) hg_unpack2(acc2[i][j], acc[2 * j], acc[2 * j + 1]);
        float* cp = C + (long)gr * N + gc;
        *(float4*)cp = make_float4(acc[0] + bsv[0], acc[1] + bsv[1],
                                   acc[2] + bsv[2], acc[3] + bsv[3]);
        *(float4*)(cp + 4) = make_float4(acc[4] + bsv[4], acc[5] + bsv[5],
                                         acc[6] + bsv[6], acc[7] + bsv[7]);
    }
}

// ---------------- block-diagonal GEMM (K=64 per head) + bias + LN + ELU + coef -------
#define GL_BK 16

__global__ __launch_bounds__(256)
void hg_gemm_ln(const float* __restrict__ A, const float* __restrict__ W,
                const float* __restrict__ bias, const float* __restrict__ gam,
                const float* __restrict__ bet, float* __restrict__ h,
                const float4* __restrict__ wvn, float4* __restrict__ coef, int M) {
    __shared__ float As[GL_BK][4][68];
    __shared__ float Bs[GL_BK][256];
    int tid = threadIdx.x, tx = tid & 31, ty = tid >> 5;
    int row0 = blockIdx.x * 64;
    int arow = tid & 63, apart = tid >> 6;
    int head = tx >> 3;

    unsigned long long acc2[8][4];
    #pragma unroll
    for (int i = 0; i < 8; i++)
        #pragma unroll
        for (int j = 0; j < 4; j++) acc2[i][j] = 0ull;

    for (int k0 = 0; k0 < 64; k0 += GL_BK) {
        __syncthreads();
        {
            int gr = row0 + arow;
            float4 t0 = make_float4(0.f, 0.f, 0.f, 0.f), t1 = t0, t2 = t0, t3 = t0;
            if (gr < M) {
                const float4* ap = (const float4*)(A + (long)gr * HD + apart * 64 + k0);
                t0 = ap[0]; t1 = ap[1]; t2 = ap[2]; t3 = ap[3];
            }
            float vv[16] = {t0.x, t0.y, t0.z, t0.w, t1.x, t1.y, t1.z, t1.w,
                            t2.x, t2.y, t2.z, t2.w, t3.x, t3.y, t3.z, t3.w};
            #pragma unroll
            for (int k = 0; k < GL_BK; k++) As[k][apart][arow] = vv[k];
        }
        {
            int kk = tid >> 4, c = (tid & 15) * 4;
            const float* wp = W + (long)(k0 + kk) * HD;
            #pragma unroll
            for (int q = 0; q < 4; q++)
                *(float4*)&Bs[kk][c + q * 64] = *(const float4*)(wp + c + q * 64);
        }
        __syncthreads();

        #pragma unroll
        for (int k = 0; k < GL_BK; k++) {
            float4 a0 = *(float4*)&As[k][head][ty * 8];
            float4 a1 = *(float4*)&As[k][head][ty * 8 + 4];
            ulonglong2 bb0 = *(ulonglong2*)&Bs[k][tx * 8];
            ulonglong2 bb1 = *(ulonglong2*)&Bs[k][tx * 8 + 4];
            unsigned long long b2[4] = {bb0.x, bb0.y, bb1.x, bb1.y};
            float af[8] = {a0.x, a0.y, a0.z, a0.w, a1.x, a1.y, a1.z, a1.w};
            #pragma unroll
            for (int i = 0; i < 8; i++) {
                unsigned long long a2 = hg_pack2(af[i], af[i]);
                #pragma unroll
                for (int j = 0; j < 4; j++) hg_ffma2(acc2[i][j], a2, b2[j]);
            }
        }
    }

    int cbase = tx * 8;
    float bsv[8], gmv[8], btv[8];
    {
        float4 t0 = *(const float4*)(bias + cbase), t1 = *(const float4*)(bias + cbase + 4);
        bsv[0]=t0.x; bsv[1]=t0.y; bsv[2]=t0.z; bsv[3]=t0.w;
        bsv[4]=t1.x; bsv[5]=t1.y; bsv[6]=t1.z; bsv[7]=t1.w;
        t0 = *(const float4*)(gam + cbase); t1 = *(const float4*)(gam + cbase + 4);
        gmv[0]=t0.x; gmv[1]=t0.y; gmv[2]=t0.z; gmv[3]=t0.w;
        gmv[4]=t1.x; gmv[5]=t1.y; gmv[6]=t1.z; gmv[7]=t1.w;
        t0 = *(const float4*)(bet + cbase); t1 = *(const float4*)(bet + cbase + 4);
        btv[0]=t0.x; btv[1]=t0.y; btv[2]=t0.z; btv[3]=t0.w;
        btv[4]=t1.x; btv[5]=t1.y; btv[6]=t1.z; btv[7]=t1.w;
    }
    float4 wv4[8];
    if (wvn) {
        #pragma unroll
        for (int j = 0; j < 8; j++) wv4[j] = wvn[cbase + j];
    }

    #pragma unroll
    for (int i = 0; i < 8; i++) {
        int r = row0 + ty * 8 + i;
        float v[8];
        #pragma unroll
        for (int j = 0; j < 4; j++) hg_unpack2(acc2[i][j], v[2 * j], v[2 * j + 1]);
        #pragma unroll
        for (int j = 0; j < 8; j++) v[j] += bsv[j];
        float sum = 0.f, sq = 0.f;
        #pragma unroll
        for (int j = 0; j < 8; j++) { sum += v[j]; sq += v[j] * v[j]; }
        #pragma unroll
        for (int o = 16; o > 0; o >>= 1) {
            sum += __shfl_xor_sync(0xffffffffu, sum, o);
            sq  += __shfl_xor_sync(0xffffffffu, sq, o);
        }
        float mu = sum * (1.f / HD);
        float var = sq * (1.f / HD) - mu * mu;
        float rstd = rsqrtf(var + LN_EPS);
        float y[8];
        #pragma unroll
        for (int j = 0; j < 8; j++) {
            float t = (v[j] - mu) * rstd * gmv[j] + btv[j];
            y[j] = t > 0.f ? t : expm1f(t);
        }
        if (r < M) {
            float* hp = h + (long)r * HD + cbase;
            *(float4*)hp = make_float4(y[0], y[1], y[2], y[3]);
            *(float4*)(hp + 4) = make_float4(y[4], y[5], y[6], y[7]);
        }
        if (wvn) {
            float p0 = 0.f, p1 = 0.f, p2 = 0.f, p3 = 0.f;
            #pragma unroll
            for (int j = 0; j < 8; j++) {
                p0 += y[j] * wv4[j].x; p1 += y[j] * wv4[j].y;
                p2 += y[j] * wv4[j].z; p3 += y[j] * wv4[j].w;
            }
            #pragma unroll
            for (int o = 16; o > 0; o >>= 1) {
                p0 += __shfl_xor_sync(0xffffffffu, p0, o);
                p1 += __shfl_xor_sync(0xffffffffu, p1, o);
                p2 += __shfl_xor_sync(0xffffffffu, p2, o);
                p3 += __shfl_xor_sync(0xffffffffu, p3, o);
            }
            if (tx == 0 && r < M) coef[r] = make_float4(p0, p1, p2, p3);
        }
    }
}

// ---------------- CSR build ----------------
__global__ void hg_zero2(int* a, int na, int* b, int nb) {
    int i = blockIdx.x * blockDim.x + threadIdx.x;
    if (i < na) a[i] = 0;
    if (i < nb) b[i] = 0;
}

__global__ void hg_count(const int* __restrict__ dst_at, int* cnt_at,
                         const int* __restrict__ dst_ta, int* cnt_ta) {
    int i = blockIdx.x * blockDim.x + threadIdx.x;
    if (i < NE) {
        atomicAdd(&cnt_at[dst_at[i]], 1);
        atomicAdd(&cnt_ta[dst_ta[i]], 1);
    }
}

__device__ __forceinline__ int hg_warp_incl_scan(int v, int lane) {
    #pragma unroll
    for (int o = 1; o < 32; o <<= 1) {
        int t = __shfl_up_sync(0xffffffffu, v, o);
        if (lane >= o) v += t;
    }
    return v;
}

__global__ void hg_scan1(const int* __restrict__ cnt, int* __restrict__ rp,
                         int* __restrict__ bsum, int n) {
    __shared__ int ws[32];
    int lane = threadIdx.x & 31, wid = threadIdx.x >> 5;
    int i = blockIdx.x * 1024 + threadIdx.x;
    int v = (i < n) ? cnt[i] : 0;
    int s = hg_warp_incl_scan(v, lane);
    if (lane == 31) ws[wid] = s;
    __syncthreads();
    if (wid == 0) {
        int w = ws[lane];
        w = hg_warp_incl_scan(w, lane);
        ws[lane] = w;
    }
    __syncthreads();
    s += (wid ? ws[wid - 1] : 0);
    if (i < n) rp[i + 1] = s;
    if (bsum && threadIdx.x == 1023) bsum[blockIdx.x] = s;
}

__global__ void hg_scan3(int* __restrict__ rp, const int* __restrict__ bsum, int n) {
    int i = blockIdx.x * blockDim.x + threadIdx.x;
    if (i == 0) rp[0] = 0;
    if (i < n) {
        int b = i >> 10;
        if (b > 0) rp[i + 1] += bsum[b - 1];
    }
}

__global__ void hg_fill(const int* __restrict__ s_at, const int* __restrict__ d_at,
                        int* cur_at, int* src_at, int* dst_at,
                        const int* __restrict__ s_ta, const int* __restrict__ d_ta,
                        int* cur_ta, int* src_ta, int* dst_ta) {
    int i = blockIdx.x * blockDim.x + threadIdx.x;
    if (i < NE) {
        int d0 = d_at[i];
        int p = atomicAdd(&cur_at[d0], 1);
        src_at[p] = s_at[i];
        dst_at[p] = d0;
        int d1 = d_ta[i];
        int q = atomicAdd(&cur_ta[d1], 1);
        src_ta[q] = s_ta[i];
        dst_ta[q] = d1;
    }
}

// ---------------- folded attention weights, all 6 in one launch ----------------
struct AttW6 {
    const float* W[6];
    const float* a[6];
    float* o[6];
    int K[6];
};

__global__ void hg_att_w6(AttW6 p) {
    int j = blockIdx.y;
    int k = blockIdx.x;
    if (k >= p.K[j]) return;
    int head = threadIdx.x >> 5, lane = threadIdx.x & 31;
    const float* wr = p.W[j] + (long)k * HD + head * 64;
    const float* ar = p.a[j] + head * 64;
    float s = wr[lane] * ar[lane] + wr[lane + 32] * ar[lane + 32];
    #pragma unroll
    for (int o = 16; o > 0; o >>= 1) s += __shfl_xor_sync(0xffffffffu, s, o);
    if (lane == 0) p.o[j][k * 4 + head] = s;
}

// ---------------- fused node coefficients (layer-0, from h64) ----------------
__global__ void hg_coef2(const float* __restrict__ x,
                         const float* __restrict__ Wv1, const float* __restrict__ Wv2,
                         float4* __restrict__ out1, float4* __restrict__ out2,
                         int n, int K) {
    int warp = (blockIdx.x * blockDim.x + threadIdx.x) >> 5;
    int lane = threadIdx.x & 31;
    if (warp >= n) return;
    const float* xp = x + (long)warp * K;
    const float4* wv1 = (const float4*)Wv1;
    const float4* wv2 = (const float4*)Wv2;
    float s0 = 0.f, s1 = 0.f, s2 = 0.f, s3 = 0.f;
    float t0 = 0.f, t1 = 0.f, t2 = 0.f, t3 = 0.f;
    for (int k = lane; k < K; k += 32) {
        float xv = xp[k];
        float4 w1 = wv1[k];
        float4 w2 = wv2[k];
        s0 += xv * w1.x; s1 += xv * w1.y; s2 += xv * w1.z; s3 += xv * w1.w;
        t0 += xv * w2.x; t1 += xv * w2.y; t2 += xv * w2.z; t3 += xv * w2.w;
    }
    #pragma unroll
    for (int o = 16; o > 0; o >>= 1) {
        s0 += __shfl_xor_sync(0xffffffffu, s0, o);
        s1 += __shfl_xor_sync(0xffffffffu, s1, o);
        s2 += __shfl_xor_sync(0xffffffffu, s2, o);
        s3 += __shfl_xor_sync(0xffffffffu, s3, o);
        t0 += __shfl_xor_sync(0xffffffffu, t0, o);
        t1 += __shfl_xor_sync(0xffffffffu, t1, o);
        t2 += __shfl_xor_sync(0xffffffffu, t2, o);
        t3 += __shfl_xor_sync(0xffffffffu, t3, o);
    }
    if (lane == 0) {
        out1[warp] = make_float4(s0, s1, s2, s3);
        out2[warp] = make_float4(t0, t1, t2, t3);
    }
}

// ---------------- per-edge logits in CSR order ----------------
__device__ __forceinline__ float hg_leaky(float v) { return v >= 0.f ? v : NEG_SLOPE * v; }

__global__ void hg_edge_al(const int* __restrict__ src, const int* __restrict__ dst,
                           const float4* __restrict__ als, const float4* __restrict__ ald,
                           float4* __restrict__ al) {
    int i = blockIdx.x * blockDim.x + threadIdx.x;
    if (i >= NE) return;
    float4 s = als[src[i]];
    float4 d = ald[dst[i]];
    float4 r;
    r.x = hg_leaky(s.x + d.x);
    r.y = hg_leaky(s.y + d.y);
    r.z = hg_leaky(s.z + d.z);
    r.w = hg_leaky(s.w + d.w);
    al[i] = r;
}

__global__ void hg_edge_al2(const int* __restrict__ src0, const int* __restrict__ dst0,
                            const float4* __restrict__ als0, const float4* __restrict__ ald0,
                            float4* __restrict__ al0,
                            const int* __restrict__ src1, const int* __restrict__ dst1,
                            const float4* __restrict__ als1, const float4* __restrict__ ald1,
                            float4* __restrict__ al1) {
    int i = blockIdx.x * blockDim.x + threadIdx.x;
    if (i < NE) {
        float4 s = als0[src0[i]];
        float4 d = ald0[dst0[i]];
        al0[i] = make_float4(hg_leaky(s.x + d.x), hg_leaky(s.y + d.y),
                             hg_leaky(s.z + d.z), hg_leaky(s.w + d.w));
    } else if (i < 2 * NE) {
        int j = i - NE;
        float4 s = als1[src1[j]];
        float4 d = ald1[dst1[j]];
        al1[j] = make_float4(hg_leaky(s.x + d.x), hg_leaky(s.y + d.y),
                             hg_leaky(s.z + d.z), hg_leaky(s.w + d.w));
    }
}

// ---------------- layer-0: 2-pass softmax agg of 64-dim x into head blocks ------------
__global__ void hg_agg64(const float* __restrict__ x, const int* __restrict__ srcs,
                         const float4* __restrict__ al, const int* __restrict__ rp,
                         float* __restrict__ aggx, int ndst) {
    int warp = (blockIdx.x * blockDim.x + threadIdx.x) >> 5;
    int lane = threadIdx.x & 31;
    if (warp >= ndst) return;
    int beg = rp[warp], end = rp[warp + 1];
    int c0 = lane * 8;
    int hl = lane >> 3;
    int xo = c0 & 63;

    float acc[8] = {0.f, 0.f, 0.f, 0.f, 0.f, 0.f, 0.f, 0.f};
    if (beg < end) {
        float m0 = -3.4e38f, m1 = -3.4e38f, m2 = -3.4e38f, m3 = -3.4e38f;
        for (int t = beg; t < end; t++) {
            float4 a = al[t];
            m0 = fmaxf(m0, a.x); m1 = fmaxf(m1, a.y);
            m2 = fmaxf(m2, a.z); m3 = fmaxf(m3, a.w);
        }
        float mh = (hl & 2) ? ((hl & 1) ? m3 : m2) : ((hl & 1) ? m1 : m0);
        float den = 0.f;
        for (int t = beg; t < end; t++) {
            int sidx = srcs[t];
            float4 a = al[t];
            float av = (hl & 2) ? ((hl & 1) ? a.w : a.z) : ((hl & 1) ? a.y : a.x);
            float e = __expf(av - mh);
            den += e;
            const float4* hp = (const float4*)(x + (long)sidx * HDIM + xo);
            float4 v0 = hp[0], v1 = hp[1];
            acc[0] += e * v0.x; acc[1] += e * v0.y;
            acc[2] += e * v0.z; acc[3] += e * v0.w;
            acc[4] += e * v1.x; acc[5] += e * v1.y;
            acc[6] += e * v1.z; acc[7] += e * v1.w;
        }
        float inv = 1.f / den;
        #pragma unroll
        for (int j = 0; j < 8; j++) acc[j] *= inv;
    }
    float* op = aggx + (long)warp * HD + c0;
    *(float4*)op = make_float4(acc[0], acc[1], acc[2], acc[3]);
    *(float4*)(op + 4) = make_float4(acc[4], acc[5], acc[6], acc[7]);
}

// ---------------- layer-1 FUSED 2-pass agg + bias + LN + residual + ELU --------------
__global__ void hg_gat_agg_ln(const float* __restrict__ hs, const int* __restrict__ srcs,
                              const float4* __restrict__ al, const int* __restrict__ rp,
                              const float* __restrict__ bias, const float* __restrict__ gam,
                              const float* __restrict__ bet, float* __restrict__ h,
                              int residual, int ndst) {
    int warp = (blockIdx.x * blockDim.x + threadIdx.x) >> 5;
    int lane = threadIdx.x & 31;
    if (warp >= ndst) return;
    int beg = rp[warp], end = rp[warp + 1];
    int c0 = lane * 8;
    int hl = lane >> 3;

    float acc[8] = {0.f, 0.f, 0.f, 0.f, 0.f, 0.f, 0.f, 0.f};
    if (beg < end) {
        float m0 = -3.4e38f, m1 = -3.4e38f, m2 = -3.4e38f, m3 = -3.4e38f;
        for (int t = beg; t < end; t++) {
            float4 a = al[t];
            m0 = fmaxf(m0, a.x); m1 = fmaxf(m1, a.y);
            m2 = fmaxf(m2, a.z); m3 = fmaxf(m3, a.w);
        }
        float mh = (hl & 2) ? ((hl & 1) ? m3 : m2) : ((hl & 1) ? m1 : m0);
        float den = 0.f;
        for (int t = beg; t < end; t++) {
            int sidx = srcs[t];
            float4 a = al[t];
            float av = (hl & 2) ? ((hl & 1) ? a.w : a.z) : ((hl & 1) ? a.y : a.x);
            float e = __expf(av - mh);
            den += e;
            const float4* hp = (const float4*)(hs + (long)sidx * HD + c0);
            float4 v0 = hp[0], v1 = hp[1];
            acc[0] += e * v0.x; acc[1] += e * v0.y;
            acc[2] += e * v0.z; acc[3] += e * v0.w;
            acc[4] += e * v1.x; acc[5] += e * v1.y;
            acc[6] += e * v1.z; acc[7] += e * v1.w;
        }
        float inv = 1.f / den;
        #pragma unroll
        for (int j = 0; j < 8; j++) acc[j] *= inv;
    }

    const float4* bp = (const float4*)(bias + c0);
    float4 b0 = bp[0], b1 = bp[1];
    float v[8] = {acc[0] + b0.x, acc[1] + b0.y, acc[2] + b0.z, acc[3] + b0.w,
                  acc[4] + b1.x, acc[5] + b1.y, acc[6] + b1.z, acc[7] + b1.w};
    float sum = 0.f, sq = 0.f;
    #pragma unroll
    for (int j = 0; j < 8; j++) { sum += v[j]; sq += v[j] * v[j]; }
    #pragma unroll
    for (int o = 16; o > 0; o >>= 1) {
        sum += __shfl_xor_sync(0xffffffffu, sum, o);
        sq  += __shfl_xor_sync(0xffffffffu, sq, o);
    }
    float mu = sum * (1.f / HD);
    float var = sq * (1.f / HD) - mu * mu;
    float rstd = rsqrtf(var + LN_EPS);

    const float4* gp = (const float4*)(gam + c0);
    const float4* ep = (const float4*)(bet + c0);
    float4 g0 = gp[0], g1 = gp[1];
    float4 e0 = ep[0], e1 = ep[1];
    float gm[8] = {g0.x, g0.y, g0.z, g0.w, g1.x, g1.y, g1.z, g1.w};
    float bt[8] = {e0.x, e0.y, e0.z, e0.w, e1.x, e1.y, e1.z, e1.w};
    float* hp = h + (long)warp * HD + c0;
    float r[8] = {0.f, 0.f, 0.f, 0.f, 0.f, 0.f, 0.f, 0.f};
    if (residual) {
        float4 r0 = ((const float4*)hp)[0], r1 = ((const float4*)hp)[1];
        r[0] = r0.x; r[1] = r0.y; r[2] = r0.z; r[3] = r0.w;
        r[4] = r1.x; r[5] = r1.y; r[6] = r1.z; r[7] = r1.w;
    }
    float y[8];
    #pragma unroll
    for (int j = 0; j < 8; j++) {
        float t = (v[j] - mu) * rstd * gm[j] + bt[j] + r[j];
        y[j] = t > 0.f ? t : expm1f(t);
    }
    *(float4*)hp = make_float4(y[0], y[1], y[2], y[3]);
    *(float4*)(hp + 4) = make_float4(y[4], y[5], y[6], y[7]);
}

// ---------------- mean pooling addr -> tx (warp per tx node) ----------------
__global__ void hg_pool_mean(const float* __restrict__ haddr, const int* __restrict__ srcs,
                             const int* __restrict__ rp, float* __restrict__ out, int ndst) {
    int warp = (blockIdx.x * blockDim.x + threadIdx.x) >> 5;
    int lane = threadIdx.x & 31;
    if (warp >= ndst) return;
    int beg = rp[warp], end = rp[warp + 1];
    int c0 = lane * 8;
    float acc[8] = {0.f, 0.f, 0.f, 0.f, 0.f, 0.f, 0.f, 0.f};
    for (int t = beg; t < end; t++) {
        int s = srcs[t];
        const float4* hp = (const float4*)(haddr + (long)s * HD + c0);
        float4 v0 = hp[0], v1 = hp[1];
        acc[0] += v0.x; acc[1] += v0.y; acc[2] += v0.z; acc[3] += v0.w;
        acc[4] += v1.x; acc[5] += v1.y; acc[6] += v1.z; acc[7] += v1.w;
    }
    int deg = end - beg;
    float inv = 1.f / (float)(deg > 0 ? deg : 1);
    float* op = out + (long)warp * HD + c0;
    *(float4*)op = make_float4(acc[0] * inv, acc[1] * inv, acc[2] * inv, acc[3] * inv);
    *(float4*)(op + 4) = make_float4(acc[4] * inv, acc[5] * inv, acc[6] * inv, acc[7] * inv);
}

// ---------------- host launcher ----------------
#define SYMADDR(p, s) do { void* _t = nullptr; cudaGetSymbolAddress(&_t, s); p = (decltype(p))_t; } while (0)

static inline void launch_gemm(const float* A, const float* B, const float* bias,
                               float* C, int M, int N, int K) {
    dim3 grid((N + BN - 1) / BN, (M + BM - 1) / BM);
    hg_sgemm<<<grid, 256>>>(A, B, bias, C, M, N, K);
}

extern "C" void kernel_launch(void* const* d_in, const int* in_sizes, int n_in,
                              void* d_out, int out_size) {
    const float* x_tx      = (const float*)d_in[0];
    const float* x_addr    = (const float*)d_in[1];
    const int*   addr_idx_at = (const int*)d_in[2];
    const int*   tx_idx_at   = (const int*)d_in[3];
    const int*   tx_idx_ta   = (const int*)d_in[4];
    const int*   addr_idx_ta = (const int*)d_in[5];
    const float* w_in_tx   = (const float*)d_in[6];
    const float* b_in_tx   = (const float*)d_in[7];
    const float* w_in_addr = (const float*)d_in[8];
    const float* b_in_addr = (const float*)d_in[9];
    const float* w_at0 = (const float*)d_in[10];
    const float* as_at0 = (const float*)d_in[11];
    const float* ad_at0 = (const float*)d_in[12];
    const float* b_at0 = (const float*)d_in[13];
    const float* w_ta0 = (const float*)d_in[14];
    const float* as_ta0 = (const float*)d_in[15];
    const float* ad_ta0 = (const float*)d_in[16];
    const float* b_ta0 = (const float*)d_in[17];
    // layer-1 at-relation weights are dead (h_tx after layer 1 unused by output)
    const float* w_ta1 = (const float*)d_in[22];
    const float* as_ta1 = (const float*)d_in[23];
    const float* ad_ta1 = (const float*)d_in[24];
    const float* b_ta1 = (const float*)d_in[25];
    const float* ln_g_tx = (const float*)d_in[26];
    const float* ln_b_tx = (const float*)d_in[27];
    const float* ln_g_addr = (const float*)d_in[28];
    const float* ln_b_addr = (const float*)d_in[29];
    const float* w_out = (const float*)d_in[30];
    const float* b_out = (const float*)d_in[31];
    float* out = (float*)d_out;

    float *p_htx64, *p_haddr64, *p_buf_addr, *p_buf_tx, *p_pool_tx, *p_htx, *p_haddr;
    float4 *p_als_at, *p_ald_at, *p_als_ta, *p_ald_ta, *p_al_at, *p_al_ta;
    int *p_cnt_tx, *p_cnt_addr, *p_rp_at, *p_rp_ta, *p_cur_tx, *p_cur_addr;
    int *p_src_at, *p_dst_at, *p_src_ta, *p_dst_ta, *p_bsum_tx, *p_bsum_addr;
    float *p_ws_at, *p_wd_at, *p_ws_ta, *p_wd_ta, *p_ws_ta1, *p_wd_ta1;
    SYMADDR(p_htx64, g_htx64);     SYMADDR(p_haddr64, g_haddr64);
    SYMADDR(p_buf_addr, g_buf_addr); SYMADDR(p_buf_tx, g_buf_tx);
    SYMADDR(p_pool_tx, g_pool_tx);
    SYMADDR(p_htx, g_htx);         SYMADDR(p_haddr, g_haddr);
    SYMADDR(p_als_at, g_als_at);   SYMADDR(p_ald_at, g_ald_at);
    SYMADDR(p_als_ta, g_als_ta);   SYMADDR(p_ald_ta, g_ald_ta);
    SYMADDR(p_al_at, g_al_at);     SYMADDR(p_al_ta, g_al_ta);
    SYMADDR(p_cnt_tx, g_cnt_tx);   SYMADDR(p_cnt_addr, g_cnt_addr);
    SYMADDR(p_rp_at, g_rp_at);     SYMADDR(p_rp_ta, g_rp_ta);
    SYMADDR(p_cur_tx, g_cur_tx);   SYMADDR(p_cur_addr, g_cur_addr);
    SYMADDR(p_src_at, g_src_at);   SYMADDR(p_dst_at, g_dst_at);
    SYMADDR(p_src_ta, g_src_ta);   SYMADDR(p_dst_ta, g_dst_ta);
    SYMADDR(p_bsum_tx, g_bsum_tx); SYMADDR(p_bsum_addr, g_bsum_addr);
    SYMADDR(p_ws_at, g_ws_at);     SYMADDR(p_wd_at, g_wd_at);
    SYMADDR(p_ws_ta, g_ws_ta);     SYMADDR(p_wd_ta, g_wd_ta);
    SYMADDR(p_ws_ta1, g_ws_ta1);   SYMADDR(p_wd_ta1, g_wd_ta1);

    const int TB = 256;
    const int nb_tx = (N_TX + 1023) / 1024;
    const int nb_addr = (N_ADDR + 1023) / 1024;
    int cblk_tx = (N_TX * 32 + TB - 1) / TB;
    int cblk_addr = (N_ADDR * 32 + TB - 1) / TB;
    int eblk = (NE + TB - 1) / TB;

    // ---- CSR build ----
    hg_zero2<<<(N_ADDR + TB - 1) / TB, TB>>>(p_cnt_tx, N_TX, p_cnt_addr, N_ADDR);
    hg_count<<<(NE + TB - 1) / TB, TB>>>(tx_idx_at, p_cnt_tx, addr_idx_ta, p_cnt_addr);
    hg_scan1<<<nb_tx, 1024>>>(p_cnt_tx, p_rp_at, p_bsum_tx, N_TX);
    hg_scan1<<<nb_addr, 1024>>>(p_cnt_addr, p_rp_ta, p_bsum_addr, N_ADDR);
    hg_scan1<<<1, 1024>>>(p_bsum_tx, p_bsum_tx - 1, nullptr, nb_tx);
    hg_scan1<<<1, 1024>>>(p_bsum_addr, p_bsum_addr - 1, nullptr, nb_addr);
    hg_scan3<<<(N_TX + TB - 1) / TB, TB>>>(p_rp_at, p_bsum_tx, N_TX);
    hg_scan3<<<(N_ADDR + TB - 1) / TB, TB>>>(p_rp_ta, p_bsum_addr, N_ADDR);
    cudaMemcpyAsync(p_cur_tx, p_rp_at, N_TX * sizeof(int), cudaMemcpyDeviceToDevice);
    cudaMemcpyAsync(p_cur_addr, p_rp_ta, N_ADDR * sizeof(int), cudaMemcpyDeviceToDevice);
    hg_fill<<<(NE + TB - 1) / TB, TB>>>(addr_idx_at, tx_idx_at, p_cur_tx, p_src_at, p_dst_at,
                                        tx_idx_ta, addr_idx_ta, p_cur_addr, p_src_ta, p_dst_ta);

    // ---- input projections (N=64 specialized tile: no padded-column waste) ----
    hg_sgemm_n64<<<(N_TX + BM - 1) / BM, 128>>>(x_tx, w_in_tx, b_in_tx, p_htx64,
                                                N_TX, F_TX);
    hg_sgemm_n64<<<(N_ADDR + BM - 1) / BM, 128>>>(x_addr, w_in_addr, b_in_addr, p_haddr64,
                                                  N_ADDR, F_ADDR);

    // ---- fold all 6 attention weight vectors in one launch ----
    {
        AttW6 p;
        p.W[0] = w_at0; p.a[0] = as_at0; p.o[0] = p_ws_at;  p.K[0] = HDIM;
        p.W[1] = w_at0; p.a[1] = ad_at0; p.o[1] = p_wd_at;  p.K[1] = HDIM;
        p.W[2] = w_ta0; p.a[2] = as_ta0; p.o[2] = p_ws_ta;  p.K[2] = HDIM;
        p.W[3] = w_ta0; p.a[3] = ad_ta0; p.o[3] = p_wd_ta;  p.K[3] = HDIM;
        p.W[4] = w_ta1; p.a[4] = as_ta1; p.o[4] = p_ws_ta1; p.K[4] = HD;
        p.W[5] = w_ta1; p.a[5] = ad_ta1; p.o[5] = p_wd_ta1; p.K[5] = HD;
        hg_att_w6<<<dim3(HD, 6), 128>>>(p);
    }

    // ---- layer 0: coefficients from h64, logits, aggregate-then-project ----
    hg_coef2<<<cblk_addr, TB>>>(p_haddr64, p_ws_at, p_wd_ta, p_als_at, p_ald_ta,
                                N_ADDR, HDIM);
    hg_coef2<<<cblk_tx,   TB>>>(p_htx64,   p_wd_at, p_ws_ta, p_ald_at, p_als_ta,
                                N_TX, HDIM);

    hg_edge_al2<<<2 * eblk, TB>>>(p_src_at, p_dst_at, p_als_at, p_ald_at, p_al_at,
                                  p_src_ta, p_dst_ta, p_als_ta, p_ald_ta, p_al_ta);

    // aggregate 64-dim sources into head-blocked aggx (2-pass softmax)
    hg_agg64<<<cblk_tx,   TB>>>(p_haddr64, p_src_at, p_al_at, p_rp_at, p_buf_tx, N_TX);
    hg_agg64<<<cblk_addr, TB>>>(p_htx64,   p_src_ta, p_al_ta, p_rp_ta, p_buf_addr, N_ADDR);

    // block-diagonal GEMM + bias + LN + ELU + next-layer coef
    hg_gemm_ln<<<(N_TX + 63) / 64, 256>>>(p_buf_tx, w_at0, b_at0, ln_g_tx, ln_b_tx,
                                          p_htx, (const float4*)p_ws_ta1, p_als_ta, N_TX);
    hg_gemm_ln<<<(N_ADDR + 63) / 64, 256>>>(p_buf_addr, w_ta0, b_ta0, ln_g_addr, ln_b_addr,
                                            p_haddr, (const float4*)p_wd_ta1, p_ald_ta,
                                            N_ADDR);

    // ---- layer 1 (ta relation only; tx branch is dead): project-then-aggregate ----
    launch_gemm(p_htx, w_ta1, nullptr, p_buf_tx, N_TX, HD, HD);

    hg_edge_al<<<eblk, TB>>>(p_src_ta, p_dst_ta, p_als_ta, p_ald_ta, p_al_ta);

    hg_gat_agg_ln<<<cblk_addr, TB>>>(p_buf_tx, p_src_ta, p_al_ta, p_rp_ta,
                                     b_ta1, ln_g_addr, ln_b_addr, p_haddr, 1, N_ADDR);

    // ---- scatter-mean pooling addr -> tx over 'at' edges ----
    hg_pool_mean<<<cblk_tx, TB>>>(p_haddr, p_src_at, p_rp_at, p_pool_tx, N_TX);

    // ---- output projection ----
    launch_gemm(p_pool_tx, w_out, b_out, out, N_TX, HD, HD);
}

// round 16
// speedup vs baseline: 1.3976x; 1.0097x over previous
#include <cuda_runtime.h>
#include <math.h>
#include <stdint.h>

// ---------------- problem constants ----------------
#define N_TX   100000
#define N_ADDR 200000
#define NE     400000
#define F_TX   165
#define F_ADDR 64
#define HDIM   64
#define HD     256
#define LN_EPS 1e-5f
#define NEG_SLOPE 0.2f

// ---------------- scratch (device globals; no cudaMalloc allowed) ----------------
__device__ float g_htx64[(size_t)N_TX * HDIM];
__device__ float g_haddr64[(size_t)N_ADDR * HDIM];
__device__ float g_buf_addr[(size_t)N_ADDR * HD];  // aggx_addr (L0)
__device__ float g_buf_tx[(size_t)N_TX * HD];      // aggx_tx (L0), then hs_ta (L1)
__device__ float g_pool_tx[(size_t)N_TX * HD];
__device__ float g_htx[(size_t)N_TX * HD];
__device__ float g_haddr[(size_t)N_ADDR * HD];
__device__ float4 g_als_at[N_ADDR];
__device__ float4 g_ald_at[N_TX];
__device__ float4 g_als_ta[N_TX];
__device__ float4 g_ald_ta[N_ADDR];
__device__ float4 g_al_at[NE];
__device__ float4 g_al_ta[NE];
__device__ int g_cnt_tx[N_TX];
__device__ int g_cnt_addr[N_ADDR];
__device__ int g_rp_at[N_TX + 1];
__device__ int g_rp_ta[N_ADDR + 1];
__device__ int g_cur_tx[N_TX];
__device__ int g_cur_addr[N_ADDR];
__device__ int g_src_at[NE];
__device__ int g_dst_at[NE];
__device__ int g_src_ta[NE];
__device__ int g_dst_ta[NE];
__device__ int g_bsum_tx[256];
__device__ int g_bsum_addr[256];
__device__ float g_ws_at[HD * 4];
__device__ float g_wd_at[HD * 4];
__device__ float g_ws_ta[HD * 4];
__device__ float g_wd_ta[HD * 4];
__device__ float g_ws_ta1[HD * 4];
__device__ float g_wd_ta1[HD * 4];

// ---------------- packed f32x2 helpers (sm_103a FFMA2 pipe) ----------------
__device__ __forceinline__ unsigned long long hg_pack2(float x, float y) {
    unsigned long long r;
    asm("mov.b64 %0, {%1, %2};" : "=l"(r) : "f"(x), "f"(y));
    return r;
}
__device__ __forceinline__ void hg_unpack2(unsigned long long v, float& x, float& y) {
    asm("mov.b64 {%0, %1}, %2;" : "=f"(x), "=f"(y) : "l"(v));
}
__device__ __forceinline__ void hg_ffma2(unsigned long long& d,
                                         unsigned long long a, unsigned long long b) {
    asm("fma.rn.f32x2 %0, %1, %2, %0;" : "+l"(d) : "l"(a), "l"(b));
}

// ---------------- SGEMM (N>=128 path): C[M,N] = A[M,K] @ B[K,N] (+bias) --------------
#define BM 128
#define BN 128
#define BK 16
#define TM 8
#define TN 8

__global__ __launch_bounds__(256)
void hg_sgemm(const float* __restrict__ A, const float* __restrict__ B,
              const float* __restrict__ bias, float* __restrict__ C,
              int M, int N, int K) {
    __shared__ float As[2][BK][BM];
    __shared__ float Bs[2][BK][BN];
    int tid = threadIdx.x;
    int row0 = blockIdx.y * BM, col0 = blockIdx.x * BN;
    int tx = tid & 15, ty = tid >> 4;
    int arow = tid >> 1, acol = (tid & 1) * 8;
    int brow = tid >> 4, bcol = (tid & 15) * 8;
    bool k4 = ((K & 3) == 0);
    int nk = (K + BK - 1) / BK;

    float ra[8];
    float4 rb0, rb1;

    unsigned long long acc2[TM][TN / 2];
    #pragma unroll
    for (int i = 0; i < TM; i++)
        #pragma unroll
        for (int j = 0; j < TN / 2; j++) acc2[i][j] = 0ull;

    auto loadA = [&](int k0) {
        int gr = row0 + arow;
        if (k4) {
            #pragma unroll
            for (int i = 0; i < 8; i += 4) {
                int gk = k0 + acol + i;
                float4 v = make_float4(0.f, 0.f, 0.f, 0.f);
                if (gr < M && gk < K) v = *(const float4*)(A + (long)gr * K + gk);
                ra[i] = v.x; ra[i + 1] = v.y; ra[i + 2] = v.z; ra[i + 3] = v.w;
            }
        } else {
            #pragma unroll
            for (int i = 0; i < 8; i++) {
                int gk = k0 + acol + i;
                ra[i] = (gr < M && gk < K) ? A[(long)gr * K + gk] : 0.f;
            }
        }
    };
    auto loadB = [&](int k0) {
        int gk = k0 + brow, gn = col0 + bcol;
        rb0 = make_float4(0.f, 0.f, 0.f, 0.f);
        rb1 = rb0;
        if (gk < K && gn < N) {
            rb0 = *(const float4*)(B + (long)gk * N + gn);
            rb1 = *(const float4*)(B + (long)gk * N + gn + 4);
        }
    };
    auto storeA = [&](int s) {
        #pragma unroll
        for (int i = 0; i < 8; i++) As[s][acol + i][arow] = ra[i];
    };
    auto storeB = [&](int s) {
        *(float4*)&Bs[s][brow][bcol] = rb0;
        *(float4*)&Bs[s][brow][bcol + 4] = rb1;
    };

    loadA(0); loadB(0);
    storeA(0); storeB(0);
    __syncthreads();

    int s = 0;
    for (int t = 0; t < nk; t++) {
        if (t + 1 < nk) { loadA((t + 1) * BK); loadB((t + 1) * BK); }
        #pragma unroll
        for (int k = 0; k < BK; k++) {
            float4 a0 = *(float4*)&As[s][k][ty * TM];
            float4 a1 = *(float4*)&As[s][k][ty * TM + 4];
            ulonglong2 bb0 = *(ulonglong2*)&Bs[s][k][tx * TN];
            ulonglong2 bb1 = *(ulonglong2*)&Bs[s][k][tx * TN + 4];
            unsigned long long b2[4] = {bb0.x, bb0.y, bb1.x, bb1.y};
            float af[8] = {a0.x, a0.y, a0.z, a0.w, a1.x, a1.y, a1.z, a1.w};
            #pragma unroll
            for (int i = 0; i < TM; i++) {
                unsigned long long a2 = hg_pack2(af[i], af[i]);
                #pragma unroll
                for (int j = 0; j < TN / 2; j++) hg_ffma2(acc2[i][j], a2, b2[j]);
            }
        }
        if (t + 1 < nk) {
            storeA(s ^ 1); storeB(s ^ 1);
            __syncthreads();
            s ^= 1;
        }
    }

    int gc = col0 + tx * TN;
    if (gc >= N) return;
    float bsv[8];
    #pragma unroll
    for (int j = 0; j < 8; j++) bsv[j] = bias ? bias[gc + j] : 0.f;
    #pragma unroll
    for (int i = 0; i < TM; i++) {
        int gr = row0 + ty * TM + i;
        if (gr >= M) continue;
        float acc[8];
        #pragma unroll
        for (int j = 0; j < 4; j++) hg_unpack2(acc2[i][j], acc[2 * j], acc[2 * j + 1]);
        float* cp = C + (long)gr * N + gc;
        *(float4*)cp = make_float4(acc[0] + bsv[0], acc[1] + bsv[1],
                                   acc[2] + bsv[2], acc[3] + bsv[3]);
        *(float4*)(cp + 4) = make_float4(acc[4] + bsv[4], acc[5] + bsv[5],
                                         acc[6] + bsv[6], acc[7] + bsv[7]);
    }
}

// ---------------- SGEMM N=64 path: 128x64 tile, 128 threads (input projections) ------
__global__ __launch_bounds__(128)
void hg_sgemm_n64(const float* __restrict__ A, const float* __restrict__ B,
                  const float* __restrict__ bias, float* __restrict__ C,
                  int M, int K) {
    const int N = 64;
    __shared__ float As[2][BK][BM];
    __shared__ float Bs[2][BK][64];
    int tid = threadIdx.x;
    int row0 = blockIdx.x * BM;
    int tx = tid & 7, ty = tid >> 3;
    int arow = tid;
    int brow = tid >> 3, bcol = (tid & 7) * 8;
    bool k4 = ((K & 3) == 0);
    int nk = (K + BK - 1) / BK;

    float ra[16];
    float4 rb0, rb1;

    unsigned long long acc2[TM][4];
    #pragma unroll
    for (int i = 0; i < TM; i++)
        #pragma unroll
        for (int j = 0; j < 4; j++) acc2[i][j] = 0ull;

    auto loadA = [&](int k0) {
        int gr = row0 + arow;
        if (k4) {
            #pragma unroll
            for (int i = 0; i < 16; i += 4) {
                int gk = k0 + i;
                float4 v = make_float4(0.f, 0.f, 0.f, 0.f);
                if (gr < M && gk + 3 < K) v = *(const float4*)(A + (long)gr * K + gk);
                else {
                    #pragma unroll
                    for (int q = 0; q < 4; q++)
                        ((float*)&v)[q] = (gr < M && gk + q < K) ? A[(long)gr * K + gk + q] : 0.f;
                }
                ra[i] = v.x; ra[i + 1] = v.y; ra[i + 2] = v.z; ra[i + 3] = v.w;
            }
        } else {
            #pragma unroll
            for (int i = 0; i < 16; i++) {
                int gk = k0 + i;
                ra[i] = (gr < M && gk < K) ? A[(long)gr * K + gk] : 0.f;
            }
        }
    };
    auto loadB = [&](int k0) {
        int gk = k0 + brow;
        rb0 = make_float4(0.f, 0.f, 0.f, 0.f);
        rb1 = rb0;
        if (gk < K) {
            rb0 = *(const float4*)(B + (long)gk * N + bcol);
            rb1 = *(const float4*)(B + (long)gk * N + bcol + 4);
        }
    };
    auto storeA = [&](int s) {
        #pragma unroll
        for (int i = 0; i < 16; i++) As[s][i][arow] = ra[i];
    };
    auto storeB = [&](int s) {
        *(float4*)&Bs[s][brow][bcol] = rb0;
        *(float4*)&Bs[s][brow][bcol + 4] = rb1;
    };

    loadA(0); loadB(0);
    storeA(0); storeB(0);
    __syncthreads();

    int s = 0;
    for (int t = 0; t < nk; t++) {
        if (t + 1 < nk) { loadA((t + 1) * BK); loadB((t + 1) * BK); }
        #pragma unroll
        for (int k = 0; k < BK; k++) {
            float4 a0 = *(float4*)&As[s][k][ty * TM];
            float4 a1 = *(float4*)&As[s][k][ty * TM + 4];
            ulonglong2 bb0 = *(ulonglong2*)&Bs[s][k][tx * 8];
            ulonglong2 bb1 = *(ulonglong2*)&Bs[s][k][tx * 8 + 4];
            unsigned long long b2[4] = {bb0.x, bb0.y, bb1.x, bb1.y};
            float af[8] = {a0.x, a0.y, a0.z, a0.w, a1.x, a1.y, a1.z, a1.w};
            #pragma unroll
            for (int i = 0; i < TM; i++) {
                unsigned long long a2 = hg_pack2(af[i], af[i]);
                #pragma unroll
                for (int j = 0; j < 4; j++) hg_ffma2(acc2[i][j], a2, b2[j]);
            }
        }
        if (t + 1 < nk) {
            storeA(s ^ 1); storeB(s ^ 1);
            __syncthreads();
            s ^= 1;
        }
    }

    int gc = tx * 8;
    float bsv[8];
    #pragma unroll
    for (int j = 0; j < 8; j++) bsv[j] = bias ? bias[gc + j] : 0.f;
    #pragma unroll
    for (int i = 0; i < TM; i++) {
        int gr = row0 + ty * TM + i;
        if (gr >= M) continue;
        float acc[8];
        #pragma unroll
        for (int j = 0; j < 4; j++) hg_unpack2(acc2[i][j], acc[2 * j], acc[2 * j + 1]);
        float* cp = C + (long)gr * N + gc;
        *(float4*)cp = make_float4(acc[0] + bsv[0], acc[1] + bsv[1],
                                   acc[2] + bsv[2], acc[3] + bsv[3]);
        *(float4*)(cp + 4) = make_float4(acc[4] + bsv[4], acc[5] + bsv[5],
                                         acc[6] + bsv[6], acc[7] + bsv[7]);
    }
}

// ---------------- block-diagonal GEMM (K=64 per head) + bias + LN + ELU + coef -------
#define GL_BK 16

__global__ __launch_bounds__(256)
void hg_gemm_ln(const float* __restrict__ A, const float* __restrict__ W,
                const float* __restrict__ bias, const float* __restrict__ gam,
                const float* __restrict__ bet, float* __restrict__ h,
                const float4* __restrict__ wvn, float4* __restrict__ coef, int M) {
    __shared__ float As[GL_BK][4][68];
    __shared__ float Bs[GL_BK][256];
    int tid = threadIdx.x, tx = tid & 31, ty = tid >> 5;
    int row0 = blockIdx.x * 64;
    int arow = tid & 63, apart = tid >> 6;
    int head = tx >> 3;

    unsigned long long acc2[8][4];
    #pragma unroll
    for (int i = 0; i < 8; i++)
        #pragma unroll
        for (int j = 0; j < 4; j++) acc2[i][j] = 0ull;

    for (int k0 = 0; k0 < 64; k0 += GL_BK) {
        __syncthreads();
        {
            int gr = row0 + arow;
            float4 t0 = make_float4(0.f, 0.f, 0.f, 0.f), t1 = t0, t2 = t0, t3 = t0;
            if (gr < M) {
                const float4* ap = (const float4*)(A + (long)gr * HD + apart * 64 + k0);
                t0 = ap[0]; t1 = ap[1]; t2 = ap[2]; t3 = ap[3];
            }
            float vv[16] = {t0.x, t0.y, t0.z, t0.w, t1.x, t1.y, t1.z, t1.w,
                            t2.x, t2.y, t2.z, t2.w, t3.x, t3.y, t3.z, t3.w};
            #pragma unroll
            for (int k = 0; k < GL_BK; k++) As[k][apart][arow] = vv[k];
        }
        {
            int kk = tid >> 4, c = (tid & 15) * 4;
            const float* wp = W + (long)(k0 + kk) * HD;
            #pragma unroll
            for (int q = 0; q < 4; q++)
                *(float4*)&Bs[kk][c + q * 64] = *(const float4*)(wp + c + q * 64);
        }
        __syncthreads();

        #pragma unroll
        for (int k = 0; k < GL_BK; k++) {
            float4 a0 = *(float4*)&As[k][head][ty * 8];
            float4 a1 = *(float4*)&As[k][head][ty * 8 + 4];
            ulonglong2 bb0 = *(ulonglong2*)&Bs[k][tx * 8];
            ulonglong2 bb1 = *(ulonglong2*)&Bs[k][tx * 8 + 4];
            unsigned long long b2[4] = {bb0.x, bb0.y, bb1.x, bb1.y};
            float af[8] = {a0.x, a0.y, a0.z, a0.w, a1.x, a1.y, a1.z, a1.w};
            #pragma unroll
            for (int i = 0; i < 8; i++) {
                unsigned long long a2 = hg_pack2(af[i], af[i]);
                #pragma unroll
                for (int j = 0; j < 4; j++) hg_ffma2(acc2[i][j], a2, b2[j]);
            }
        }
    }

    int cbase = tx * 8;
    float bsv[8], gmv[8], btv[8];
    {
        float4 t0 = *(const float4*)(bias + cbase), t1 = *(const float4*)(bias + cbase + 4);
        bsv[0]=t0.x; bsv[1]=t0.y; bsv[2]=t0.z; bsv[3]=t0.w;
        bsv[4]=t1.x; bsv[5]=t1.y; bsv[6]=t1.z; bsv[7]=t1.w;
        t0 = *(const float4*)(gam + cbase); t1 = *(const float4*)(gam + cbase + 4);
        gmv[0]=t0.x; gmv[1]=t0.y; gmv[2]=t0.z; gmv[3]=t0.w;
        gmv[4]=t1.x; gmv[5]=t1.y; gmv[6]=t1.z; gmv[7]=t1.w;
        t0 = *(const float4*)(bet + cbase); t1 = *(const float4*)(bet + cbase + 4);
        btv[0]=t0.x; btv[1]=t0.y; btv[2]=t0.z; btv[3]=t0.w;
        btv[4]=t1.x; btv[5]=t1.y; btv[6]=t1.z; btv[7]=t1.w;
    }
    float4 wv4[8];
    if (wvn) {
        #pragma unroll
        for (int j = 0; j < 8; j++) wv4[j] = wvn[cbase + j];
    }

    #pragma unroll
    for (int i = 0; i < 8; i++) {
        int r = row0 + ty * 8 + i;
        float v[8];
        #pragma unroll
        for (int j = 0; j < 4; j++) hg_unpack2(acc2[i][j], v[2 * j], v[2 * j + 1]);
        #pragma unroll
        for (int j = 0; j < 8; j++) v[j] += bsv[j];
        float sum = 0.f, sq = 0.f;
        #pragma unroll
        for (int j = 0; j < 8; j++) { sum += v[j]; sq += v[j] * v[j]; }
        #pragma unroll
        for (int o = 16; o > 0; o >>= 1) {
            sum += __shfl_xor_sync(0xffffffffu, sum, o);
            sq  += __shfl_xor_sync(0xffffffffu, sq, o);
        }
        float mu = sum * (1.f / HD);
        float var = sq * (1.f / HD) - mu * mu;
        float rstd = rsqrtf(var + LN_EPS);
        float y[8];
        #pragma unroll
        for (int j = 0; j < 8; j++) {
            float t = (v[j] - mu) * rstd * gmv[j] + btv[j];
            y[j] = t > 0.f ? t : expm1f(t);
        }
        if (r < M) {
            float* hp = h + (long)r * HD + cbase;
            *(float4*)hp = make_float4(y[0], y[1], y[2], y[3]);
            *(float4*)(hp + 4) = make_float4(y[4], y[5], y[6], y[7]);
        }
        if (wvn) {
            float p0 = 0.f, p1 = 0.f, p2 = 0.f, p3 = 0.f;
            #pragma unroll
            for (int j = 0; j < 8; j++) {
                p0 += y[j] * wv4[j].x; p1 += y[j] * wv4[j].y;
                p2 += y[j] * wv4[j].z; p3 += y[j] * wv4[j].w;
            }
            #pragma unroll
            for (int o = 16; o > 0; o >>= 1) {
                p0 += __shfl_xor_sync(0xffffffffu, p0, o);
                p1 += __shfl_xor_sync(0xffffffffu, p1, o);
                p2 += __shfl_xor_sync(0xffffffffu, p2, o);
                p3 += __shfl_xor_sync(0xffffffffu, p3, o);
            }
            if (tx == 0 && r < M) coef[r] = make_float4(p0, p1, p2, p3);
        }
    }
}

// ---------------- CSR build ----------------
__global__ void hg_zero2(int* a, int na, int* b, int nb) {
    int i = blockIdx.x * blockDim.x + threadIdx.x;
    if (i < na) a[i] = 0;
    if (i < nb) b[i] = 0;
}

__global__ void hg_count(const int* __restrict__ dst_at, int* cnt_at,
                         const int* __restrict__ dst_ta, int* cnt_ta) {
    int i = blockIdx.x * blockDim.x + threadIdx.x;
    if (i < NE) {
        atomicAdd(&cnt_at[dst_at[i]], 1);
        atomicAdd(&cnt_ta[dst_ta[i]], 1);
    }
}

__device__ __forceinline__ int hg_warp_incl_scan(int v, int lane) {
    #pragma unroll
    for (int o = 1; o < 32; o <<= 1) {
        int t = __shfl_up_sync(0xffffffffu, v, o);
        if (lane >= o) v += t;
    }
    return v;
}

__global__ void hg_scan1(const int* __restrict__ cnt, int* __restrict__ rp,
                         int* __restrict__ bsum, int n) {
    __shared__ int ws[32];
    int lane = threadIdx.x & 31, wid = threadIdx.x >> 5;
    int i = blockIdx.x * 1024 + threadIdx.x;
    int v = (i < n) ? cnt[i] : 0;
    int s = hg_warp_incl_scan(v, lane);
    if (lane == 31) ws[wid] = s;
    __syncthreads();
    if (wid == 0) {
        int w = ws[lane];
        w = hg_warp_incl_scan(w, lane);
        ws[lane] = w;
    }
    __syncthreads();
    s += (wid ? ws[wid - 1] : 0);
    if (i < n) rp[i + 1] = s;
    if (bsum && threadIdx.x == 1023) bsum[blockIdx.x] = s;
}

__global__ void hg_scan3(int* __restrict__ rp, const int* __restrict__ bsum, int n) {
    int i = blockIdx.x * blockDim.x + threadIdx.x;
    if (i == 0) rp[0] = 0;
    if (i < n) {
        int b = i >> 10;
        if (b > 0) rp[i + 1] += bsum[b - 1];
    }
}

__global__ void hg_fill(const int* __restrict__ s_at, const int* __restrict__ d_at,
                        int* cur_at, int* src_at, int* dst_at,
                        const int* __restrict__ s_ta, const int* __restrict__ d_ta,
                        int* cur_ta, int* src_ta, int* dst_ta) {
    int i = blockIdx.x * blockDim.x + threadIdx.x;
    if (i < NE) {
        int d0 = d_at[i];
        int p = atomicAdd(&cur_at[d0], 1);
        src_at[p] = s_at[i];
        dst_at[p] = d0;
        int d1 = d_ta[i];
        int q = atomicAdd(&cur_ta[d1], 1);
        src_ta[q] = s_ta[i];
        dst_ta[q] = d1;
    }
}

// ---------------- folded attention weights, all 6 in one launch ----------------
struct AttW6 {
    const float* W[6];
    const float* a[6];
    float* o[6];
    int K[6];
};

__global__ void hg_att_w6(AttW6 p) {
    int j = blockIdx.y;
    int k = blockIdx.x;
    if (k >= p.K[j]) return;
    int head = threadIdx.x >> 5, lane = threadIdx.x & 31;
    const float* wr = p.W[j] + (long)k * HD + head * 64;
    const float* ar = p.a[j] + head * 64;
    float s = wr[lane] * ar[lane] + wr[lane + 32] * ar[lane + 32];
    #pragma unroll
    for (int o = 16; o > 0; o >>= 1) s += __shfl_xor_sync(0xffffffffu, s, o);
    if (lane == 0) p.o[j][k * 4 + head] = s;
}

// ---------------- fused node coefficients (layer-0, from h64) ----------------
__global__ void hg_coef2(const float* __restrict__ x,
                         const float* __restrict__ Wv1, const float* __restrict__ Wv2,
                         float4* __restrict__ out1, float4* __restrict__ out2,
                         int n, int K) {
    int warp = (blockIdx.x * blockDim.x + threadIdx.x) >> 5;
    int lane = threadIdx.x & 31;
    if (warp >= n) return;
    const float* xp = x + (long)warp * K;
    const float4* wv1 = (const float4*)Wv1;
    const float4* wv2 = (const float4*)Wv2;
    float s0 = 0.f, s1 = 0.f, s2 = 0.f, s3 = 0.f;
    float t0 = 0.f, t1 = 0.f, t2 = 0.f, t3 = 0.f;
    for (int k = lane; k < K; k += 32) {
        float xv = xp[k];
        float4 w1 = wv1[k];
        float4 w2 = wv2[k];
        s0 += xv * w1.x; s1 += xv * w1.y; s2 += xv * w1.z; s3 += xv * w1.w;
        t0 += xv * w2.x; t1 += xv * w2.y; t2 += xv * w2.z; t3 += xv * w2.w;
    }
    #pragma unroll
    for (int o = 16; o > 0; o >>= 1) {
        s0 += __shfl_xor_sync(0xffffffffu, s0, o);
        s1 += __shfl_xor_sync(0xffffffffu, s1, o);
        s2 += __shfl_xor_sync(0xffffffffu, s2, o);
        s3 += __shfl_xor_sync(0xffffffffu, s3, o);
        t0 += __shfl_xor_sync(0xffffffffu, t0, o);
        t1 += __shfl_xor_sync(0xffffffffu, t1, o);
        t2 += __shfl_xor_sync(0xffffffffu, t2, o);
        t3 += __shfl_xor_sync(0xffffffffu, t3, o);
    }
    if (lane == 0) {
        out1[warp] = make_float4(s0, s1, s2, s3);
        out2[warp] = make_float4(t0, t1, t2, t3);
    }
}

// ---------------- per-edge logits in CSR order ----------------
__device__ __forceinline__ float hg_leaky(float v) { return v >= 0.f ? v : NEG_SLOPE * v; }

__global__ void hg_edge_al(const int* __restrict__ src, const int* __restrict__ dst,
                           const float4* __restrict__ als, const float4* __restrict__ ald,
                           float4* __restrict__ al) {
    int i = blockIdx.x * blockDim.x + threadIdx.x;
    if (i >= NE) return;
    float4 s = als[src[i]];
    float4 d = ald[dst[i]];
    float4 r;
    r.x = hg_leaky(s.x + d.x);
    r.y = hg_leaky(s.y + d.y);
    r.z = hg_leaky(s.z + d.z);
    r.w = hg_leaky(s.w + d.w);
    al[i] = r;
}

__global__ void hg_edge_al2(const int* __restrict__ src0, const int* __restrict__ dst0,
                            const float4* __restrict__ als0, const float4* __restrict__ ald0,
                            float4* __restrict__ al0,
                            const int* __restrict__ src1, const int* __restrict__ dst1,
                            const float4* __restrict__ als1, const float4* __restrict__ ald1,
                            float4* __restrict__ al1) {
    int i = blockIdx.x * blockDim.x + threadIdx.x;
    if (i < NE) {
        float4 s = als0[src0[i]];
        float4 d = ald0[dst0[i]];
        al0[i] = make_float4(hg_leaky(s.x + d.x), hg_leaky(s.y + d.y),
                             hg_leaky(s.z + d.z), hg_leaky(s.w + d.w));
    } else if (i < 2 * NE) {
        int j = i - NE;
        float4 s = als1[src1[j]];
        float4 d = ald1[dst1[j]];
        al1[j] = make_float4(hg_leaky(s.x + d.x), hg_leaky(s.y + d.y),
                             hg_leaky(s.z + d.z), hg_leaky(s.w + d.w));
    }
}

// ---------------- layer-0: 2-pass softmax agg of 64-dim x into head blocks ------------
__global__ void hg_agg64(const float* __restrict__ x, const int* __restrict__ srcs,
                         const float4* __restrict__ al, const int* __restrict__ rp,
                         float* __restrict__ aggx, int ndst) {
    int warp = (blockIdx.x * blockDim.x + threadIdx.x) >> 5;
    int lane = threadIdx.x & 31;
    if (warp >= ndst) return;
    int beg = rp[warp], end = rp[warp + 1];
    int c0 = lane * 8;
    int hl = lane >> 3;
    int xo = c0 & 63;

    float acc[8] = {0.f, 0.f, 0.f, 0.f, 0.f, 0.f, 0.f, 0.f};
    if (beg < end) {
        float m0 = -3.4e38f, m1 = -3.4e38f, m2 = -3.4e38f, m3 = -3.4e38f;
        for (int t = beg; t < end; t++) {
            float4 a = al[t];
            m0 = fmaxf(m0, a.x); m1 = fmaxf(m1, a.y);
            m2 = fmaxf(m2, a.z); m3 = fmaxf(m3, a.w);
        }
        float mh = (hl & 2) ? ((hl & 1) ? m3 : m2) : ((hl & 1) ? m1 : m0);
        float den = 0.f;
        for (int t = beg; t < end; t++) {
            int sidx = srcs[t];
            float4 a = al[t];
            float av = (hl & 2) ? ((hl & 1) ? a.w : a.z) : ((hl & 1) ? a.y : a.x);
            float e = __expf(av - mh);
            den += e;
            const float4* hp = (const float4*)(x + (long)sidx * HDIM + xo);
            float4 v0 = hp[0], v1 = hp[1];
            acc[0] += e * v0.x; acc[1] += e * v0.y;
            acc[2] += e * v0.z; acc[3] += e * v0.w;
            acc[4] += e * v1.x; acc[5] += e * v1.y;
            acc[6] += e * v1.z; acc[7] += e * v1.w;
        }
        float inv = 1.f / den;
        #pragma unroll
        for (int j = 0; j < 8; j++) acc[j] *= inv;
    }
    float* op = aggx + (long)warp * HD + c0;
    *(float4*)op = make_float4(acc[0], acc[1], acc[2], acc[3]);
    *(float4*)(op + 4) = make_float4(acc[4], acc[5], acc[6], acc[7]);
}

// ---------------- layer-1 FUSED 2-pass agg + bias + LN + residual + ELU --------------
__global__ void hg_gat_agg_ln(const float* __restrict__ hs, const int* __restrict__ srcs,
                              const float4* __restrict__ al, const int* __restrict__ rp,
                              const float* __restrict__ bias, const float* __restrict__ gam,
                              const float* __restrict__ bet, float* __restrict__ h,
                              int residual, int ndst) {
    int warp = (blockIdx.x * blockDim.x + threadIdx.x) >> 5;
    int lane = threadIdx.x & 31;
    if (warp >= ndst) return;
    int beg = rp[warp], end = rp[warp + 1];
    int c0 = lane * 8;
    int hl = lane >> 3;

    float acc[8] = {0.f, 0.f, 0.f, 0.f, 0.f, 0.f, 0.f, 0.f};
    if (beg < end) {
        float m0 = -3.4e38f, m1 = -3.4e38f, m2 = -3.4e38f, m3 = -3.4e38f;
        for (int t = beg; t < end; t++) {
            float4 a = al[t];
            m0 = fmaxf(m0, a.x); m1 = fmaxf(m1, a.y);
            m2 = fmaxf(m2, a.z); m3 = fmaxf(m3, a.w);
        }
        float mh = (hl & 2) ? ((hl & 1) ? m3 : m2) : ((hl & 1) ? m1 : m0);
        float den = 0.f;
        for (int t = beg; t < end; t++) {
            int sidx = srcs[t];
            float4 a = al[t];
            float av = (hl & 2) ? ((hl & 1) ? a.w : a.z) : ((hl & 1) ? a.y : a.x);
            float e = __expf(av - mh);
            den += e;
            const float4* hp = (const float4*)(hs + (long)sidx * HD + c0);
            float4 v0 = hp[0], v1 = hp[1];
            acc[0] += e * v0.x; acc[1] += e * v0.y;
            acc[2] += e * v0.z; acc[3] += e * v0.w;
            acc[4] += e * v1.x; acc[5] += e * v1.y;
            acc[6] += e * v1.z; acc[7] += e * v1.w;
        }
        float inv = 1.f / den;
        #pragma unroll
        for (int j = 0; j < 8; j++) acc[j] *= inv;
    }

    const float4* bp = (const float4*)(bias + c0);
    float4 b0 = bp[0], b1 = bp[1];
    float v[8] = {acc[0] + b0.x, acc[1] + b0.y, acc[2] + b0.z, acc[3] + b0.w,
                  acc[4] + b1.x, acc[5] + b1.y, acc[6] + b1.z, acc[7] + b1.w};
    float sum = 0.f, sq = 0.f;
    #pragma unroll
    for (int j = 0; j < 8; j++) { sum += v[j]; sq += v[j] * v[j]; }
    #pragma unroll
    for (int o = 16; o > 0; o >>= 1) {
        sum += __shfl_xor_sync(0xffffffffu, sum, o);
        sq  += __shfl_xor_sync(0xffffffffu, sq, o);
    }
    float mu = sum * (1.f / HD);
    float var = sq * (1.f / HD) - mu * mu;
    float rstd = rsqrtf(var + LN_EPS);

    const float4* gp = (const float4*)(gam + c0);
    const float4* ep = (const float4*)(bet + c0);
    float4 g0 = gp[0], g1 = gp[1];
    float4 e0 = ep[0], e1 = ep[1];
    float gm[8] = {g0.x, g0.y, g0.z, g0.w, g1.x, g1.y, g1.z, g1.w};
    float bt[8] = {e0.x, e0.y, e0.z, e0.w, e1.x, e1.y, e1.z, e1.w};
    float* hp = h + (long)warp * HD + c0;
    float r[8] = {0.f, 0.f, 0.f, 0.f, 0.f, 0.f, 0.f, 0.f};
    if (residual) {
        float4 r0 = ((const float4*)hp)[0], r1 = ((const float4*)hp)[1];
        r[0] = r0.x; r[1] = r0.y; r[2] = r0.z; r[3] = r0.w;
        r[4] = r1.x; r[5] = r1.y; r[6] = r1.z; r[7] = r1.w;
    }
    float y[8];
    #pragma unroll
    for (int j = 0; j < 8; j++) {
        float t = (v[j] - mu) * rstd * gm[j] + bt[j] + r[j];
        y[j] = t > 0.f ? t : expm1f(t);
    }
    *(float4*)hp = make_float4(y[0], y[1], y[2], y[3]);
    *(float4*)(hp + 4) = make_float4(y[4], y[5], y[6], y[7]);
}

// ---------------- mean pooling addr -> tx (warp per tx node) ----------------
__global__ void hg_pool_mean(const float* __restrict__ haddr, const int* __restrict__ srcs,
                             const int* __restrict__ rp, float* __restrict__ out, int ndst) {
    int warp = (blockIdx.x * blockDim.x + threadIdx.x) >> 5;
    int lane = threadIdx.x & 31;
    if (warp >= ndst) return;
    int beg = rp[warp], end = rp[warp + 1];
    int c0 = lane * 8;
    float acc[8] = {0.f, 0.f, 0.f, 0.f, 0.f, 0.f, 0.f, 0.f};
    for (int t = beg; t < end; t++) {
        int s = srcs[t];
        const float4* hp = (const float4*)(haddr + (long)s * HD + c0);
        float4 v0 = hp[0], v1 = hp[1];
        acc[0] += v0.x; acc[1] += v0.y; acc[2] += v0.z; acc[3] += v0.w;
        acc[4] += v1.x; acc[5] += v1.y; acc[6] += v1.z; acc[7] += v1.w;
    }
    int deg = end - beg;
    float inv = 1.f / (float)(deg > 0 ? deg : 1);
    float* op = out + (long)warp * HD + c0;
    *(float4*)op = make_float4(acc[0] * inv, acc[1] * inv, acc[2] * inv, acc[3] * inv);
    *(float4*)(op + 4) = make_float4(acc[4] * inv, acc[5] * inv, acc[6] * inv, acc[7] * inv);
}

// ---------------- host launcher ----------------
#define SYMADDR(p, s) do { void* _t = nullptr; cudaGetSymbolAddress(&_t, s); p = (decltype(p))_t; } while (0)

static inline void launch_gemm(const float* A, const float* B, const float* bias,
                               float* C, int M, int N, int K) {
    dim3 grid((N + BN - 1) / BN, (M + BM - 1) / BM);
    hg_sgemm<<<grid, 256>>>(A, B, bias, C, M, N, K);
}

// side stream + fork/join events (created once; host objects, no device memory)
static cudaStream_t hg_s1 = nullptr;
static cudaEvent_t hg_ev_fork = nullptr, hg_ev_join = nullptr;

extern "C" void kernel_launch(void* const* d_in, const int* in_sizes, int n_in,
                              void* d_out, int out_size) {
    const float* x_tx      = (const float*)d_in[0];
    const float* x_addr    = (const float*)d_in[1];
    const int*   addr_idx_at = (const int*)d_in[2];
    const int*   tx_idx_at   = (const int*)d_in[3];
    const int*   tx_idx_ta   = (const int*)d_in[4];
    const int*   addr_idx_ta = (const int*)d_in[5];
    const float* w_in_tx   = (const float*)d_in[6];
    const float* b_in_tx   = (const float*)d_in[7];
    const float* w_in_addr = (const float*)d_in[8];
    const float* b_in_addr = (const float*)d_in[9];
    const float* w_at0 = (const float*)d_in[10];
    const float* as_at0 = (const float*)d_in[11];
    const float* ad_at0 = (const float*)d_in[12];
    const float* b_at0 = (const float*)d_in[13];
    const float* w_ta0 = (const float*)d_in[14];
    const float* as_ta0 = (const float*)d_in[15];
    const float* ad_ta0 = (const float*)d_in[16];
    const float* b_ta0 = (const float*)d_in[17];
    // layer-1 at-relation weights are dead (h_tx after layer 1 unused by output)
    const float* w_ta1 = (const float*)d_in[22];
    const float* as_ta1 = (const float*)d_in[23];
    const float* ad_ta1 = (const float*)d_in[24];
    const float* b_ta1 = (const float*)d_in[25];
    const float* ln_g_tx = (const float*)d_in[26];
    const float* ln_b_tx = (const float*)d_in[27];
    const float* ln_g_addr = (const float*)d_in[28];
    const float* ln_b_addr = (const float*)d_in[29];
    const float* w_out = (const float*)d_in[30];
    const float* b_out = (const float*)d_in[31];
    float* out = (float*)d_out;

    float *p_htx64, *p_haddr64, *p_buf_addr, *p_buf_tx, *p_pool_tx, *p_htx, *p_haddr;
    float4 *p_als_at, *p_ald_at, *p_als_ta, *p_ald_ta, *p_al_at, *p_al_ta;
    int *p_cnt_tx, *p_cnt_addr, *p_rp_at, *p_rp_ta, *p_cur_tx, *p_cur_addr;
    int *p_src_at, *p_dst_at, *p_src_ta, *p_dst_ta, *p_bsum_tx, *p_bsum_addr;
    float *p_ws_at, *p_wd_at, *p_ws_ta, *p_wd_ta, *p_ws_ta1, *p_wd_ta1;
    SYMADDR(p_htx64, g_htx64);     SYMADDR(p_haddr64, g_haddr64);
    SYMADDR(p_buf_addr, g_buf_addr); SYMADDR(p_buf_tx, g_buf_tx);
    SYMADDR(p_pool_tx, g_pool_tx);
    SYMADDR(p_htx, g_htx);         SYMADDR(p_haddr, g_haddr);
    SYMADDR(p_als_at, g_als_at);   SYMADDR(p_ald_at, g_ald_at);
    SYMADDR(p_als_ta, g_als_ta);   SYMADDR(p_ald_ta, g_ald_ta);
    SYMADDR(p_al_at, g_al_at);     SYMADDR(p_al_ta, g_al_ta);
    SYMADDR(p_cnt_tx, g_cnt_tx);   SYMADDR(p_cnt_addr, g_cnt_addr);
    SYMADDR(p_rp_at, g_rp_at);     SYMADDR(p_rp_ta, g_rp_ta);
    SYMADDR(p_cur_tx, g_cur_tx);   SYMADDR(p_cur_addr, g_cur_addr);
    SYMADDR(p_src_at, g_src_at);   SYMADDR(p_dst_at, g_dst_at);
    SYMADDR(p_src_ta, g_src_ta);   SYMADDR(p_dst_ta, g_dst_ta);
    SYMADDR(p_bsum_tx, g_bsum_tx); SYMADDR(p_bsum_addr, g_bsum_addr);
    SYMADDR(p_ws_at, g_ws_at);     SYMADDR(p_wd_at, g_wd_at);
    SYMADDR(p_ws_ta, g_ws_ta);     SYMADDR(p_wd_ta, g_wd_ta);
    SYMADDR(p_ws_ta1, g_ws_ta1);   SYMADDR(p_wd_ta1, g_wd_ta1);

    if (!hg_s1) {
        cudaStreamCreateWithFlags(&hg_s1, cudaStreamNonBlocking);
        cudaEventCreateWithFlags(&hg_ev_fork, cudaEventDisableTiming);
        cudaEventCreateWithFlags(&hg_ev_join, cudaEventDisableTiming);
    }

    const int TB = 256;
    const int nb_tx = (N_TX + 1023) / 1024;
    const int nb_addr = (N_ADDR + 1023) / 1024;
    int cblk_tx = (N_TX * 32 + TB - 1) / TB;
    int cblk_addr = (N_ADDR * 32 + TB - 1) / TB;
    int eblk = (NE + TB - 1) / TB;

    // ---- fork: side stream runs CSR build + att_w6 + addr projection,
    //      main stream runs tx projection concurrently ----
    cudaEventRecord(hg_ev_fork, 0);
    cudaStreamWaitEvent(hg_s1, hg_ev_fork, 0);

    // (side stream) CSR build
    hg_zero2<<<(N_ADDR + TB - 1) / TB, TB, 0, hg_s1>>>(p_cnt_tx, N_TX, p_cnt_addr, N_ADDR);
    hg_count<<<(NE + TB - 1) / TB, TB, 0, hg_s1>>>(tx_idx_at, p_cnt_tx, addr_idx_ta, p_cnt_addr);
    hg_scan1<<<nb_tx, 1024, 0, hg_s1>>>(p_cnt_tx, p_rp_at, p_bsum_tx, N_TX);
    hg_scan1<<<nb_addr, 1024, 0, hg_s1>>>(p_cnt_addr, p_rp_ta, p_bsum_addr, N_ADDR);
    hg_scan1<<<1, 1024, 0, hg_s1>>>(p_bsum_tx, p_bsum_tx - 1, nullptr, nb_tx);
    hg_scan1<<<1, 1024, 0, hg_s1>>>(p_bsum_addr, p_bsum_addr - 1, nullptr, nb_addr);
    hg_scan3<<<(N_TX + TB - 1) / TB, TB, 0, hg_s1>>>(p_rp_at, p_bsum_tx, N_TX);
    hg_scan3<<<(N_ADDR + TB - 1) / TB, TB, 0, hg_s1>>>(p_rp_ta, p_bsum_addr, N_ADDR);
    cudaMemcpyAsync(p_cur_tx, p_rp_at, N_TX * sizeof(int), cudaMemcpyDeviceToDevice, hg_s1);
    cudaMemcpyAsync(p_cur_addr, p_rp_ta, N_ADDR * sizeof(int), cudaMemcpyDeviceToDevice, hg_s1);
    hg_fill<<<(NE + TB - 1) / TB, TB, 0, hg_s1>>>(addr_idx_at, tx_idx_at, p_cur_tx,
                                                  p_src_at, p_dst_at,
                                                  tx_idx_ta, addr_idx_ta, p_cur_addr,
                                                  p_src_ta, p_dst_ta);
    // (side stream) fold all 6 attention weight vectors
    {
        AttW6 p;
        p.W[0] = w_at0; p.a[0] = as_at0; p.o[0] = p_ws_at;  p.K[0] = HDIM;
        p.W[1] = w_at0; p.a[1] = ad_at0; p.o[1] = p_wd_at;  p.K[1] = HDIM;
        p.W[2] = w_ta0; p.a[2] = as_ta0; p.o[2] = p_ws_ta;  p.K[2] = HDIM;
        p.W[3] = w_ta0; p.a[3] = ad_ta0; p.o[3] = p_wd_ta;  p.K[3] = HDIM;
        p.W[4] = w_ta1; p.a[4] = as_ta1; p.o[4] = p_ws_ta1; p.K[4] = HD;
        p.W[5] = w_ta1; p.a[5] = ad_ta1; p.o[5] = p_wd_ta1; p.K[5] = HD;
        hg_att_w6<<<dim3(HD, 6), 128, 0, hg_s1>>>(p);
    }
    // (side stream) addr input projection
    hg_sgemm_n64<<<(N_ADDR + BM - 1) / BM, 128, 0, hg_s1>>>(x_addr, w_in_addr, b_in_addr,
                                                            p_haddr64, N_ADDR, F_ADDR);
    cudaEventRecord(hg_ev_join, hg_s1);

    // (main stream) tx input projection, concurrent with the side stream
    hg_sgemm_n64<<<(N_TX + BM - 1) / BM, 128>>>(x_tx, w_in_tx, b_in_tx, p_htx64,
                                                N_TX, F_TX);

    // join: everything below needs CSR + both projections + folded weights
    cudaStreamWaitEvent(0, hg_ev_join, 0);

    // ---- layer 0: coefficients from h64, logits, aggregate-then-project ----
    hg_coef2<<<cblk_addr, TB>>>(p_haddr64, p_ws_at, p_wd_ta, p_als_at, p_ald_ta,
                                N_ADDR, HDIM);
    hg_coef2<<<cblk_tx,   TB>>>(p_htx64,   p_wd_at, p_ws_ta, p_ald_at, p_als_ta,
                                N_TX, HDIM);

    hg_edge_al2<<<2 * eblk, TB>>>(p_src_at, p_dst_at, p_als_at, p_ald_at, p_al_at,
                                  p_src_ta, p_dst_ta, p_als_ta, p_ald_ta, p_al_ta);

    // aggregate 64-dim sources into head-blocked aggx (2-pass softmax)
    hg_agg64<<<cblk_tx,   TB>>>(p_haddr64, p_src_at, p_al_at, p_rp_at, p_buf_tx, N_TX);
    hg_agg64<<<cblk_addr, TB>>>(p_htx64,   p_src_ta, p_al_ta, p_rp_ta, p_buf_addr, N_ADDR);

    // block-diagonal GEMM + bias + LN + ELU + next-layer coef
    hg_gemm_ln<<<(N_TX + 63) / 64, 256>>>(p_buf_tx, w_at0, b_at0, ln_g_tx, ln_b_tx,
                                          p_htx, (const float4*)p_ws_ta1, p_als_ta, N_TX);
    hg_gemm_ln<<<(N_ADDR + 63) / 64, 256>>>(p_buf_addr, w_ta0, b_ta0, ln_g_addr, ln_b_addr,
                                            p_haddr, (const float4*)p_wd_ta1, p_ald_ta,
                                            N_ADDR);

    // ---- layer 1 (ta relation only; tx branch is dead): project-then-aggregate ----
    launch_gemm(p_htx, w_ta1, nullptr, p_buf_tx, N_TX, HD, HD);

    hg_edge_al<<<eblk, TB>>>(p_src_ta, p_dst_ta, p_als_ta, p_ald_ta, p_al_ta);

    hg_gat_agg_ln<<<cblk_addr, TB>>>(p_buf_tx, p_src_ta, p_al_ta, p_rp_ta,
                                     b_ta1, ln_g_addr, ln_b_addr, p_haddr, 1, N_ADDR);

    // ---- scatter-mean pooling addr -> tx over 'at' edges ----
    hg_pool_mean<<<cblk_tx, TB>>>(p_haddr, p_src_at, p_rp_at, p_pool_tx, N_TX);

    // ---- output projection ----
    launch_gemm(p_pool_tx, w_out, b_out, out, N_TX, HD, HD);
}

// round 17
// speedup vs baseline: 1.4266x; 1.0208x over previous
#include <cuda_runtime.h>
#include <math.h>
#include <stdint.h>

// ---------------- problem constants ----------------
#define N_TX   100000
#define N_ADDR 200000
#define NE     400000
#define F_TX   165
#define F_ADDR 64
#define HDIM   64
#define HD     256
#define LN_EPS 1e-5f
#define NEG_SLOPE 0.2f

// ---------------- scratch (device globals; no cudaMalloc allowed) ----------------
__device__ float g_htx64[(size_t)N_TX * HDIM];
__device__ float g_haddr64[(size_t)N_ADDR * HDIM];
__device__ float g_buf_addr[(size_t)N_ADDR * HD];
__device__ float g_buf_tx[(size_t)N_TX * HD];
__device__ float g_pool_tx[(size_t)N_TX * HD];
__device__ float g_htx[(size_t)N_TX * HD];
__device__ float g_haddr[(size_t)N_ADDR * HD];
__device__ float4 g_als_at[N_ADDR];
__device__ float4 g_ald_at[N_TX];
__device__ float4 g_als_ta[N_TX];
__device__ float4 g_ald_ta[N_ADDR];
__device__ float4 g_al_at[NE];
__device__ float4 g_al_ta[NE];
__device__ int g_cnt_tx[N_TX];
__device__ int g_cnt_addr[N_ADDR];
__device__ int g_rp_at[N_TX + 1];
__device__ int g_rp_ta[N_ADDR + 1];
__device__ int g_cur_tx[N_TX];
__device__ int g_cur_addr[N_ADDR];
__device__ int g_src_at[NE];
__device__ int g_dst_at[NE];
__device__ int g_src_ta[NE];
__device__ int g_dst_ta[NE];
__device__ int g_bsum_tx[256];
__device__ int g_bsum_addr[256];
__device__ float g_ws_at[HD * 4];
__device__ float g_wd_at[HD * 4];
__device__ float g_ws_ta[HD * 4];
__device__ float g_wd_ta[HD * 4];
__device__ float g_ws_ta1[HD * 4];
__device__ float g_wd_ta1[HD * 4];

// ---------------- packed f32x2 helpers (sm_103a FFMA2 pipe) ----------------
__device__ __forceinline__ unsigned long long hg_pack2(float x, float y) {
    unsigned long long r;
    asm("mov.b64 %0, {%1, %2};" : "=l"(r) : "f"(x), "f"(y));
    return r;
}
__device__ __forceinline__ void hg_unpack2(unsigned long long v, float& x, float& y) {
    asm("mov.b64 {%0, %1}, %2;" : "=f"(x), "=f"(y) : "l"(v));
}
__device__ __forceinline__ void hg_ffma2(unsigned long long& d,
                                         unsigned long long a, unsigned long long b) {
    asm("fma.rn.f32x2 %0, %1, %2, %0;" : "+l"(d) : "l"(a), "l"(b));
}

// ---------------- SGEMM (N>=128 path): C[M,N] = A[M,K] @ B[K,N] (+bias) --------------
#define BM 128
#define BN 128
#define BK 16
#define TM 8
#define TN 8

__global__ __launch_bounds__(256)
void hg_sgemm(const float* __restrict__ A, const float* __restrict__ B,
              const float* __restrict__ bias, float* __restrict__ C,
              int M, int N, int K) {
    __shared__ float As[2][BK][BM];
    __shared__ float Bs[2][BK][BN];
    int tid = threadIdx.x;
    int row0 = blockIdx.y * BM, col0 = blockIdx.x * BN;
    int tx = tid & 15, ty = tid >> 4;
    int arow = tid >> 1, acol = (tid & 1) * 8;
    int brow = tid >> 4, bcol = (tid & 15) * 8;
    bool k4 = ((K & 3) == 0);
    int nk = (K + BK - 1) / BK;

    float ra[8];
    float4 rb0, rb1;

    unsigned long long acc2[TM][TN / 2];
    #pragma unroll
    for (int i = 0; i < TM; i++)
        #pragma unroll
        for (int j = 0; j < TN / 2; j++) acc2[i][j] = 0ull;

    auto loadA = [&](int k0) {
        int gr = row0 + arow;
        if (k4) {
            #pragma unroll
            for (int i = 0; i < 8; i += 4) {
                int gk = k0 + acol + i;
                float4 v = make_float4(0.f, 0.f, 0.f, 0.f);
                if (gr < M && gk < K) v = *(const float4*)(A + (long)gr * K + gk);
                ra[i] = v.x; ra[i + 1] = v.y; ra[i + 2] = v.z; ra[i + 3] = v.w;
            }
        } else {
            #pragma unroll
            for (int i = 0; i < 8; i++) {
                int gk = k0 + acol + i;
                ra[i] = (gr < M && gk < K) ? A[(long)gr * K + gk] : 0.f;
            }
        }
    };
    auto loadB = [&](int k0) {
        int gk = k0 + brow, gn = col0 + bcol;
        rb0 = make_float4(0.f, 0.f, 0.f, 0.f);
        rb1 = rb0;
        if (gk < K && gn < N) {
            rb0 = *(const float4*)(B + (long)gk * N + gn);
            rb1 = *(const float4*)(B + (long)gk * N + gn + 4);
        }
    };
    auto storeA = [&](int s) {
        #pragma unroll
        for (int i = 0; i < 8; i++) As[s][acol + i][arow] = ra[i];
    };
    auto storeB = [&](int s) {
        *(float4*)&Bs[s][brow][bcol] = rb0;
        *(float4*)&Bs[s][brow][bcol + 4] = rb1;
    };

    loadA(0); loadB(0);
    storeA(0); storeB(0);
    __syncthreads();

    int s = 0;
    for (int t = 0; t < nk; t++) {
        if (t + 1 < nk) { loadA((t + 1) * BK); loadB((t + 1) * BK); }
        #pragma unroll
        for (int k = 0; k < BK; k++) {
            float4 a0 = *(float4*)&As[s][k][ty * TM];
            float4 a1 = *(float4*)&As[s][k][ty * TM + 4];
            ulonglong2 bb0 = *(ulonglong2*)&Bs[s][k][tx * TN];
            ulonglong2 bb1 = *(ulonglong2*)&Bs[s][k][tx * TN + 4];
            unsigned long long b2[4] = {bb0.x, bb0.y, bb1.x, bb1.y};
            float af[8] = {a0.x, a0.y, a0.z, a0.w, a1.x, a1.y, a1.z, a1.w};
            #pragma unroll
            for (int i = 0; i < TM; i++) {
                unsigned long long a2 = hg_pack2(af[i], af[i]);
                #pragma unroll
                for (int j = 0; j < TN / 2; j++) hg_ffma2(acc2[i][j], a2, b2[j]);
            }
        }
        if (t + 1 < nk) {
            storeA(s ^ 1); storeB(s ^ 1);
            __syncthreads();
            s ^= 1;
        }
    }

    int gc = col0 + tx * TN;
    if (gc >= N) return;
    float bsv[8];
    #pragma unroll
    for (int j = 0; j < 8; j++) bsv[j] = bias ? bias[gc + j] : 0.f;
    #pragma unroll
    for (int i = 0; i < TM; i++) {
        int gr = row0 + ty * TM + i;
        if (gr >= M) continue;
        float acc[8];
        #pragma unroll
        for (int j = 0; j < 4; j++) hg_unpack2(acc2[i][j], acc[2 * j], acc[2 * j + 1]);
        float* cp = C + (long)gr * N + gc;
        *(float4*)cp = make_float4(acc[0] + bsv[0], acc[1] + bsv[1],
                                   acc[2] + bsv[2], acc[3] + bsv[3]);
        *(float4*)(cp + 4) = make_float4(acc[4] + bsv[4], acc[5] + bsv[5],
                                         acc[6] + bsv[6], acc[7] + bsv[7]);
    }
}

// ---------------- SGEMM N=64 path: 128x64 tile, 128 threads (input projections) ------
__global__ __launch_bounds__(128)
void hg_sgemm_n64(const float* __restrict__ A, const float* __restrict__ B,
                  const float* __restrict__ bias, float* __restrict__ C,
                  int M, int K) {
    const int N = 64;
    __shared__ float As[2][BK][BM];
    __shared__ float Bs[2][BK][64];
    int tid = threadIdx.x;
    int row0 = blockIdx.x * BM;
    int tx = tid & 7, ty = tid >> 3;
    int arow = tid;
    int brow = tid >> 3, bcol = (tid & 7) * 8;
    bool k4 = ((K & 3) == 0);
    int nk = (K + BK - 1) / BK;

    float ra[16];
    float4 rb0, rb1;

    unsigned long long acc2[TM][4];
    #pragma unroll
    for (int i = 0; i < TM; i++)
        #pragma unroll
        for (int j = 0; j < 4; j++) acc2[i][j] = 0ull;

    auto loadA = [&](int k0) {
        int gr = row0 + arow;
        if (k4) {
            #pragma unroll
            for (int i = 0; i < 16; i += 4) {
                int gk = k0 + i;
                float4 v = make_float4(0.f, 0.f, 0.f, 0.f);
                if (gr < M && gk + 3 < K) v = *(const float4*)(A + (long)gr * K + gk);
                else {
                    #pragma unroll
                    for (int q = 0; q < 4; q++)
                        ((float*)&v)[q] = (gr < M && gk + q < K) ? A[(long)gr * K + gk + q] : 0.f;
                }
                ra[i] = v.x; ra[i + 1] = v.y; ra[i + 2] = v.z; ra[i + 3] = v.w;
            }
        } else {
            #pragma unroll
            for (int i = 0; i < 16; i++) {
                int gk = k0 + i;
                ra[i] = (gr < M && gk < K) ? A[(long)gr * K + gk] : 0.f;
            }
        }
    };
    auto loadB = [&](int k0) {
        int gk = k0 + brow;
        rb0 = make_float4(0.f, 0.f, 0.f, 0.f);
        rb1 = rb0;
        if (gk < K) {
            rb0 = *(const float4*)(B + (long)gk * N + bcol);
            rb1 = *(const float4*)(B + (long)gk * N + bcol + 4);
        }
    };
    auto storeA = [&](int s) {
        #pragma unroll
        for (int i = 0; i < 16; i++) As[s][i][arow] = ra[i];
    };
    auto storeB = [&](int s) {
        *(float4*)&Bs[s][brow][bcol] = rb0;
        *(float4*)&Bs[s][brow][bcol + 4] = rb1;
    };

    loadA(0); loadB(0);
    storeA(0); storeB(0);
    __syncthreads();

    int s = 0;
    for (int t = 0; t < nk; t++) {
        if (t + 1 < nk) { loadA((t + 1) * BK); loadB((t + 1) * BK); }
        #pragma unroll
        for (int k = 0; k < BK; k++) {
            float4 a0 = *(float4*)&As[s][k][ty * TM];
            float4 a1 = *(float4*)&As[s][k][ty * TM + 4];
            ulonglong2 bb0 = *(ulonglong2*)&Bs[s][k][tx * 8];
            ulonglong2 bb1 = *(ulonglong2*)&Bs[s][k][tx * 8 + 4];
            unsigned long long b2[4] = {bb0.x, bb0.y, bb1.x, bb1.y};
            float af[8] = {a0.x, a0.y, a0.z, a0.w, a1.x, a1.y, a1.z, a1.w};
            #pragma unroll
            for (int i = 0; i < TM; i++) {
                unsigned long long a2 = hg_pack2(af[i], af[i]);
                #pragma unroll
                for (int j = 0; j < 4; j++) hg_ffma2(acc2[i][j], a2, b2[j]);
            }
        }
        if (t + 1 < nk) {
            storeA(s ^ 1); storeB(s ^ 1);
            __syncthreads();
            s ^= 1;
        }
    }

    int gc = tx * 8;
    float bsv[8];
    #pragma unroll
    for (int j = 0; j < 8; j++) bsv[j] = bias ? bias[gc + j] : 0.f;
    #pragma unroll
    for (int i = 0; i < TM; i++) {
        int gr = row0 + ty * TM + i;
        if (gr >= M) continue;
        float acc[8];
        #pragma unroll
        for (int j = 0; j < 4; j++) hg_unpack2(acc2[i][j], acc[2 * j], acc[2 * j + 1]);
        float* cp = C + (long)gr * N + gc;
        *(float4*)cp = make_float4(acc[0] + bsv[0], acc[1] + bsv[1],
                                   acc[2] + bsv[2], acc[3] + bsv[3]);
        *(float4*)(cp + 4) = make_float4(acc[4] + bsv[4], acc[5] + bsv[5],
                                         acc[6] + bsv[6], acc[7] + bsv[7]);
    }
}

// ---------------- block-diagonal GEMM (K=64 per head) + bias + LN + ELU + coef -------
#define GL_BK 16

__global__ __launch_bounds__(256)
void hg_gemm_ln(const float* __restrict__ A, const float* __restrict__ W,
                const float* __restrict__ bias, const float* __restrict__ gam,
                const float* __restrict__ bet, float* __restrict__ h,
                const float4* __restrict__ wvn, float4* __restrict__ coef, int M) {
    __shared__ float As[GL_BK][4][68];
    __shared__ float Bs[GL_BK][256];
    int tid = threadIdx.x, tx = tid & 31, ty = tid >> 5;
    int row0 = blockIdx.x * 64;
    int arow = tid & 63, apart = tid >> 6;
    int head = tx >> 3;

    unsigned long long acc2[8][4];
    #pragma unroll
    for (int i = 0; i < 8; i++)
        #pragma unroll
        for (int j = 0; j < 4; j++) acc2[i][j] = 0ull;

    for (int k0 = 0; k0 < 64; k0 += GL_BK) {
        __syncthreads();
        {
            int gr = row0 + arow;
            float4 t0 = make_float4(0.f, 0.f, 0.f, 0.f), t1 = t0, t2 = t0, t3 = t0;
            if (gr < M) {
                const float4* ap = (const float4*)(A + (long)gr * HD + apart * 64 + k0);
                t0 = ap[0]; t1 = ap[1]; t2 = ap[2]; t3 = ap[3];
            }
            float vv[16] = {t0.x, t0.y, t0.z, t0.w, t1.x, t1.y, t1.z, t1.w,
                            t2.x, t2.y, t2.z, t2.w, t3.x, t3.y, t3.z, t3.w};
            #pragma unroll
            for (int k = 0; k < GL_BK; k++) As[k][apart][arow] = vv[k];
        }
        {
            int kk = tid >> 4, c = (tid & 15) * 4;
            const float* wp = W + (long)(k0 + kk) * HD;
            #pragma unroll
            for (int q = 0; q < 4; q++)
                *(float4*)&Bs[kk][c + q * 64] = *(const float4*)(wp + c + q * 64);
        }
        __syncthreads();

        #pragma unroll
        for (int k = 0; k < GL_BK; k++) {
            float4 a0 = *(float4*)&As[k][head][ty * 8];
            float4 a1 = *(float4*)&As[k][head][ty * 8 + 4];
            ulonglong2 bb0 = *(ulonglong2*)&Bs[k][tx * 8];
            ulonglong2 bb1 = *(ulonglong2*)&Bs[k][tx * 8 + 4];
            unsigned long long b2[4] = {bb0.x, bb0.y, bb1.x, bb1.y};
            float af[8] = {a0.x, a0.y, a0.z, a0.w, a1.x, a1.y, a1.z, a1.w};
            #pragma unroll
            for (int i = 0; i < 8; i++) {
                unsigned long long a2 = hg_pack2(af[i], af[i]);
                #pragma unroll
                for (int j = 0; j < 4; j++) hg_ffma2(acc2[i][j], a2, b2[j]);
            }
        }
    }

    int cbase = tx * 8;
    float bsv[8], gmv[8], btv[8];
    {
        float4 t0 = *(const float4*)(bias + cbase), t1 = *(const float4*)(bias + cbase + 4);
        bsv[0]=t0.x; bsv[1]=t0.y; bsv[2]=t0.z; bsv[3]=t0.w;
        bsv[4]=t1.x; bsv[5]=t1.y; bsv[6]=t1.z; bsv[7]=t1.w;
        t0 = *(const float4*)(gam + cbase); t1 = *(const float4*)(gam + cbase + 4);
        gmv[0]=t0.x; gmv[1]=t0.y; gmv[2]=t0.z; gmv[3]=t0.w;
        gmv[4]=t1.x; gmv[5]=t1.y; gmv[6]=t1.z; gmv[7]=t1.w;
        t0 = *(const float4*)(bet + cbase); t1 = *(const float4*)(bet + cbase + 4);
        btv[0]=t0.x; btv[1]=t0.y; btv[2]=t0.z; btv[3]=t0.w;
        btv[4]=t1.x; btv[5]=t1.y; btv[6]=t1.z; btv[7]=t1.w;
    }
    float4 wv4[8];
    if (wvn) {
        #pragma unroll
        for (int j = 0; j < 8; j++) wv4[j] = wvn[cbase + j];
    }

    #pragma unroll
    for (int i = 0; i < 8; i++) {
        int r = row0 + ty * 8 + i;
        float v[8];
        #pragma unroll
        for (int j = 0; j < 4; j++) hg_unpack2(acc2[i][j], v[2 * j], v[2 * j + 1]);
        #pragma unroll
        for (int j = 0; j < 8; j++) v[j] += bsv[j];
        float sum = 0.f, sq = 0.f;
        #pragma unroll
        for (int j = 0; j < 8; j++) { sum += v[j]; sq += v[j] * v[j]; }
        #pragma unroll
        for (int o = 16; o > 0; o >>= 1) {
            sum += __shfl_xor_sync(0xffffffffu, sum, o);
            sq  += __shfl_xor_sync(0xffffffffu, sq, o);
        }
        float mu = sum * (1.f / HD);
        float var = sq * (1.f / HD) - mu * mu;
        float rstd = rsqrtf(var + LN_EPS);
        float y[8];
        #pragma unroll
        for (int j = 0; j < 8; j++) {
            float t = (v[j] - mu) * rstd * gmv[j] + btv[j];
            y[j] = t > 0.f ? t : expm1f(t);
        }
        if (r < M) {
            float* hp = h + (long)r * HD + cbase;
            *(float4*)hp = make_float4(y[0], y[1], y[2], y[3]);
            *(float4*)(hp + 4) = make_float4(y[4], y[5], y[6], y[7]);
        }
        if (wvn) {
            float p0 = 0.f, p1 = 0.f, p2 = 0.f, p3 = 0.f;
            #pragma unroll
            for (int j = 0; j < 8; j++) {
                p0 += y[j] * wv4[j].x; p1 += y[j] * wv4[j].y;
                p2 += y[j] * wv4[j].z; p3 += y[j] * wv4[j].w;
            }
            #pragma unroll
            for (int o = 16; o > 0; o >>= 1) {
                p0 += __shfl_xor_sync(0xffffffffu, p0, o);
                p1 += __shfl_xor_sync(0xffffffffu, p1, o);
                p2 += __shfl_xor_sync(0xffffffffu, p2, o);
                p3 += __shfl_xor_sync(0xffffffffu, p3, o);
            }
            if (tx == 0 && r < M) coef[r] = make_float4(p0, p1, p2, p3);
        }
    }
}

// ---------------- CSR build ----------------
__global__ void hg_zero2(int* a, int na, int* b, int nb) {
    int i = blockIdx.x * blockDim.x + threadIdx.x;
    if (i < na) a[i] = 0;
    if (i < nb) b[i] = 0;
}

__global__ void hg_count(const int* __restrict__ dst_at, int* cnt_at,
                         const int* __restrict__ dst_ta, int* cnt_ta) {
    int i = blockIdx.x * blockDim.x + threadIdx.x;
    if (i < NE) {
        atomicAdd(&cnt_at[dst_at[i]], 1);
        atomicAdd(&cnt_ta[dst_ta[i]], 1);
    }
}

__device__ __forceinline__ int hg_warp_incl_scan(int v, int lane) {
    #pragma unroll
    for (int o = 1; o < 32; o <<= 1) {
        int t = __shfl_up_sync(0xffffffffu, v, o);
        if (lane >= o) v += t;
    }
    return v;
}

__global__ void hg_scan1(const int* __restrict__ cnt, int* __restrict__ rp,
                         int* __restrict__ bsum, int n) {
    __shared__ int ws[32];
    int lane = threadIdx.x & 31, wid = threadIdx.x >> 5;
    int i = blockIdx.x * 1024 + threadIdx.x;
    int v = (i < n) ? cnt[i] : 0;
    int s = hg_warp_incl_scan(v, lane);
    if (lane == 31) ws[wid] = s;
    __syncthreads();
    if (wid == 0) {
        int w = ws[lane];
        w = hg_warp_incl_scan(w, lane);
        ws[lane] = w;
    }
    __syncthreads();
    s += (wid ? ws[wid - 1] : 0);
    if (i < n) rp[i + 1] = s;
    if (bsum && threadIdx.x == 1023) bsum[blockIdx.x] = s;
}

__global__ void hg_scan3(int* __restrict__ rp, const int* __restrict__ bsum, int n) {
    int i = blockIdx.x * blockDim.x + threadIdx.x;
    if (i == 0) rp[0] = 0;
    if (i < n) {
        int b = i >> 10;
        if (b > 0) rp[i + 1] += bsum[b - 1];
    }
}

__global__ void hg_fill(const int* __restrict__ s_at, const int* __restrict__ d_at,
                        int* cur_at, int* src_at, int* dst_at,
                        const int* __restrict__ s_ta, const int* __restrict__ d_ta,
                        int* cur_ta, int* src_ta, int* dst_ta) {
    int i = blockIdx.x * blockDim.x + threadIdx.x;
    if (i < NE) {
        int d0 = d_at[i];
        int p = atomicAdd(&cur_at[d0], 1);
        src_at[p] = s_at[i];
        dst_at[p] = d0;
        int d1 = d_ta[i];
        int q = atomicAdd(&cur_ta[d1], 1);
        src_ta[q] = s_ta[i];
        dst_ta[q] = d1;
    }
}

// ---------------- folded attention weights, all 6 in one launch ----------------
struct AttW6 {
    const float* W[6];
    const float* a[6];
    float* o[6];
    int K[6];
};

__global__ void hg_att_w6(AttW6 p) {
    int j = blockIdx.y;
    int k = blockIdx.x;
    if (k >= p.K[j]) return;
    int head = threadIdx.x >> 5, lane = threadIdx.x & 31;
    const float* wr = p.W[j] + (long)k * HD + head * 64;
    const float* ar = p.a[j] + head * 64;
    float s = wr[lane] * ar[lane] + wr[lane + 32] * ar[lane + 32];
    #pragma unroll
    for (int o = 16; o > 0; o >>= 1) s += __shfl_xor_sync(0xffffffffu, s, o);
    if (lane == 0) p.o[j][k * 4 + head] = s;
}

// ---------------- fused node coefficients (layer-0, from h64) ----------------
__global__ void hg_coef2(const float* __restrict__ x,
                         const float* __restrict__ Wv1, const float* __restrict__ Wv2,
                         float4* __restrict__ out1, float4* __restrict__ out2,
                         int n, int K) {
    int warp = (blockIdx.x * blockDim.x + threadIdx.x) >> 5;
    int lane = threadIdx.x & 31;
    if (warp >= n) return;
    const float* xp = x + (long)warp * K;
    const float4* wv1 = (const float4*)Wv1;
    const float4* wv2 = (const float4*)Wv2;
    float s0 = 0.f, s1 = 0.f, s2 = 0.f, s3 = 0.f;
    float t0 = 0.f, t1 = 0.f, t2 = 0.f, t3 = 0.f;
    for (int k = lane; k < K; k += 32) {
        float xv = xp[k];
        float4 w1 = wv1[k];
        float4 w2 = wv2[k];
        s0 += xv * w1.x; s1 += xv * w1.y; s2 += xv * w1.z; s3 += xv * w1.w;
        t0 += xv * w2.x; t1 += xv * w2.y; t2 += xv * w2.z; t3 += xv * w2.w;
    }
    #pragma unroll
    for (int o = 16; o > 0; o >>= 1) {
        s0 += __shfl_xor_sync(0xffffffffu, s0, o);
        s1 += __shfl_xor_sync(0xffffffffu, s1, o);
        s2 += __shfl_xor_sync(0xffffffffu, s2, o);
        s3 += __shfl_xor_sync(0xffffffffu, s3, o);
        t0 += __shfl_xor_sync(0xffffffffu, t0, o);
        t1 += __shfl_xor_sync(0xffffffffu, t1, o);
        t2 += __shfl_xor_sync(0xffffffffu, t2, o);
        t3 += __shfl_xor_sync(0xffffffffu, t3, o);
    }
    if (lane == 0) {
        out1[warp] = make_float4(s0, s1, s2, s3);
        out2[warp] = make_float4(t0, t1, t2, t3);
    }
}

// ---------------- per-edge logits in CSR order ----------------
__device__ __forceinline__ float hg_leaky(float v) { return v >= 0.f ? v : NEG_SLOPE * v; }

__global__ void hg_edge_al(const int* __restrict__ src, const int* __restrict__ dst,
                           const float4* __restrict__ als, const float4* __restrict__ ald,
                           float4* __restrict__ al) {
    int i = blockIdx.x * blockDim.x + threadIdx.x;
    if (i >= NE) return;
    float4 s = als[src[i]];
    float4 d = ald[dst[i]];
    float4 r;
    r.x = hg_leaky(s.x + d.x);
    r.y = hg_leaky(s.y + d.y);
    r.z = hg_leaky(s.z + d.z);
    r.w = hg_leaky(s.w + d.w);
    al[i] = r;
}

// ---------------- layer-0: 2-pass softmax agg of 64-dim x into head blocks ------------
__global__ void hg_agg64(const float* __restrict__ x, const int* __restrict__ srcs,
                         const float4* __restrict__ al, const int* __restrict__ rp,
                         float* __restrict__ aggx, int ndst) {
    int warp = (blockIdx.x * blockDim.x + threadIdx.x) >> 5;
    int lane = threadIdx.x & 31;
    if (warp >= ndst) return;
    int beg = rp[warp], end = rp[warp + 1];
    int c0 = lane * 8;
    int hl = lane >> 3;
    int xo = c0 & 63;

    float acc[8] = {0.f, 0.f, 0.f, 0.f, 0.f, 0.f, 0.f, 0.f};
    if (beg < end) {
        float m0 = -3.4e38f, m1 = -3.4e38f, m2 = -3.4e38f, m3 = -3.4e38f;
        for (int t = beg; t < end; t++) {
            float4 a = al[t];
            m0 = fmaxf(m0, a.x); m1 = fmaxf(m1, a.y);
            m2 = fmaxf(m2, a.z); m3 = fmaxf(m3, a.w);
        }
        float mh = (hl & 2) ? ((hl & 1) ? m3 : m2) : ((hl & 1) ? m1 : m0);
        float den = 0.f;
        for (int t = beg; t < end; t++) {
            int sidx = srcs[t];
            float4 a = al[t];
            float av = (hl & 2) ? ((hl & 1) ? a.w : a.z) : ((hl & 1) ? a.y : a.x);
            float e = __expf(av - mh);
            den += e;
            const float4* hp = (const float4*)(x + (long)sidx * HDIM + xo);
            float4 v0 = hp[0], v1 = hp[1];
            acc[0] += e * v0.x; acc[1] += e * v0.y;
            acc[2] += e * v0.z; acc[3] += e * v0.w;
            acc[4] += e * v1.x; acc[5] += e * v1.y;
            acc[6] += e * v1.z; acc[7] += e * v1.w;
        }
        float inv = 1.f / den;
        #pragma unroll
        for (int j = 0; j < 8; j++) acc[j] *= inv;
    }
    float* op = aggx + (long)warp * HD + c0;
    *(float4*)op = make_float4(acc[0], acc[1], acc[2], acc[3]);
    *(float4*)(op + 4) = make_float4(acc[4], acc[5], acc[6], acc[7]);
}

// ---------------- layer-1 FUSED 2-pass agg + bias + LN + residual + ELU --------------
__global__ void hg_gat_agg_ln(const float* __restrict__ hs, const int* __restrict__ srcs,
                              const float4* __restrict__ al, const int* __restrict__ rp,
                              const float* __restrict__ bias, const float* __restrict__ gam,
                              const float* __restrict__ bet, float* __restrict__ h,
                              int residual, int ndst) {
    int warp = (blockIdx.x * blockDim.x + threadIdx.x) >> 5;
    int lane = threadIdx.x & 31;
    if (warp >= ndst) return;
    int beg = rp[warp], end = rp[warp + 1];
    int c0 = lane * 8;
    int hl = lane >> 3;

    float acc[8] = {0.f, 0.f, 0.f, 0.f, 0.f, 0.f, 0.f, 0.f};
    if (beg < end) {
        float m0 = -3.4e38f, m1 = -3.4e38f, m2 = -3.4e38f, m3 = -3.4e38f;
        for (int t = beg; t < end; t++) {
            float4 a = al[t];
            m0 = fmaxf(m0, a.x); m1 = fmaxf(m1, a.y);
            m2 = fmaxf(m2, a.z); m3 = fmaxf(m3, a.w);
        }
        float mh = (hl & 2) ? ((hl & 1) ? m3 : m2) : ((hl & 1) ? m1 : m0);
        float den = 0.f;
        for (int t = beg; t < end; t++) {
            int sidx = srcs[t];
            float4 a = al[t];
            float av = (hl & 2) ? ((hl & 1) ? a.w : a.z) : ((hl & 1) ? a.y : a.x);
            float e = __expf(av - mh);
            den += e;
            const float4* hp = (const float4*)(hs + (long)sidx * HD + c0);
            float4 v0 = hp[0], v1 = hp[1];
            acc[0] += e * v0.x; acc[1] += e * v0.y;
            acc[2] += e * v0.z; acc[3] += e * v0.w;
            acc[4] += e * v1.x; acc[5] += e * v1.y;
            acc[6] += e * v1.z; acc[7] += e * v1.w;
        }
        float inv = 1.f / den;
        #pragma unroll
        for (int j = 0; j < 8; j++) acc[j] *= inv;
    }

    const float4* bp = (const float4*)(bias + c0);
    float4 b0 = bp[0], b1 = bp[1];
    float v[8] = {acc[0] + b0.x, acc[1] + b0.y, acc[2] + b0.z, acc[3] + b0.w,
                  acc[4] + b1.x, acc[5] + b1.y, acc[6] + b1.z, acc[7] + b1.w};
    float sum = 0.f, sq = 0.f;
    #pragma unroll
    for (int j = 0; j < 8; j++) { sum += v[j]; sq += v[j] * v[j]; }
    #pragma unroll
    for (int o = 16; o > 0; o >>= 1) {
        sum += __shfl_xor_sync(0xffffffffu, sum, o);
        sq  += __shfl_xor_sync(0xffffffffu, sq, o);
    }
    float mu = sum * (1.f / HD);
    float var = sq * (1.f / HD) - mu * mu;
    float rstd = rsqrtf(var + LN_EPS);

    const float4* gp = (const float4*)(gam + c0);
    const float4* ep = (const float4*)(bet + c0);
    float4 g0 = gp[0], g1 = gp[1];
    float4 e0 = ep[0], e1 = ep[1];
    float gm[8] = {g0.x, g0.y, g0.z, g0.w, g1.x, g1.y, g1.z, g1.w};
    float bt[8] = {e0.x, e0.y, e0.z, e0.w, e1.x, e1.y, e1.z, e1.w};
    float* hp = h + (long)warp * HD + c0;
    float r[8] = {0.f, 0.f, 0.f, 0.f, 0.f, 0.f, 0.f, 0.f};
    if (residual) {
        float4 r0 = ((const float4*)hp)[0], r1 = ((const float4*)hp)[1];
        r[0] = r0.x; r[1] = r0.y; r[2] = r0.z; r[3] = r0.w;
        r[4] = r1.x; r[5] = r1.y; r[6] = r1.z; r[7] = r1.w;
    }
    float y[8];
    #pragma unroll
    for (int j = 0; j < 8; j++) {
        float t = (v[j] - mu) * rstd * gm[j] + bt[j] + r[j];
        y[j] = t > 0.f ? t : expm1f(t);
    }
    *(float4*)hp = make_float4(y[0], y[1], y[2], y[3]);
    *(float4*)(hp + 4) = make_float4(y[4], y[5], y[6], y[7]);
}

// ---------------- mean pooling addr -> tx (warp per tx node) ----------------
__global__ void hg_pool_mean(const float* __restrict__ haddr, const int* __restrict__ srcs,
                             const int* __restrict__ rp, float* __restrict__ out, int ndst) {
    int warp = (blockIdx.x * blockDim.x + threadIdx.x) >> 5;
    int lane = threadIdx.x & 31;
    if (warp >= ndst) return;
    int beg = rp[warp], end = rp[warp + 1];
    int c0 = lane * 8;
    float acc[8] = {0.f, 0.f, 0.f, 0.f, 0.f, 0.f, 0.f, 0.f};
    for (int t = beg; t < end; t++) {
        int s = srcs[t];
        const float4* hp = (const float4*)(haddr + (long)s * HD + c0);
        float4 v0 = hp[0], v1 = hp[1];
        acc[0] += v0.x; acc[1] += v0.y; acc[2] += v0.z; acc[3] += v0.w;
        acc[4] += v1.x; acc[5] += v1.y; acc[6] += v1.z; acc[7] += v1.w;
    }
    int deg = end - beg;
    float inv = 1.f / (float)(deg > 0 ? deg : 1);
    float* op = out + (long)warp * HD + c0;
    *(float4*)op = make_float4(acc[0] * inv, acc[1] * inv, acc[2] * inv, acc[3] * inv);
    *(float4*)(op + 4) = make_float4(acc[4] * inv, acc[5] * inv, acc[6] * inv, acc[7] * inv);
}

// ---------------- host launcher ----------------
#define SYMADDR(p, s) do { void* _t = nullptr; cudaGetSymbolAddress(&_t, s); p = (decltype(p))_t; } while (0)

static inline void launch_gemm(const float* A, const float* B, const float* bias,
                               float* C, int M, int N, int K) {
    dim3 grid((N + BN - 1) / BN, (M + BM - 1) / BM);
    hg_sgemm<<<grid, 256>>>(A, B, bias, C, M, N, K);
}

// side stream + fork/join events (host objects, created once)
static cudaStream_t hg_s1 = nullptr;
static cudaEvent_t hg_ev_fork = nullptr, hg_ev_join = nullptr;
static cudaEvent_t hg_ev_fork2 = nullptr, hg_ev_tx = nullptr, hg_ev_join2 = nullptr;

extern "C" void kernel_launch(void* const* d_in, const int* in_sizes, int n_in,
                              void* d_out, int out_size) {
    const float* x_tx      = (const float*)d_in[0];
    const float* x_addr    = (const float*)d_in[1];
    const int*   addr_idx_at = (const int*)d_in[2];
    const int*   tx_idx_at   = (const int*)d_in[3];
    const int*   tx_idx_ta   = (const int*)d_in[4];
    const int*   addr_idx_ta = (const int*)d_in[5];
    const float* w_in_tx   = (const float*)d_in[6];
    const float* b_in_tx   = (const float*)d_in[7];
    const float* w_in_addr = (const float*)d_in[8];
    const float* b_in_addr = (const float*)d_in[9];
    const float* w_at0 = (const float*)d_in[10];
    const float* as_at0 = (const float*)d_in[11];
    const float* ad_at0 = (const float*)d_in[12];
    const float* b_at0 = (const float*)d_in[13];
    const float* w_ta0 = (const float*)d_in[14];
    const float* as_ta0 = (const float*)d_in[15];
    const float* ad_ta0 = (const float*)d_in[16];
    const float* b_ta0 = (const float*)d_in[17];
    // layer-1 at-relation weights are dead (h_tx after layer 1 unused by output)
    const float* w_ta1 = (const float*)d_in[22];
    const float* as_ta1 = (const float*)d_in[23];
    const float* ad_ta1 = (const float*)d_in[24];
    const float* b_ta1 = (const float*)d_in[25];
    const float* ln_g_tx = (const float*)d_in[26];
    const float* ln_b_tx = (const float*)d_in[27];
    const float* ln_g_addr = (const float*)d_in[28];
    const float* ln_b_addr = (const float*)d_in[29];
    const float* w_out = (const float*)d_in[30];
    const float* b_out = (const float*)d_in[31];
    float* out = (float*)d_out;

    float *p_htx64, *p_haddr64, *p_buf_addr, *p_buf_tx, *p_pool_tx, *p_htx, *p_haddr;
    float4 *p_als_at, *p_ald_at, *p_als_ta, *p_ald_ta, *p_al_at, *p_al_ta;
    int *p_cnt_tx, *p_cnt_addr, *p_rp_at, *p_rp_ta, *p_cur_tx, *p_cur_addr;
    int *p_src_at, *p_dst_at, *p_src_ta, *p_dst_ta, *p_bsum_tx, *p_bsum_addr;
    float *p_ws_at, *p_wd_at, *p_ws_ta, *p_wd_ta, *p_ws_ta1, *p_wd_ta1;
    SYMADDR(p_htx64, g_htx64);     SYMADDR(p_haddr64, g_haddr64);
    SYMADDR(p_buf_addr, g_buf_addr); SYMADDR(p_buf_tx, g_buf_tx);
    SYMADDR(p_pool_tx, g_pool_tx);
    SYMADDR(p_htx, g_htx);         SYMADDR(p_haddr, g_haddr);
    SYMADDR(p_als_at, g_als_at);   SYMADDR(p_ald_at, g_ald_at);
    SYMADDR(p_als_ta, g_als_ta);   SYMADDR(p_ald_ta, g_ald_ta);
    SYMADDR(p_al_at, g_al_at);     SYMADDR(p_al_ta, g_al_ta);
    SYMADDR(p_cnt_tx, g_cnt_tx);   SYMADDR(p_cnt_addr, g_cnt_addr);
    SYMADDR(p_rp_at, g_rp_at);     SYMADDR(p_rp_ta, g_rp_ta);
    SYMADDR(p_cur_tx, g_cur_tx);   SYMADDR(p_cur_addr, g_cur_addr);
    SYMADDR(p_src_at, g_src_at);   SYMADDR(p_dst_at, g_dst_at);
    SYMADDR(p_src_ta, g_src_ta);   SYMADDR(p_dst_ta, g_dst_ta);
    SYMADDR(p_bsum_tx, g_bsum_tx); SYMADDR(p_bsum_addr, g_bsum_addr);
    SYMADDR(p_ws_at, g_ws_at);     SYMADDR(p_wd_at, g_wd_at);
    SYMADDR(p_ws_ta, g_ws_ta);     SYMADDR(p_wd_ta, g_wd_ta);
    SYMADDR(p_ws_ta1, g_ws_ta1);   SYMADDR(p_wd_ta1, g_wd_ta1);

    if (!hg_s1) {
        cudaStreamCreateWithFlags(&hg_s1, cudaStreamNonBlocking);
        cudaEventCreateWithFlags(&hg_ev_fork, cudaEventDisableTiming);
        cudaEventCreateWithFlags(&hg_ev_join, cudaEventDisableTiming);
        cudaEventCreateWithFlags(&hg_ev_fork2, cudaEventDisableTiming);
        cudaEventCreateWithFlags(&hg_ev_tx, cudaEventDisableTiming);
        cudaEventCreateWithFlags(&hg_ev_join2, cudaEventDisableTiming);
    }

    const int TB = 256;
    const int nb_tx = (N_TX + 1023) / 1024;
    const int nb_addr = (N_ADDR + 1023) / 1024;
    int cblk_tx = (N_TX * 32 + TB - 1) / TB;
    int cblk_addr = (N_ADDR * 32 + TB - 1) / TB;
    int eblk = (NE + TB - 1) / TB;

    // ---- fork 1: side = CSR build + att_w6 + addr projection; main = tx projection ---
    cudaEventRecord(hg_ev_fork, 0);
    cudaStreamWaitEvent(hg_s1, hg_ev_fork, 0);

    hg_zero2<<<(N_ADDR + TB - 1) / TB, TB, 0, hg_s1>>>(p_cnt_tx, N_TX, p_cnt_addr, N_ADDR);
    hg_count<<<(NE + TB - 1) / TB, TB, 0, hg_s1>>>(tx_idx_at, p_cnt_tx, addr_idx_ta, p_cnt_addr);
    hg_scan1<<<nb_tx, 1024, 0, hg_s1>>>(p_cnt_tx, p_rp_at, p_bsum_tx, N_TX);
    hg_scan1<<<nb_addr, 1024, 0, hg_s1>>>(p_cnt_addr, p_rp_ta, p_bsum_addr, N_ADDR);
    hg_scan1<<<1, 1024, 0, hg_s1>>>(p_bsum_tx, p_bsum_tx - 1, nullptr, nb_tx);
    hg_scan1<<<1, 1024, 0, hg_s1>>>(p_bsum_addr, p_bsum_addr - 1, nullptr, nb_addr);
    hg_scan3<<<(N_TX + TB - 1) / TB, TB, 0, hg_s1>>>(p_rp_at, p_bsum_tx, N_TX);
    hg_scan3<<<(N_ADDR + TB - 1) / TB, TB, 0, hg_s1>>>(p_rp_ta, p_bsum_addr, N_ADDR);
    cudaMemcpyAsync(p_cur_tx, p_rp_at, N_TX * sizeof(int), cudaMemcpyDeviceToDevice, hg_s1);
    cudaMemcpyAsync(p_cur_addr, p_rp_ta, N_ADDR * sizeof(int), cudaMemcpyDeviceToDevice, hg_s1);
    hg_fill<<<(NE + TB - 1) / TB, TB, 0, hg_s1>>>(addr_idx_at, tx_idx_at, p_cur_tx,
                                                  p_src_at, p_dst_at,
                                                  tx_idx_ta, addr_idx_ta, p_cur_addr,
                                                  p_src_ta, p_dst_ta);
    {
        AttW6 p;
        p.W[0] = w_at0; p.a[0] = as_at0; p.o[0] = p_ws_at;  p.K[0] = HDIM;
        p.W[1] = w_at0; p.a[1] = ad_at0; p.o[1] = p_wd_at;  p.K[1] = HDIM;
        p.W[2] = w_ta0; p.a[2] = as_ta0; p.o[2] = p_ws_ta;  p.K[2] = HDIM;
        p.W[3] = w_ta0; p.a[3] = ad_ta0; p.o[3] = p_wd_ta;  p.K[3] = HDIM;
        p.W[4] = w_ta1; p.a[4] = as_ta1; p.o[4] = p_ws_ta1; p.K[4] = HD;
        p.W[5] = w_ta1; p.a[5] = ad_ta1; p.o[5] = p_wd_ta1; p.K[5] = HD;
        hg_att_w6<<<dim3(HD, 6), 128, 0, hg_s1>>>(p);
    }
    hg_sgemm_n64<<<(N_ADDR + BM - 1) / BM, 128, 0, hg_s1>>>(x_addr, w_in_addr, b_in_addr,
                                                            p_haddr64, N_ADDR, F_ADDR);
    cudaEventRecord(hg_ev_join, hg_s1);

    hg_sgemm_n64<<<(N_TX + BM - 1) / BM, 128>>>(x_tx, w_in_tx, b_in_tx, p_htx64,
                                                N_TX, F_TX);
    cudaStreamWaitEvent(0, hg_ev_join, 0);

    // ---- layer-0 node coefficients (need both projections) ----
    hg_coef2<<<cblk_addr, TB>>>(p_haddr64, p_ws_at, p_wd_ta, p_als_at, p_ald_ta,
                                N_ADDR, HDIM);
    hg_coef2<<<cblk_tx,   TB>>>(p_htx64,   p_wd_at, p_ws_ta, p_ald_at, p_als_ta,
                                N_TX, HDIM);

    // ---- fork 2: split the two node-type chains across streams ----
    // main (tx chain):  edge_al_at -> agg64_tx -> gemm_ln_tx -> L1 sgemm (compute-bound)
    // side (addr chain): edge_al_ta -> agg64_addr -> gemm_ln_addr -> L1 edge_al (mem-bound)
    cudaEventRecord(hg_ev_fork2, 0);
    cudaStreamWaitEvent(hg_s1, hg_ev_fork2, 0);

    // (side) addr chain
    hg_edge_al<<<eblk, TB, 0, hg_s1>>>(p_src_ta, p_dst_ta, p_als_ta, p_ald_ta, p_al_ta);
    hg_agg64<<<cblk_addr, TB, 0, hg_s1>>>(p_htx64, p_src_ta, p_al_ta, p_rp_ta,
                                          p_buf_addr, N_ADDR);
    hg_gemm_ln<<<(N_ADDR + 63) / 64, 256, 0, hg_s1>>>(p_buf_addr, w_ta0, b_ta0,
                                                      ln_g_addr, ln_b_addr, p_haddr,
                                                      (const float4*)p_wd_ta1, p_ald_ta,
                                                      N_ADDR);

    // (main) tx chain
    hg_edge_al<<<eblk, TB>>>(p_src_at, p_dst_at, p_als_at, p_ald_at, p_al_at);
    hg_agg64<<<cblk_tx, TB>>>(p_haddr64, p_src_at, p_al_at, p_rp_at, p_buf_tx, N_TX);
    hg_gemm_ln<<<(N_TX + 63) / 64, 256>>>(p_buf_tx, w_at0, b_at0, ln_g_tx, ln_b_tx,
                                          p_htx, (const float4*)p_ws_ta1, p_als_ta, N_TX);
    cudaEventRecord(hg_ev_tx, 0);   // gemm_ln_tx done: als_ta ready

    // (main) layer-1 projection — overlaps the side chain's remaining work
    launch_gemm(p_htx, w_ta1, nullptr, p_buf_tx, N_TX, HD, HD);

    // (side) layer-1 logits: needs als_ta (main) + ald_ta (side)
    cudaStreamWaitEvent(hg_s1, hg_ev_tx, 0);
    hg_edge_al<<<eblk, TB, 0, hg_s1>>>(p_src_ta, p_dst_ta, p_als_ta, p_ald_ta, p_al_ta);
    cudaEventRecord(hg_ev_join2, hg_s1);

    // join: layer-1 aggregation needs L1 GEMM (main) + L1 logits (side)
    cudaStreamWaitEvent(0, hg_ev_join2, 0);
    hg_gat_agg_ln<<<cblk_addr, TB>>>(p_buf_tx, p_src_ta, p_al_ta, p_rp_ta,
                                     b_ta1, ln_g_addr, ln_b_addr, p_haddr, 1, N_ADDR);

    // ---- scatter-mean pooling addr -> tx over 'at' edges ----
    hg_pool_mean<<<cblk_tx, TB>>>(p_haddr, p_src_at, p_rp_at, p_pool_tx, N_TX);

    // ---- output projection ----
    launch_gemm(p_pool_tx, w_out, b_out, out, N_TX, HD, HD);
}